// round 10
// baseline (speedup 1.0000x reference)
#include <cuda_runtime.h>
#include <cuda_bf16.h>

// Problem constants (reference: N_NODES=50000, F=128, HIDDEN=128, OUT=64, E=600000)
#define MAX_NODES 50000
#define MAX_EDGES 600000
#define SCAN_NB ((MAX_NODES + 255) / 256)   // 196

// ---------------- scratch (device globals; no allocations allowed) -------------
__device__ int   g_bad = 0;              // sticky: 1 if edge_index is int32 (input-dependent only)
__device__ int   g_row [MAX_EDGES];
__device__ int   g_col [MAX_EDGES];
__device__ int   g_srt [MAX_EDGES];      // edge sources sorted by destination (CSR)
__device__ int   g_cnt [MAX_NODES];      // in-degree (excl. self-loop)
__device__ int   g_off [MAX_NODES];      // CSR row offsets (exclusive scan of cnt)
__device__ int   g_cur [MAX_NODES];      // placement cursors
__device__ int   g_stat[SCAN_NB];        // decoupled-lookback status (reset by k_prep)
__device__ int   g_aggr[SCAN_NB];
__device__ int   g_pref[SCAN_NB];
__device__ float g_dis [MAX_NODES];
__device__ float g_xs1 [MAX_NODES * 128];
__device__ float g_z1  [MAX_NODES * 128];
__device__ float g_xs2 [MAX_NODES * 64];
__device__ float g_z2  [MAX_NODES * 64];

// ---------------- f32x2 packed-FMA helpers -------------------------------------
__device__ __forceinline__ void fma2(unsigned long long& acc,
                                     unsigned long long a, unsigned long long b) {
    asm("fma.rn.f32x2 %0, %1, %2, %0;" : "+l"(acc) : "l"(a), "l"(b));
}
__device__ __forceinline__ unsigned long long dup2(float f) {
    unsigned long long d; unsigned int u = __float_as_uint(f);
    asm("mov.b64 %0, {%1, %1};" : "=l"(d) : "r"(u));
    return d;
}
__device__ __forceinline__ float2 unpk2(unsigned long long v) {
    float2 f;
    asm("mov.b64 {%0, %1}, %2;" : "=f"(f.x), "=f"(f.y) : "l"(v));
    return f;
}

// ---------------- prep: zero cnt + scan status + dtype sniff -------------------
__global__ void k_prep(const long long* __restrict__ ei, int E, int n,
                       int* __restrict__ cnt, int* __restrict__ stat,
                       int* __restrict__ bad) {
    int i = blockIdx.x * blockDim.x + threadIdx.x;
    if (i < n) cnt[i] = 0;
    if (i < SCAN_NB) stat[i] = 0;
    bool oob = false;
    if (i < E) {
        long long v = ei[i];
        oob = (v < 0 || v >= (long long)n);
    }
    unsigned m = __ballot_sync(0xFFFFFFFFu, oob);
    if (oob && (threadIdx.x & 31) == (__ffs(m) - 1)) {
        if (*bad == 0) atomicOr(bad, 1);
    }
}

// ---------------- convert to int32 row/col + in-degree count -------------------
__global__ void k_convert(const void* __restrict__ ei, int E, int n,
                          const int* __restrict__ bad,
                          int* __restrict__ row, int* __restrict__ col,
                          int* __restrict__ cnt) {
    int i = blockIdx.x * blockDim.x + threadIdx.x;
    if (i >= E) return;
    int r, c;
    if (*bad == 0) {   // true int64 indices
        r = (int)((const long long*)ei)[i];
        c = (int)((const long long*)ei)[(size_t)E + i];
    } else {           // int32 layout
        r = ((const int*)ei)[i];
        c = ((const int*)ei)[(size_t)E + i];
    }
    if ((unsigned)r >= (unsigned)n) r = 0;
    if ((unsigned)c >= (unsigned)n) c = 0;
    row[i] = r;
    col[i] = c;
    atomicAdd(&cnt[c], 1);
}

// ---------------- single-pass decoupled-lookback scan --------------------------
__global__ __launch_bounds__(256) void k_scan(
    const int* __restrict__ cnt, int n,
    int* __restrict__ off, int* __restrict__ cur, float* __restrict__ dis,
    volatile int* stat, volatile int* aggr, volatile int* pref)
{
    __shared__ int sh[256];
    __shared__ int s_prefix;
    const int b = blockIdx.x;
    const int i = b * 256 + threadIdx.x;
    int v = (i < n) ? cnt[i] : 0;
    sh[threadIdx.x] = v;
    __syncthreads();
#pragma unroll
    for (int d = 1; d < 256; d <<= 1) {
        int t = (threadIdx.x >= d) ? sh[threadIdx.x - d] : 0;
        __syncthreads();
        sh[threadIdx.x] += t;
        __syncthreads();
    }
    int incl = sh[threadIdx.x];
    int total = sh[255];

    if (threadIdx.x == 0) {
        if (b == 0) {
            pref[0] = total;
            __threadfence();
            ((int*)stat)[0] = 2;
            s_prefix = 0;
        } else {
            aggr[b] = total;
            __threadfence();
            ((int*)stat)[b] = 1;
            int run = 0;
            int p = b - 1;
            while (true) {
                int st;
                do { st = stat[p]; } while (st == 0);
                __threadfence();
                if (st == 2) { run += pref[p]; break; }
                run += aggr[p];
                p--;
            }
            pref[b] = run + total;
            __threadfence();
            ((int*)stat)[b] = 2;
            s_prefix = run;
        }
    }
    __syncthreads();
    int prefix = s_prefix;
    if (i < n) {
        int o = prefix + incl - v;
        off[i] = o;
        cur[i] = o;
        dis[i] = rsqrtf((float)(v + 1));
    }
}

__global__ void k_place(const int* __restrict__ row, const int* __restrict__ col,
                        int* __restrict__ cur, int* __restrict__ srt, int E) {
    int e = blockIdx.x * blockDim.x + threadIdx.x;
    if (e >= E) return;
    int pos = atomicAdd(&cur[col[e]], 1);
    srt[pos] = row[e];
}

// ---------------- SGEMM (f32x2, double-buffered smem): X[M,K] @ W[K,N] ---------
// MODE 3: raw (no epilogue).
template<int K, int N, int MODE>
__global__ __launch_bounds__(256) void k_gemm(
    const float* __restrict__ X, const float* __restrict__ W,
    const float* __restrict__ bias, float* __restrict__ out, int M)
{
    constexpr int BM = 128;
    constexpr int BK = 16;
    constexpr int TN = 8;
    constexpr int TX = N / TN;
    constexpr int TY = 256 / TX;
    constexpr int TM = BM / TY;
    constexpr int TP = TM / 2;
    constexpr int CH = K / BK;
    constexpr int WL = (BK * N) / 1024;

    __shared__ float As[2][BK][BM + 4];
    __shared__ float Ws[2][BK][N];

    const int tid = threadIdx.x;
    const int tx = tid % TX;
    const int ty = tid / TX;
    const int row0 = blockIdx.x * BM;

    const int ar  = tid >> 2;
    const int akg = tid & 3;
    const bool arow_ok0 = (row0 + ar) < M;
    const bool arow_ok1 = (row0 + ar + 64) < M;
    const float* aptr0 = &X[(size_t)(row0 + ar)      * K + akg * 4];
    const float* aptr1 = &X[(size_t)(row0 + ar + 64) * K + akg * 4];

    unsigned long long acc2[TP][TN];
#pragma unroll
    for (int i = 0; i < TP; i++)
#pragma unroll
        for (int j = 0; j < TN; j++) acc2[i][j] = 0ull;

    float4 ra0, ra1, rw[WL];

    ra0 = arow_ok0 ? *(const float4*)(aptr0) : make_float4(0.f,0.f,0.f,0.f);
    ra1 = arow_ok1 ? *(const float4*)(aptr1) : make_float4(0.f,0.f,0.f,0.f);
#pragma unroll
    for (int l = 0; l < WL; l++) {
        int idx = tid + l * 256;
        int r   = idx / (N / 4);
        int cg  = idx % (N / 4);
        rw[l] = *(const float4*)&W[(size_t)r * N + cg * 4];
    }
    {
        As[0][akg*4+0][ar] = ra0.x; As[0][akg*4+1][ar] = ra0.y;
        As[0][akg*4+2][ar] = ra0.z; As[0][akg*4+3][ar] = ra0.w;
        As[0][akg*4+0][ar+64] = ra1.x; As[0][akg*4+1][ar+64] = ra1.y;
        As[0][akg*4+2][ar+64] = ra1.z; As[0][akg*4+3][ar+64] = ra1.w;
#pragma unroll
        for (int l = 0; l < WL; l++) {
            int idx = tid + l * 256;
            int r   = idx / (N / 4);
            int cg  = idx % (N / 4);
            *(float4*)&Ws[0][r][cg * 4] = rw[l];
        }
    }
    __syncthreads();

#pragma unroll
    for (int c = 0; c < CH; c++) {
        const int cur = c & 1;
        if (c + 1 < CH) {
            const int kc = (c + 1) * BK;
            ra0 = arow_ok0 ? *(const float4*)(aptr0 + kc) : make_float4(0.f,0.f,0.f,0.f);
            ra1 = arow_ok1 ? *(const float4*)(aptr1 + kc) : make_float4(0.f,0.f,0.f,0.f);
#pragma unroll
            for (int l = 0; l < WL; l++) {
                int idx = tid + l * 256;
                int r   = idx / (N / 4);
                int cg  = idx % (N / 4);
                rw[l] = *(const float4*)&W[(size_t)(kc + r) * N + cg * 4];
            }
        }

#pragma unroll
        for (int k = 0; k < BK; k++) {
            unsigned long long ap[TP];
#pragma unroll
            for (int i = 0; i < TM / 4; i++) {
                ulonglong2 t = *(const ulonglong2*)&As[cur][k][ty * TM + i * 4];
                ap[i * 2]     = t.x;
                ap[i * 2 + 1] = t.y;
            }
            float4 w0 = *(const float4*)&Ws[cur][k][tx * TN];
            float4 w1 = *(const float4*)&Ws[cur][k][tx * TN + 4];
            unsigned long long wd[TN];
            wd[0] = dup2(w0.x); wd[1] = dup2(w0.y);
            wd[2] = dup2(w0.z); wd[3] = dup2(w0.w);
            wd[4] = dup2(w1.x); wd[5] = dup2(w1.y);
            wd[6] = dup2(w1.z); wd[7] = dup2(w1.w);
#pragma unroll
            for (int i = 0; i < TP; i++)
#pragma unroll
                for (int j = 0; j < TN; j++)
                    fma2(acc2[i][j], ap[i], wd[j]);
        }

        if (c + 1 < CH) {
            const int nxt = cur ^ 1;
            As[nxt][akg*4+0][ar] = ra0.x; As[nxt][akg*4+1][ar] = ra0.y;
            As[nxt][akg*4+2][ar] = ra0.z; As[nxt][akg*4+3][ar] = ra0.w;
            As[nxt][akg*4+0][ar+64] = ra1.x; As[nxt][akg*4+1][ar+64] = ra1.y;
            As[nxt][akg*4+2][ar+64] = ra1.z; As[nxt][akg*4+3][ar+64] = ra1.w;
#pragma unroll
            for (int l = 0; l < WL; l++) {
                int idx = tid + l * 256;
                int r   = idx / (N / 4);
                int cg  = idx % (N / 4);
                *(float4*)&Ws[nxt][r][cg * 4] = rw[l];
            }
        }
        __syncthreads();
    }

#pragma unroll
    for (int i = 0; i < TP; i++) {
        int r0 = row0 + ty * TM + 2 * i;
        float lo[TN], hi[TN];
#pragma unroll
        for (int j = 0; j < TN; j++) {
            float2 f = unpk2(acc2[i][j]);
            lo[j] = f.x; hi[j] = f.y;
        }
#pragma unroll
        for (int h = 0; h < 2; h++) {
            int r = r0 + h;
            if (r >= M) continue;
            float* v = h ? hi : lo;
            size_t ob = (size_t)r * N + tx * TN;
            *(float4*)&out[ob]     = make_float4(v[0], v[1], v[2], v[3]);
            *(float4*)&out[ob + 4] = make_float4(v[4], v[5], v[6], v[7]);
        }
    }
}

// ---------------- fused decoder: out = relu(z2@W1 + b1) @ W2 + b2 --------------
// All tiles smem-resident: z2 tile (transposed), W1, W2, and the intermediate
// T (transposed). Stage 2 reads both operands straight from smem, no syncs.
// Dynamic smem layout (floats):
//   As1 [64][132]   @ 0        (8448)
//   Ws1 [64][128]   @ 8448     (8192)
//   Ws2 [128][128]  @ 16640    (16384)
//   Tt  [128][132]  @ 33024    (16896)
#define DEC_SMEM_FLOATS 49920
__global__ __launch_bounds__(256) void k_decoder(
    const float* __restrict__ Z2, const float* __restrict__ W1,
    const float* __restrict__ b1, const float* __restrict__ W2,
    const float* __restrict__ b2, float* __restrict__ out, int M)
{
    extern __shared__ float sm[];
    float* As1 = sm;            // [64][132]
    float* Ws1 = sm + 8448;     // [64][128]
    float* Ws2 = sm + 16640;    // [128][128]
    float* Tt  = sm + 33024;    // [128][132]

    const int tid = threadIdx.x;
    const int tx = tid % 16;        // 16 col-groups of 8
    const int ty = tid / 16;        // 16 row-groups of 8
    const int row0 = blockIdx.x * 128;

    // ---- load all tiles ----
    // As1: z2 tile transposed. 128 rows x 64 cols = 2048 float4.
#pragma unroll
    for (int l = 0; l < 8; l++) {
        int idx = tid + l * 256;    // 0..2047
        int r   = idx >> 4;         // 0..127
        int kg  = idx & 15;         // 0..15 (float4 along k)
        int gr  = row0 + r;
        float4 v = make_float4(0.f,0.f,0.f,0.f);
        if (gr < M) v = *(const float4*)&Z2[(size_t)gr * 64 + kg * 4];
        As1[(kg*4+0)*132 + r] = v.x;
        As1[(kg*4+1)*132 + r] = v.y;
        As1[(kg*4+2)*132 + r] = v.z;
        As1[(kg*4+3)*132 + r] = v.w;
    }
    // Ws1: 64x128 = 2048 float4
#pragma unroll
    for (int l = 0; l < 8; l++) {
        int idx = tid + l * 256;
        int r   = idx >> 5;         // /32
        int cg  = idx & 31;
        *(float4*)&Ws1[r*128 + cg*4] = *(const float4*)&W1[(size_t)r*128 + cg*4];
    }
    // Ws2: 128x128 = 4096 float4
#pragma unroll
    for (int l = 0; l < 16; l++) {
        int idx = tid + l * 256;
        int r   = idx >> 5;
        int cg  = idx & 31;
        *(float4*)&Ws2[r*128 + cg*4] = *(const float4*)&W2[(size_t)r*128 + cg*4];
    }
    __syncthreads();

    // ---- stage 1: T = relu(z2 @ W1 + b1), write transposed into Tt ----
    {
        unsigned long long acc2[4][8];
#pragma unroll
        for (int i = 0; i < 4; i++)
#pragma unroll
            for (int j = 0; j < 8; j++) acc2[i][j] = 0ull;

#pragma unroll
        for (int k = 0; k < 64; k++) {
            unsigned long long ap[4];
#pragma unroll
            for (int i = 0; i < 2; i++) {
                ulonglong2 t = *(const ulonglong2*)&As1[k*132 + ty*8 + i*4];
                ap[i*2]   = t.x;
                ap[i*2+1] = t.y;
            }
            float4 w0 = *(const float4*)&Ws1[k*128 + tx*8];
            float4 w1 = *(const float4*)&Ws1[k*128 + tx*8 + 4];
            unsigned long long wd[8];
            wd[0] = dup2(w0.x); wd[1] = dup2(w0.y);
            wd[2] = dup2(w0.z); wd[3] = dup2(w0.w);
            wd[4] = dup2(w1.x); wd[5] = dup2(w1.y);
            wd[6] = dup2(w1.z); wd[7] = dup2(w1.w);
#pragma unroll
            for (int i = 0; i < 4; i++)
#pragma unroll
                for (int j = 0; j < 8; j++)
                    fma2(acc2[i][j], ap[i], wd[j]);
        }

        // epilogue 1: bias + relu, store transposed: Tt[col][row]
#pragma unroll
        for (int i = 0; i < 4; i++) {
            int r0 = ty * 8 + 2 * i;
#pragma unroll
            for (int j = 0; j < 8; j++) {
                float2 f = unpk2(acc2[i][j]);
                float b = b1[tx*8 + j];
                Tt[(tx*8+j)*132 + r0]     = fmaxf(f.x + b, 0.f);
                Tt[(tx*8+j)*132 + r0 + 1] = fmaxf(f.y + b, 0.f);
            }
        }
    }
    __syncthreads();

    // ---- stage 2: out = T @ W2 + b2 (both operands in smem, K=128) ----
    {
        unsigned long long acc2[4][8];
#pragma unroll
        for (int i = 0; i < 4; i++)
#pragma unroll
            for (int j = 0; j < 8; j++) acc2[i][j] = 0ull;

#pragma unroll
        for (int k = 0; k < 128; k++) {
            unsigned long long ap[4];
#pragma unroll
            for (int i = 0; i < 2; i++) {
                ulonglong2 t = *(const ulonglong2*)&Tt[k*132 + ty*8 + i*4];
                ap[i*2]   = t.x;
                ap[i*2+1] = t.y;
            }
            float4 w0 = *(const float4*)&Ws2[k*128 + tx*8];
            float4 w1 = *(const float4*)&Ws2[k*128 + tx*8 + 4];
            unsigned long long wd[8];
            wd[0] = dup2(w0.x); wd[1] = dup2(w0.y);
            wd[2] = dup2(w0.z); wd[3] = dup2(w0.w);
            wd[4] = dup2(w1.x); wd[5] = dup2(w1.y);
            wd[6] = dup2(w1.z); wd[7] = dup2(w1.w);
#pragma unroll
            for (int i = 0; i < 4; i++)
#pragma unroll
                for (int j = 0; j < 8; j++)
                    fma2(acc2[i][j], ap[i], wd[j]);
        }

        // epilogue 2: + b2, store to global
        float bb[8];
#pragma unroll
        for (int j = 0; j < 8; j++) bb[j] = b2[tx*8 + j];
#pragma unroll
        for (int i = 0; i < 4; i++) {
            int r0 = row0 + ty * 8 + 2 * i;
#pragma unroll
            for (int h = 0; h < 2; h++) {
                int r = r0 + h;
                if (r >= M) continue;
                float o[8];
#pragma unroll
                for (int j = 0; j < 8; j++) {
                    float2 f = unpk2(acc2[i][j]);
                    o[j] = (h ? f.y : f.x) + bb[j];
                }
                size_t ob = (size_t)r * 128 + tx * 8;
                *(float4*)&out[ob]     = make_float4(o[0], o[1], o[2], o[3]);
                *(float4*)&out[ob + 4] = make_float4(o[4], o[5], o[6], o[7]);
            }
        }
    }
}

// ---------------- CSR gather F=128: one warp per node --------------------------
__global__ __launch_bounds__(256) void k_gather128(
    const int* __restrict__ off, const int* __restrict__ cnt,
    const int* __restrict__ srt, const float* __restrict__ xs,
    const float* __restrict__ dis, const float* __restrict__ bias,
    float* __restrict__ out, int n)
{
    int w    = (blockIdx.x * blockDim.x + threadIdx.x) >> 5;
    int lane = threadIdx.x & 31;
    if (w >= n) return;
    int s = off[w];
    int e = s + cnt[w];
    float d = dis[w];

    float4 sv = *(const float4*)&xs[(size_t)w * 128 + lane * 4];
    float4 sum = make_float4(d * sv.x, d * sv.y, d * sv.z, d * sv.w);
    int t = s;
    for (; t + 4 <= e; t += 4) {
        int i0 = __ldg(&srt[t]);
        int i1 = __ldg(&srt[t + 1]);
        int i2 = __ldg(&srt[t + 2]);
        int i3 = __ldg(&srt[t + 3]);
        float d0 = __ldg(&dis[i0]);
        float d1 = __ldg(&dis[i1]);
        float d2 = __ldg(&dis[i2]);
        float d3 = __ldg(&dis[i3]);
        float4 v0 = *(const float4*)&xs[(size_t)i0 * 128 + lane * 4];
        float4 v1 = *(const float4*)&xs[(size_t)i1 * 128 + lane * 4];
        float4 v2 = *(const float4*)&xs[(size_t)i2 * 128 + lane * 4];
        float4 v3 = *(const float4*)&xs[(size_t)i3 * 128 + lane * 4];
        sum.x = fmaf(d3, v3.x, fmaf(d2, v2.x, fmaf(d1, v1.x, fmaf(d0, v0.x, sum.x))));
        sum.y = fmaf(d3, v3.y, fmaf(d2, v2.y, fmaf(d1, v1.y, fmaf(d0, v0.y, sum.y))));
        sum.z = fmaf(d3, v3.z, fmaf(d2, v2.z, fmaf(d1, v1.z, fmaf(d0, v0.z, sum.z))));
        sum.w = fmaf(d3, v3.w, fmaf(d2, v2.w, fmaf(d1, v1.w, fmaf(d0, v0.w, sum.w))));
    }
    for (; t < e; t++) {
        int i0 = __ldg(&srt[t]);
        float d0 = __ldg(&dis[i0]);
        float4 v0 = *(const float4*)&xs[(size_t)i0 * 128 + lane * 4];
        sum.x = fmaf(d0, v0.x, sum.x); sum.y = fmaf(d0, v0.y, sum.y);
        sum.z = fmaf(d0, v0.z, sum.z); sum.w = fmaf(d0, v0.w, sum.w);
    }
    const float4 b = *(const float4*)&bias[lane * 4];
    float4 o;
    o.x = fmaxf(fmaf(d, sum.x, b.x), 0.f);
    o.y = fmaxf(fmaf(d, sum.y, b.y), 0.f);
    o.z = fmaxf(fmaf(d, sum.z, b.z), 0.f);
    o.w = fmaxf(fmaf(d, sum.w, b.w), 0.f);
    *(float4*)&out[(size_t)w * 128 + lane * 4] = o;
}

// ---------------- CSR gather F=64: one HALF-warp per node ----------------------
__global__ __launch_bounds__(256) void k_gather64(
    const int* __restrict__ off, const int* __restrict__ cnt,
    const int* __restrict__ srt, const float* __restrict__ xs,
    const float* __restrict__ dis, const float* __restrict__ bias,
    float* __restrict__ out, int n)
{
    int hw   = (blockIdx.x * blockDim.x + threadIdx.x) >> 4;   // half-warp id
    int lane = threadIdx.x & 15;
    if (hw >= n) return;
    int s = off[hw];
    int e = s + cnt[hw];
    float d = dis[hw];

    float4 sv = *(const float4*)&xs[(size_t)hw * 64 + lane * 4];
    float4 sum = make_float4(d * sv.x, d * sv.y, d * sv.z, d * sv.w);
    int t = s;
    for (; t + 4 <= e; t += 4) {
        int i0 = __ldg(&srt[t]);
        int i1 = __ldg(&srt[t + 1]);
        int i2 = __ldg(&srt[t + 2]);
        int i3 = __ldg(&srt[t + 3]);
        float d0 = __ldg(&dis[i0]);
        float d1 = __ldg(&dis[i1]);
        float d2 = __ldg(&dis[i2]);
        float d3 = __ldg(&dis[i3]);
        float4 v0 = *(const float4*)&xs[(size_t)i0 * 64 + lane * 4];
        float4 v1 = *(const float4*)&xs[(size_t)i1 * 64 + lane * 4];
        float4 v2 = *(const float4*)&xs[(size_t)i2 * 64 + lane * 4];
        float4 v3 = *(const float4*)&xs[(size_t)i3 * 64 + lane * 4];
        sum.x = fmaf(d3, v3.x, fmaf(d2, v2.x, fmaf(d1, v1.x, fmaf(d0, v0.x, sum.x))));
        sum.y = fmaf(d3, v3.y, fmaf(d2, v2.y, fmaf(d1, v1.y, fmaf(d0, v0.y, sum.y))));
        sum.z = fmaf(d3, v3.z, fmaf(d2, v2.z, fmaf(d1, v1.z, fmaf(d0, v0.z, sum.z))));
        sum.w = fmaf(d3, v3.w, fmaf(d2, v2.w, fmaf(d1, v1.w, fmaf(d0, v0.w, sum.w))));
    }
    for (; t < e; t++) {
        int i0 = __ldg(&srt[t]);
        float d0 = __ldg(&dis[i0]);
        float4 v0 = *(const float4*)&xs[(size_t)i0 * 64 + lane * 4];
        sum.x = fmaf(d0, v0.x, sum.x); sum.y = fmaf(d0, v0.y, sum.y);
        sum.z = fmaf(d0, v0.z, sum.z); sum.w = fmaf(d0, v0.w, sum.w);
    }
    const float4 b = *(const float4*)&bias[lane * 4];
    float4 o;
    o.x = fmaxf(fmaf(d, sum.x, b.x), 0.f);
    o.y = fmaxf(fmaf(d, sum.y, b.y), 0.f);
    o.z = fmaxf(fmaf(d, sum.z, b.z), 0.f);
    o.w = fmaxf(fmaf(d, sum.w, b.w), 0.f);
    *(float4*)&out[(size_t)hw * 64 + lane * 4] = o;
}

// ---------------- launch ----------------
extern "C" void kernel_launch(void* const* d_in, const int* in_sizes, int n_in,
                              void* d_out, int out_size)
{
    const float* x      = (const float*)d_in[0];
    const void*  ei     = d_in[1];
    const float* W_enc1 = (const float*)d_in[2];
    const float* b_enc1 = (const float*)d_in[3];
    const float* W_enc2 = (const float*)d_in[4];
    const float* b_enc2 = (const float*)d_in[5];
    const float* W_dec1 = (const float*)d_in[6];
    const float* b_dec1 = (const float*)d_in[7];
    const float* W_dec2 = (const float*)d_in[8];
    const float* b_dec2 = (const float*)d_in[9];
    float*       out    = (float*)d_out;

    const int M = in_sizes[0] / 128;   // 50000
    int E = in_sizes[1] / 2;           // 600000
    if (E > MAX_EDGES) E = MAX_EDGES;

    int *bad, *row, *col, *srt, *cnt, *off, *cur, *stat, *aggr, *pref;
    float *dis, *xs1, *z1, *xs2, *z2;
    cudaGetSymbolAddress((void**)&bad,  g_bad);
    cudaGetSymbolAddress((void**)&row,  g_row);
    cudaGetSymbolAddress((void**)&col,  g_col);
    cudaGetSymbolAddress((void**)&srt,  g_srt);
    cudaGetSymbolAddress((void**)&cnt,  g_cnt);
    cudaGetSymbolAddress((void**)&off,  g_off);
    cudaGetSymbolAddress((void**)&cur,  g_cur);
    cudaGetSymbolAddress((void**)&stat, g_stat);
    cudaGetSymbolAddress((void**)&aggr, g_aggr);
    cudaGetSymbolAddress((void**)&pref, g_pref);
    cudaGetSymbolAddress((void**)&dis,  g_dis);
    cudaGetSymbolAddress((void**)&xs1,  g_xs1);
    cudaGetSymbolAddress((void**)&z1,   g_z1);
    cudaGetSymbolAddress((void**)&xs2,  g_xs2);
    cudaGetSymbolAddress((void**)&z2,   g_z2);

    static bool attr_set = false;
    if (!attr_set) {
        cudaFuncSetAttribute(k_decoder, cudaFuncAttributeMaxDynamicSharedMemorySize,
                             DEC_SMEM_FLOATS * 4);
        attr_set = true;
    }

    const int TB = 256;
    const int EB = (E + TB - 1) / TB;
    const int NB = (M + 255) / 256;
    const int GB   = (M + 127) / 128;
    const int AGB1 = (M * 32 + TB - 1) / TB;
    const int AGB2 = (M * 16 + TB - 1) / TB;

    // 1: zero cnt/status + dtype sniff
    k_prep   <<<EB, TB>>>((const long long*)ei, E, M, cnt, stat, bad);
    // 2: convert + degree count
    k_convert<<<EB, TB>>>(ei, E, M, bad, row, col, cnt);
    // 3: single-pass scan -> off/cur/dis
    k_scan   <<<NB, 256>>>(cnt, M, off, cur, dis, stat, aggr, pref);
    // 4 (PROFILED SLOT): gemm1, unscaled xw
    k_gemm<128,128,3><<<GB, 256>>>(x, W_enc1, nullptr, xs1, M);
    // 5: CSR placement
    k_place  <<<EB, TB>>>(row, col, cur, srt, E);
    // 6: GCN layer 1 aggregation
    k_gather128<<<AGB1, TB>>>(off, cnt, srt, xs1, dis, b_enc1, z1, M);
    // 7: GCN layer 2 GEMM
    k_gemm<128,64,3><<<GB, 256>>>(z1, W_enc2, nullptr, xs2, M);
    // 8: GCN layer 2 aggregation (half-warp)
    k_gather64<<<AGB2, TB>>>(off, cnt, srt, xs2, dis, b_enc2, z2, M);
    // 9: fused decoder
    k_decoder<<<GB, 256, DEC_SMEM_FLOATS * 4>>>(z2, W_dec1, b_dec1, W_dec2, b_dec2, out, M);
}

// round 12
// speedup vs baseline: 1.0695x; 1.0695x over previous
#include <cuda_runtime.h>
#include <cuda_bf16.h>

// Problem constants (reference: N_NODES=50000, F=128, HIDDEN=128, OUT=64, E=600000)
#define MAX_NODES 50000
#define MAX_EDGES 600000
#define SCAN_NB ((MAX_NODES + 255) / 256)   // 196

// ---------------- scratch (device globals; no allocations allowed) -------------
__device__ int   g_bad = 0;
__device__ int   g_row [MAX_EDGES];
__device__ int   g_col [MAX_EDGES];
__device__ int   g_srt [MAX_EDGES];
__device__ int   g_cnt [MAX_NODES];
__device__ int   g_off [MAX_NODES];
__device__ int   g_cur [MAX_NODES];
__device__ int   g_stat[SCAN_NB];
__device__ int   g_aggr[SCAN_NB];
__device__ int   g_pref[SCAN_NB];
__device__ float g_dis [MAX_NODES];
__device__ float g_xs1 [MAX_NODES * 128];
__device__ float g_xs2 [MAX_NODES * 64];
__device__ float g_z2  [MAX_NODES * 64];
// bf16 split-precision operands
__device__ __nv_bfloat16 g_xhi [MAX_NODES * 128];
__device__ __nv_bfloat16 g_xlo [MAX_NODES * 128];
__device__ __nv_bfloat16 g_z1hi[MAX_NODES * 128];
__device__ __nv_bfloat16 g_z1lo[MAX_NODES * 128];
__device__ __nv_bfloat16 g_b1hi[128 * 128];   // W_enc1 transposed: B[n][k]
__device__ __nv_bfloat16 g_b1lo[128 * 128];
__device__ __nv_bfloat16 g_b2hi[64 * 128];    // W_enc2 transposed: B[n][k]
__device__ __nv_bfloat16 g_b2lo[64 * 128];

// ---------------- f32x2 packed-FMA helpers (decoder) ---------------------------
__device__ __forceinline__ void fma2(unsigned long long& acc,
                                     unsigned long long a, unsigned long long b) {
    asm("fma.rn.f32x2 %0, %1, %2, %0;" : "+l"(acc) : "l"(a), "l"(b));
}
__device__ __forceinline__ unsigned long long dup2(float f) {
    unsigned long long d; unsigned int u = __float_as_uint(f);
    asm("mov.b64 %0, {%1, %1};" : "=l"(d) : "r"(u));
    return d;
}
__device__ __forceinline__ float2 unpk2(unsigned long long v) {
    float2 f;
    asm("mov.b64 {%0, %1}, %2;" : "=f"(f.x), "=f"(f.y) : "l"(v));
    return f;
}

// ---------------- bf16 mma.sync helper (baseline PTX, sm_80+) ------------------
__device__ __forceinline__ void mma_bf16(float* c, const unsigned* a,
                                         unsigned b0, unsigned b1) {
    asm volatile(
        "mma.sync.aligned.m16n8k16.row.col.f32.bf16.bf16.f32 "
        "{%0,%1,%2,%3}, {%4,%5,%6,%7}, {%8,%9}, {%0,%1,%2,%3};"
        : "+f"(c[0]), "+f"(c[1]), "+f"(c[2]), "+f"(c[3])
        : "r"(a[0]), "r"(a[1]), "r"(a[2]), "r"(a[3]), "r"(b0), "r"(b1));
}

// ---------------- prep / convert / scan / place --------------------------------
__global__ void k_prep(const long long* __restrict__ ei, int E, int n,
                       int* __restrict__ cnt, int* __restrict__ stat,
                       int* __restrict__ bad) {
    int i = blockIdx.x * blockDim.x + threadIdx.x;
    if (i < n) cnt[i] = 0;
    if (i < SCAN_NB) stat[i] = 0;
    bool oob = false;
    if (i < E) {
        long long v = ei[i];
        oob = (v < 0 || v >= (long long)n);
    }
    unsigned m = __ballot_sync(0xFFFFFFFFu, oob);
    if (oob && (threadIdx.x & 31) == (__ffs(m) - 1)) {
        if (*bad == 0) atomicOr(bad, 1);
    }
}

__global__ void k_convert(const void* __restrict__ ei, int E, int n,
                          const int* __restrict__ bad,
                          int* __restrict__ row, int* __restrict__ col,
                          int* __restrict__ cnt) {
    int i = blockIdx.x * blockDim.x + threadIdx.x;
    if (i >= E) return;
    int r, c;
    if (*bad == 0) {
        r = (int)((const long long*)ei)[i];
        c = (int)((const long long*)ei)[(size_t)E + i];
    } else {
        r = ((const int*)ei)[i];
        c = ((const int*)ei)[(size_t)E + i];
    }
    if ((unsigned)r >= (unsigned)n) r = 0;
    if ((unsigned)c >= (unsigned)n) c = 0;
    row[i] = r;
    col[i] = c;
    atomicAdd(&cnt[c], 1);
}

__global__ __launch_bounds__(256) void k_scan(
    const int* __restrict__ cnt, int n,
    int* __restrict__ off, int* __restrict__ cur, float* __restrict__ dis,
    volatile int* stat, volatile int* aggr, volatile int* pref)
{
    __shared__ int sh[256];
    __shared__ int s_prefix;
    const int b = blockIdx.x;
    const int i = b * 256 + threadIdx.x;
    int v = (i < n) ? cnt[i] : 0;
    sh[threadIdx.x] = v;
    __syncthreads();
#pragma unroll
    for (int d = 1; d < 256; d <<= 1) {
        int t = (threadIdx.x >= d) ? sh[threadIdx.x - d] : 0;
        __syncthreads();
        sh[threadIdx.x] += t;
        __syncthreads();
    }
    int incl = sh[threadIdx.x];
    int total = sh[255];

    if (threadIdx.x == 0) {
        if (b == 0) {
            pref[0] = total;
            __threadfence();
            ((int*)stat)[0] = 2;
            s_prefix = 0;
        } else {
            aggr[b] = total;
            __threadfence();
            ((int*)stat)[b] = 1;
            int run = 0;
            int p = b - 1;
            while (true) {
                int st;
                do { st = stat[p]; } while (st == 0);
                __threadfence();
                if (st == 2) { run += pref[p]; break; }
                run += aggr[p];
                p--;
            }
            pref[b] = run + total;
            __threadfence();
            ((int*)stat)[b] = 2;
            s_prefix = run;
        }
    }
    __syncthreads();
    int prefix = s_prefix;
    if (i < n) {
        int o = prefix + incl - v;
        off[i] = o;
        cur[i] = o;
        dis[i] = rsqrtf((float)(v + 1));
    }
}

__global__ void k_place(const int* __restrict__ row, const int* __restrict__ col,
                        int* __restrict__ cur, int* __restrict__ srt, int E) {
    int e = blockIdx.x * blockDim.x + threadIdx.x;
    if (e >= E) return;
    int pos = atomicAdd(&cur[col[e]], 1);
    srt[pos] = row[e];
}

// ---------------- cvt: split x into bf16 hi/lo; transpose+split W1, W2 ---------
__global__ void k_cvt(const float* __restrict__ x, const float* __restrict__ W1,
                      const float* __restrict__ W2,
                      __nv_bfloat16* __restrict__ xhi, __nv_bfloat16* __restrict__ xlo,
                      __nv_bfloat16* __restrict__ b1hi, __nv_bfloat16* __restrict__ b1lo,
                      __nv_bfloat16* __restrict__ b2hi, __nv_bfloat16* __restrict__ b2lo,
                      int M)
{
    const int NX4 = M * 32;           // float4 count of x
    int gid = blockIdx.x * blockDim.x + threadIdx.x;
    if (gid < NX4) {
        float4 v = ((const float4*)x)[gid];
        __nv_bfloat16 h0 = __float2bfloat16(v.x), h1 = __float2bfloat16(v.y);
        __nv_bfloat16 h2 = __float2bfloat16(v.z), h3 = __float2bfloat16(v.w);
        __nv_bfloat16 l0 = __float2bfloat16(v.x - __bfloat162float(h0));
        __nv_bfloat16 l1 = __float2bfloat16(v.y - __bfloat162float(h1));
        __nv_bfloat16 l2 = __float2bfloat16(v.z - __bfloat162float(h2));
        __nv_bfloat16 l3 = __float2bfloat16(v.w - __bfloat162float(h3));
        __nv_bfloat162 a, b;
        a.x = h0; a.y = h1; b.x = h2; b.y = h3;
        *(__nv_bfloat162*)&xhi[(size_t)gid * 4]     = a;
        *(__nv_bfloat162*)&xhi[(size_t)gid * 4 + 2] = b;
        a.x = l0; a.y = l1; b.x = l2; b.y = l3;
        *(__nv_bfloat162*)&xlo[(size_t)gid * 4]     = a;
        *(__nv_bfloat162*)&xlo[(size_t)gid * 4 + 2] = b;
    } else if (gid < NX4 + 128 * 128) {
        int e = gid - NX4;
        int k = e >> 7, n = e & 127;
        float w = W1[e];
        __nv_bfloat16 h = __float2bfloat16(w);
        __nv_bfloat16 l = __float2bfloat16(w - __bfloat162float(h));
        b1hi[n * 128 + k] = h;
        b1lo[n * 128 + k] = l;
    } else if (gid < NX4 + 128 * 128 + 128 * 64) {
        int e = gid - NX4 - 128 * 128;
        int k = e >> 6, n = e & 63;
        float w = W2[e];
        __nv_bfloat16 h = __float2bfloat16(w);
        __nv_bfloat16 l = __float2bfloat16(w - __bfloat162float(h));
        b2hi[n * 128 + k] = h;
        b2lo[n * 128 + k] = l;
    }
}

// ---------------- mma.sync GEMM: out[M,N] = (Ahi+Alo)[M,128] @ B[N,128]^T ------
// Split precision: D = Ah*Bh + Ah*Bl + Al*Bh (fp32 accum).
// Block: 128 x N, 8 warps (4 m-groups x 2 n-groups), K=128 all-resident in smem.
// Row pitch 136 bf16 keeps the 32-bit fragment loads bank-conflict-free.
template<int N>
__global__ __launch_bounds__(256) void k_mmagemm(
    const __nv_bfloat16* __restrict__ Ahi, const __nv_bfloat16* __restrict__ Alo,
    const __nv_bfloat16* __restrict__ Bhi, const __nv_bfloat16* __restrict__ Blo,
    float* __restrict__ out, int M)
{
    constexpr int NT = N / 16;            // n8-tiles per warp (8 or 4)
    extern __shared__ __nv_bfloat16 smb[];
    __nv_bfloat16* Ah_s = smb;                       // [128][136]
    __nv_bfloat16* Al_s = smb + 128 * 136;
    __nv_bfloat16* Bh_s = smb + 2 * 128 * 136;       // [N][136]
    __nv_bfloat16* Bl_s = smb + 2 * 128 * 136 + N * 136;

    const int tid  = threadIdx.x;
    const int warp = tid >> 5;
    const int lane = tid & 31;
    const int gid  = lane >> 2;       // 0..7
    const int tig  = lane & 3;        // 0..3
    const int mbase = (warp >> 1) * 32;
    const int nbase = (warp & 1) * (N / 2);
    const int row0 = blockIdx.x * 128;

    // ---- load A tiles (zero-fill beyond M) ----
    for (int i = tid; i < 128 * 16; i += 256) {
        int r = i >> 4, c = i & 15;           // 16B chunks of 8 bf16
        int gr = row0 + r;
        uint4 vh = make_uint4(0,0,0,0), vl = make_uint4(0,0,0,0);
        if (gr < M) {
            vh = *(const uint4*)&Ahi[(size_t)gr * 128 + c * 8];
            vl = *(const uint4*)&Alo[(size_t)gr * 128 + c * 8];
        }
        *(uint4*)&Ah_s[r * 136 + c * 8] = vh;
        *(uint4*)&Al_s[r * 136 + c * 8] = vl;
    }
    // ---- load B tiles ----
    for (int i = tid; i < N * 16; i += 256) {
        int r = i >> 4, c = i & 15;
        *(uint4*)&Bh_s[r * 136 + c * 8] = *(const uint4*)&Bhi[(size_t)r * 128 + c * 8];
        *(uint4*)&Bl_s[r * 136 + c * 8] = *(const uint4*)&Blo[(size_t)r * 128 + c * 8];
    }
    __syncthreads();

    float acc[2][NT][4];
#pragma unroll
    for (int mi = 0; mi < 2; mi++)
#pragma unroll
        for (int nj = 0; nj < NT; nj++)
#pragma unroll
            for (int q = 0; q < 4; q++) acc[mi][nj][q] = 0.f;

#pragma unroll
    for (int pass = 0; pass < 3; pass++) {
        const __nv_bfloat16* As = (pass == 2) ? Al_s : Ah_s;
        const __nv_bfloat16* Bs = (pass == 1) ? Bl_s : Bh_s;
#pragma unroll
        for (int ks = 0; ks < 8; ks++) {
            const int k0 = ks * 16;
            unsigned a[2][4];
#pragma unroll
            for (int mi = 0; mi < 2; mi++) {
                int r = mbase + mi * 16 + gid;
                a[mi][0] = *(const unsigned*)&As[r * 136 + k0 + tig * 2];
                a[mi][1] = *(const unsigned*)&As[(r + 8) * 136 + k0 + tig * 2];
                a[mi][2] = *(const unsigned*)&As[r * 136 + k0 + 8 + tig * 2];
                a[mi][3] = *(const unsigned*)&As[(r + 8) * 136 + k0 + 8 + tig * 2];
            }
#pragma unroll
            for (int nj = 0; nj < NT; nj++) {
                int n = nbase + nj * 8 + gid;
                unsigned b0 = *(const unsigned*)&Bs[n * 136 + k0 + tig * 2];
                unsigned b1 = *(const unsigned*)&Bs[n * 136 + k0 + 8 + tig * 2];
#pragma unroll
                for (int mi = 0; mi < 2; mi++)
                    mma_bf16(acc[mi][nj], a[mi], b0, b1);
            }
        }
    }

    // ---- epilogue: c0,c1 = row gid cols tig*2..+1; c2,c3 = row gid+8 ----
#pragma unroll
    for (int mi = 0; mi < 2; mi++) {
#pragma unroll
        for (int nj = 0; nj < NT; nj++) {
            int r = row0 + mbase + mi * 16 + gid;
            int c = nbase + nj * 8 + tig * 2;
            if (r < M)
                *(float2*)&out[(size_t)r * N + c] =
                    make_float2(acc[mi][nj][0], acc[mi][nj][1]);
            if (r + 8 < M)
                *(float2*)&out[(size_t)(r + 8) * N + c] =
                    make_float2(acc[mi][nj][2], acc[mi][nj][3]);
        }
    }
}

// ---------------- fused decoder (f32x2, unchanged) -----------------------------
#define DEC_SMEM_FLOATS 49920
__global__ __launch_bounds__(256) void k_decoder(
    const float* __restrict__ Z2, const float* __restrict__ W1,
    const float* __restrict__ b1, const float* __restrict__ W2,
    const float* __restrict__ b2, float* __restrict__ out, int M)
{
    extern __shared__ float smf[];
    float* As1 = smf;
    float* Ws1 = smf + 8448;
    float* Ws2 = smf + 16640;
    float* Tt  = smf + 33024;

    const int tid = threadIdx.x;
    const int tx = tid % 16;
    const int ty = tid / 16;
    const int row0 = blockIdx.x * 128;

#pragma unroll
    for (int l = 0; l < 8; l++) {
        int idx = tid + l * 256;
        int r   = idx >> 4;
        int kg  = idx & 15;
        int gr  = row0 + r;
        float4 v = make_float4(0.f,0.f,0.f,0.f);
        if (gr < M) v = *(const float4*)&Z2[(size_t)gr * 64 + kg * 4];
        As1[(kg*4+0)*132 + r] = v.x;
        As1[(kg*4+1)*132 + r] = v.y;
        As1[(kg*4+2)*132 + r] = v.z;
        As1[(kg*4+3)*132 + r] = v.w;
    }
#pragma unroll
    for (int l = 0; l < 8; l++) {
        int idx = tid + l * 256;
        int r   = idx >> 5;
        int cg  = idx & 31;
        *(float4*)&Ws1[r*128 + cg*4] = *(const float4*)&W1[(size_t)r*128 + cg*4];
    }
#pragma unroll
    for (int l = 0; l < 16; l++) {
        int idx = tid + l * 256;
        int r   = idx >> 5;
        int cg  = idx & 31;
        *(float4*)&Ws2[r*128 + cg*4] = *(const float4*)&W2[(size_t)r*128 + cg*4];
    }
    __syncthreads();

    {
        unsigned long long acc2[4][8];
#pragma unroll
        for (int i = 0; i < 4; i++)
#pragma unroll
            for (int j = 0; j < 8; j++) acc2[i][j] = 0ull;

#pragma unroll
        for (int k = 0; k < 64; k++) {
            unsigned long long ap[4];
#pragma unroll
            for (int i = 0; i < 2; i++) {
                ulonglong2 t = *(const ulonglong2*)&As1[k*132 + ty*8 + i*4];
                ap[i*2]   = t.x;
                ap[i*2+1] = t.y;
            }
            float4 w0 = *(const float4*)&Ws1[k*128 + tx*8];
            float4 w1 = *(const float4*)&Ws1[k*128 + tx*8 + 4];
            unsigned long long wd[8];
            wd[0] = dup2(w0.x); wd[1] = dup2(w0.y);
            wd[2] = dup2(w0.z); wd[3] = dup2(w0.w);
            wd[4] = dup2(w1.x); wd[5] = dup2(w1.y);
            wd[6] = dup2(w1.z); wd[7] = dup2(w1.w);
#pragma unroll
            for (int i = 0; i < 4; i++)
#pragma unroll
                for (int j = 0; j < 8; j++)
                    fma2(acc2[i][j], ap[i], wd[j]);
        }
#pragma unroll
        for (int i = 0; i < 4; i++) {
            int r0 = ty * 8 + 2 * i;
#pragma unroll
            for (int j = 0; j < 8; j++) {
                float2 f = unpk2(acc2[i][j]);
                float b = b1[tx*8 + j];
                Tt[(tx*8+j)*132 + r0]     = fmaxf(f.x + b, 0.f);
                Tt[(tx*8+j)*132 + r0 + 1] = fmaxf(f.y + b, 0.f);
            }
        }
    }
    __syncthreads();

    {
        unsigned long long acc2[4][8];
#pragma unroll
        for (int i = 0; i < 4; i++)
#pragma unroll
            for (int j = 0; j < 8; j++) acc2[i][j] = 0ull;

#pragma unroll
        for (int k = 0; k < 128; k++) {
            unsigned long long ap[4];
#pragma unroll
            for (int i = 0; i < 2; i++) {
                ulonglong2 t = *(const ulonglong2*)&Tt[k*132 + ty*8 + i*4];
                ap[i*2]   = t.x;
                ap[i*2+1] = t.y;
            }
            float4 w0 = *(const float4*)&Ws2[k*128 + tx*8];
            float4 w1 = *(const float4*)&Ws2[k*128 + tx*8 + 4];
            unsigned long long wd[8];
            wd[0] = dup2(w0.x); wd[1] = dup2(w0.y);
            wd[2] = dup2(w0.z); wd[3] = dup2(w0.w);
            wd[4] = dup2(w1.x); wd[5] = dup2(w1.y);
            wd[6] = dup2(w1.z); wd[7] = dup2(w1.w);
#pragma unroll
            for (int i = 0; i < 4; i++)
#pragma unroll
                for (int j = 0; j < 8; j++)
                    fma2(acc2[i][j], ap[i], wd[j]);
        }

        float bb[8];
#pragma unroll
        for (int j = 0; j < 8; j++) bb[j] = b2[tx*8 + j];
#pragma unroll
        for (int i = 0; i < 4; i++) {
            int r0 = row0 + ty * 8 + 2 * i;
#pragma unroll
            for (int h = 0; h < 2; h++) {
                int r = r0 + h;
                if (r >= M) continue;
                float o[8];
#pragma unroll
                for (int j = 0; j < 8; j++) {
                    float2 f = unpk2(acc2[i][j]);
                    o[j] = (h ? f.y : f.x) + bb[j];
                }
                size_t ob = (size_t)r * 128 + tx * 8;
                *(float4*)&out[ob]     = make_float4(o[0], o[1], o[2], o[3]);
                *(float4*)&out[ob + 4] = make_float4(o[4], o[5], o[6], o[7]);
            }
        }
    }
}

// ---------------- CSR gather F=128 -> bf16 hi/lo output ------------------------
__global__ __launch_bounds__(256) void k_gather128(
    const int* __restrict__ off, const int* __restrict__ cnt,
    const int* __restrict__ srt, const float* __restrict__ xs,
    const float* __restrict__ dis, const float* __restrict__ bias,
    __nv_bfloat16* __restrict__ zhi, __nv_bfloat16* __restrict__ zlo, int n)
{
    int w    = (blockIdx.x * blockDim.x + threadIdx.x) >> 5;
    int lane = threadIdx.x & 31;
    if (w >= n) return;
    int s = off[w];
    int e = s + cnt[w];
    float d = dis[w];

    float4 sv = *(const float4*)&xs[(size_t)w * 128 + lane * 4];
    float4 sum = make_float4(d * sv.x, d * sv.y, d * sv.z, d * sv.w);
    int t = s;
    for (; t + 4 <= e; t += 4) {
        int i0 = __ldg(&srt[t]);
        int i1 = __ldg(&srt[t + 1]);
        int i2 = __ldg(&srt[t + 2]);
        int i3 = __ldg(&srt[t + 3]);
        float d0 = __ldg(&dis[i0]);
        float d1 = __ldg(&dis[i1]);
        float d2 = __ldg(&dis[i2]);
        float d3 = __ldg(&dis[i3]);
        float4 v0 = *(const float4*)&xs[(size_t)i0 * 128 + lane * 4];
        float4 v1 = *(const float4*)&xs[(size_t)i1 * 128 + lane * 4];
        float4 v2 = *(const float4*)&xs[(size_t)i2 * 128 + lane * 4];
        float4 v3 = *(const float4*)&xs[(size_t)i3 * 128 + lane * 4];
        sum.x = fmaf(d3, v3.x, fmaf(d2, v2.x, fmaf(d1, v1.x, fmaf(d0, v0.x, sum.x))));
        sum.y = fmaf(d3, v3.y, fmaf(d2, v2.y, fmaf(d1, v1.y, fmaf(d0, v0.y, sum.y))));
        sum.z = fmaf(d3, v3.z, fmaf(d2, v2.z, fmaf(d1, v1.z, fmaf(d0, v0.z, sum.z))));
        sum.w = fmaf(d3, v3.w, fmaf(d2, v2.w, fmaf(d1, v1.w, fmaf(d0, v0.w, sum.w))));
    }
    for (; t < e; t++) {
        int i0 = __ldg(&srt[t]);
        float d0 = __ldg(&dis[i0]);
        float4 v0 = *(const float4*)&xs[(size_t)i0 * 128 + lane * 4];
        sum.x = fmaf(d0, v0.x, sum.x); sum.y = fmaf(d0, v0.y, sum.y);
        sum.z = fmaf(d0, v0.z, sum.z); sum.w = fmaf(d0, v0.w, sum.w);
    }
    const float4 b = *(const float4*)&bias[lane * 4];
    float o0 = fmaxf(fmaf(d, sum.x, b.x), 0.f);
    float o1 = fmaxf(fmaf(d, sum.y, b.y), 0.f);
    float o2 = fmaxf(fmaf(d, sum.z, b.z), 0.f);
    float o3 = fmaxf(fmaf(d, sum.w, b.w), 0.f);

    __nv_bfloat16 h0 = __float2bfloat16(o0), h1 = __float2bfloat16(o1);
    __nv_bfloat16 h2 = __float2bfloat16(o2), h3 = __float2bfloat16(o3);
    __nv_bfloat16 l0 = __float2bfloat16(o0 - __bfloat162float(h0));
    __nv_bfloat16 l1 = __float2bfloat16(o1 - __bfloat162float(h1));
    __nv_bfloat16 l2 = __float2bfloat16(o2 - __bfloat162float(h2));
    __nv_bfloat16 l3 = __float2bfloat16(o3 - __bfloat162float(h3));
    __nv_bfloat162 p;
    size_t ob = (size_t)w * 128 + lane * 4;
    p.x = h0; p.y = h1; *(__nv_bfloat162*)&zhi[ob]     = p;
    p.x = h2; p.y = h3; *(__nv_bfloat162*)&zhi[ob + 2] = p;
    p.x = l0; p.y = l1; *(__nv_bfloat162*)&zlo[ob]     = p;
    p.x = l2; p.y = l3; *(__nv_bfloat162*)&zlo[ob + 2] = p;
}

// ---------------- CSR gather F=64 (half-warp, fp32 out) ------------------------
__global__ __launch_bounds__(256) void k_gather64(
    const int* __restrict__ off, const int* __restrict__ cnt,
    const int* __restrict__ srt, const float* __restrict__ xs,
    const float* __restrict__ dis, const float* __restrict__ bias,
    float* __restrict__ out, int n)
{
    int hw   = (blockIdx.x * blockDim.x + threadIdx.x) >> 4;
    int lane = threadIdx.x & 15;
    if (hw >= n) return;
    int s = off[hw];
    int e = s + cnt[hw];
    float d = dis[hw];

    float4 sv = *(const float4*)&xs[(size_t)hw * 64 + lane * 4];
    float4 sum = make_float4(d * sv.x, d * sv.y, d * sv.z, d * sv.w);
    int t = s;
    for (; t + 4 <= e; t += 4) {
        int i0 = __ldg(&srt[t]);
        int i1 = __ldg(&srt[t + 1]);
        int i2 = __ldg(&srt[t + 2]);
        int i3 = __ldg(&srt[t + 3]);
        float d0 = __ldg(&dis[i0]);
        float d1 = __ldg(&dis[i1]);
        float d2 = __ldg(&dis[i2]);
        float d3 = __ldg(&dis[i3]);
        float4 v0 = *(const float4*)&xs[(size_t)i0 * 64 + lane * 4];
        float4 v1 = *(const float4*)&xs[(size_t)i1 * 64 + lane * 4];
        float4 v2 = *(const float4*)&xs[(size_t)i2 * 64 + lane * 4];
        float4 v3 = *(const float4*)&xs[(size_t)i3 * 64 + lane * 4];
        sum.x = fmaf(d3, v3.x, fmaf(d2, v2.x, fmaf(d1, v1.x, fmaf(d0, v0.x, sum.x))));
        sum.y = fmaf(d3, v3.y, fmaf(d2, v2.y, fmaf(d1, v1.y, fmaf(d0, v0.y, sum.y))));
        sum.z = fmaf(d3, v3.z, fmaf(d2, v2.z, fmaf(d1, v1.z, fmaf(d0, v0.z, sum.z))));
        sum.w = fmaf(d3, v3.w, fmaf(d2, v2.w, fmaf(d1, v1.w, fmaf(d0, v0.w, sum.w))));
    }
    for (; t < e; t++) {
        int i0 = __ldg(&srt[t]);
        float d0 = __ldg(&dis[i0]);
        float4 v0 = *(const float4*)&xs[(size_t)i0 * 64 + lane * 4];
        sum.x = fmaf(d0, v0.x, sum.x); sum.y = fmaf(d0, v0.y, sum.y);
        sum.z = fmaf(d0, v0.z, sum.z); sum.w = fmaf(d0, v0.w, sum.w);
    }
    const float4 b = *(const float4*)&bias[lane * 4];
    float4 o;
    o.x = fmaxf(fmaf(d, sum.x, b.x), 0.f);
    o.y = fmaxf(fmaf(d, sum.y, b.y), 0.f);
    o.z = fmaxf(fmaf(d, sum.z, b.z), 0.f);
    o.w = fmaxf(fmaf(d, sum.w, b.w), 0.f);
    *(float4*)&out[(size_t)hw * 64 + lane * 4] = o;
}

// ---------------- launch ----------------
extern "C" void kernel_launch(void* const* d_in, const int* in_sizes, int n_in,
                              void* d_out, int out_size)
{
    const float* x      = (const float*)d_in[0];
    const void*  ei     = d_in[1];
    const float* W_enc1 = (const float*)d_in[2];
    const float* b_enc1 = (const float*)d_in[3];
    const float* W_enc2 = (const float*)d_in[4];
    const float* b_enc2 = (const float*)d_in[5];
    const float* W_dec1 = (const float*)d_in[6];
    const float* b_dec1 = (const float*)d_in[7];
    const float* W_dec2 = (const float*)d_in[8];
    const float* b_dec2 = (const float*)d_in[9];
    float*       out    = (float*)d_out;

    const int M = in_sizes[0] / 128;   // 50000
    int E = in_sizes[1] / 2;           // 600000
    if (E > MAX_EDGES) E = MAX_EDGES;

    int *bad, *row, *col, *srt, *cnt, *off, *cur, *stat, *aggr, *pref;
    float *dis, *xs1, *xs2, *z2;
    __nv_bfloat16 *xhi, *xlo, *z1hi, *z1lo, *b1hi, *b1lo, *b2hi, *b2lo;
    cudaGetSymbolAddress((void**)&bad,  g_bad);
    cudaGetSymbolAddress((void**)&row,  g_row);
    cudaGetSymbolAddress((void**)&col,  g_col);
    cudaGetSymbolAddress((void**)&srt,  g_srt);
    cudaGetSymbolAddress((void**)&cnt,  g_cnt);
    cudaGetSymbolAddress((void**)&off,  g_off);
    cudaGetSymbolAddress((void**)&cur,  g_cur);
    cudaGetSymbolAddress((void**)&stat, g_stat);
    cudaGetSymbolAddress((void**)&aggr, g_aggr);
    cudaGetSymbolAddress((void**)&pref, g_pref);
    cudaGetSymbolAddress((void**)&dis,  g_dis);
    cudaGetSymbolAddress((void**)&xs1,  g_xs1);
    cudaGetSymbolAddress((void**)&xs2,  g_xs2);
    cudaGetSymbolAddress((void**)&z2,   g_z2);
    cudaGetSymbolAddress((void**)&xhi,  g_xhi);
    cudaGetSymbolAddress((void**)&xlo,  g_xlo);
    cudaGetSymbolAddress((void**)&z1hi, g_z1hi);
    cudaGetSymbolAddress((void**)&z1lo, g_z1lo);
    cudaGetSymbolAddress((void**)&b1hi, g_b1hi);
    cudaGetSymbolAddress((void**)&b1lo, g_b1lo);
    cudaGetSymbolAddress((void**)&b2hi, g_b2hi);
    cudaGetSymbolAddress((void**)&b2lo, g_b2lo);

    const int TG1 = (2 * 128 * 136 + 2 * 128 * 136) * 2;  // 139264 B
    const int TG2 = (2 * 128 * 136 + 2 * 64 * 136) * 2;   // 104448 B
    static bool attr_set = false;
    if (!attr_set) {
        cudaFuncSetAttribute(k_decoder, cudaFuncAttributeMaxDynamicSharedMemorySize,
                             DEC_SMEM_FLOATS * 4);
        cudaFuncSetAttribute(k_mmagemm<128>, cudaFuncAttributeMaxDynamicSharedMemorySize, TG1);
        cudaFuncSetAttribute(k_mmagemm<64>,  cudaFuncAttributeMaxDynamicSharedMemorySize, TG2);
        attr_set = true;
    }

    const int TB = 256;
    const int EB = (E + TB - 1) / TB;
    const int NB = (M + 255) / 256;
    const int GB   = (M + 127) / 128;
    const int AGB1 = (M * 32 + TB - 1) / TB;
    const int AGB2 = (M * 16 + TB - 1) / TB;
    const int CVB  = (M * 32 + 128 * 128 + 128 * 64 + TB - 1) / TB;

    // 1: split x / transpose+split W1,W2
    k_cvt    <<<CVB, TB>>>(x, W_enc1, W_enc2, xhi, xlo, b1hi, b1lo, b2hi, b2lo, M);
    // 2: zero cnt/status + dtype sniff
    k_prep   <<<EB, TB>>>((const long long*)ei, E, M, cnt, stat, bad);
    // 3: convert + degree count
    k_convert<<<EB, TB>>>(ei, E, M, bad, row, col, cnt);
    // 4 (PROFILED SLOT): tensor gemm1 -> xs1 (unscaled xw, fp32)
    k_mmagemm<128><<<GB, 256, TG1>>>(xhi, xlo, b1hi, b1lo, xs1, M);
    // 5: single-pass scan -> off/cur/dis
    k_scan   <<<NB, 256>>>(cnt, M, off, cur, dis, stat, aggr, pref);
    // 6: CSR placement
    k_place  <<<EB, TB>>>(row, col, cur, srt, E);
    // 7: GCN layer 1 aggregation -> z1 hi/lo bf16
    k_gather128<<<AGB1, TB>>>(off, cnt, srt, xs1, dis, b_enc1, z1hi, z1lo, M);
    // 8: tensor gemm2 -> xs2 fp32
    k_mmagemm<64><<<GB, 256, TG2>>>(z1hi, z1lo, b2hi, b2lo, xs2, M);
    // 9: GCN layer 2 aggregation -> z2 fp32
    k_gather64<<<AGB2, TB>>>(off, cnt, srt, xs2, dis, b_enc2, z2, M);
    // 10: fused decoder
    k_decoder<<<GB, 256, DEC_SMEM_FLOATS * 4>>>(z2, W_dec1, b_dec1, W_dec2, b_dec2, out, M);
}

// round 13
// speedup vs baseline: 1.0705x; 1.0010x over previous
#include <cuda_runtime.h>
#include <cuda_bf16.h>

// Problem constants (reference: N_NODES=50000, F=128, HIDDEN=128, OUT=64, E=600000)
#define MAX_NODES 50000
#define MAX_EDGES 600000
#define SCAN_NB ((MAX_NODES + 255) / 256)   // 196

// ---------------- scratch (device globals; no allocations allowed) -------------
__device__ int   g_bad = 0;
__device__ int   g_row [MAX_EDGES];
__device__ int   g_col [MAX_EDGES];
__device__ int   g_srt [MAX_EDGES];
__device__ int   g_cnt [MAX_NODES];
__device__ int   g_off [MAX_NODES];
__device__ int   g_cur [MAX_NODES];
__device__ int   g_stat[SCAN_NB];
__device__ int   g_aggr[SCAN_NB];
__device__ int   g_pref[SCAN_NB];
__device__ float g_dis [MAX_NODES];
__device__ float g_xs1 [MAX_NODES * 128];
__device__ float g_xs2 [MAX_NODES * 64];
__device__ float g_z2  [MAX_NODES * 64];
// bf16 split-precision operands
__device__ __nv_bfloat16 g_xhi [MAX_NODES * 128];
__device__ __nv_bfloat16 g_xlo [MAX_NODES * 128];
__device__ __nv_bfloat16 g_z1hi[MAX_NODES * 128];
__device__ __nv_bfloat16 g_z1lo[MAX_NODES * 128];
__device__ __nv_bfloat16 g_b1hi[128 * 128];   // W_enc1 transposed: B[n][k]
__device__ __nv_bfloat16 g_b1lo[128 * 128];
__device__ __nv_bfloat16 g_b2hi[64 * 128];    // W_enc2 transposed: B[n][k]
__device__ __nv_bfloat16 g_b2lo[64 * 128];

// ---------------- f32x2 packed-FMA helpers (decoder) ---------------------------
__device__ __forceinline__ void fma2(unsigned long long& acc,
                                     unsigned long long a, unsigned long long b) {
    asm("fma.rn.f32x2 %0, %1, %2, %0;" : "+l"(acc) : "l"(a), "l"(b));
}
__device__ __forceinline__ unsigned long long dup2(float f) {
    unsigned long long d; unsigned int u = __float_as_uint(f);
    asm("mov.b64 %0, {%1, %1};" : "=l"(d) : "r"(u));
    return d;
}
__device__ __forceinline__ float2 unpk2(unsigned long long v) {
    float2 f;
    asm("mov.b64 {%0, %1}, %2;" : "=f"(f.x), "=f"(f.y) : "l"(v));
    return f;
}

// ---------------- bf16 mma.sync helper (baseline PTX, sm_80+) ------------------
__device__ __forceinline__ void mma_bf16(float* c, const unsigned* a,
                                         unsigned b0, unsigned b1) {
    asm volatile(
        "mma.sync.aligned.m16n8k16.row.col.f32.bf16.bf16.f32 "
        "{%0,%1,%2,%3}, {%4,%5,%6,%7}, {%8,%9}, {%0,%1,%2,%3};"
        : "+f"(c[0]), "+f"(c[1]), "+f"(c[2]), "+f"(c[3])
        : "r"(a[0]), "r"(a[1]), "r"(a[2]), "r"(a[3]), "r"(b0), "r"(b1));
}

// ---------------- prep / convert / scan / place --------------------------------
__global__ void k_prep(const long long* __restrict__ ei, int E, int n,
                       int* __restrict__ cnt, int* __restrict__ stat,
                       int* __restrict__ bad) {
    int i = blockIdx.x * blockDim.x + threadIdx.x;
    if (i < n) cnt[i] = 0;
    if (i < SCAN_NB) stat[i] = 0;
    bool oob = false;
    if (i < E) {
        long long v = ei[i];
        oob = (v < 0 || v >= (long long)n);
    }
    unsigned m = __ballot_sync(0xFFFFFFFFu, oob);
    if (oob && (threadIdx.x & 31) == (__ffs(m) - 1)) {
        if (*bad == 0) atomicOr(bad, 1);
    }
}

__global__ void k_convert(const void* __restrict__ ei, int E, int n,
                          const int* __restrict__ bad,
                          int* __restrict__ row, int* __restrict__ col,
                          int* __restrict__ cnt) {
    int i = blockIdx.x * blockDim.x + threadIdx.x;
    if (i >= E) return;
    int r, c;
    if (*bad == 0) {
        r = (int)((const long long*)ei)[i];
        c = (int)((const long long*)ei)[(size_t)E + i];
    } else {
        r = ((const int*)ei)[i];
        c = ((const int*)ei)[(size_t)E + i];
    }
    if ((unsigned)r >= (unsigned)n) r = 0;
    if ((unsigned)c >= (unsigned)n) c = 0;
    row[i] = r;
    col[i] = c;
    atomicAdd(&cnt[c], 1);
}

__global__ __launch_bounds__(256) void k_scan(
    const int* __restrict__ cnt, int n,
    int* __restrict__ off, int* __restrict__ cur, float* __restrict__ dis,
    volatile int* stat, volatile int* aggr, volatile int* pref)
{
    __shared__ int sh[256];
    __shared__ int s_prefix;
    const int b = blockIdx.x;
    const int i = b * 256 + threadIdx.x;
    int v = (i < n) ? cnt[i] : 0;
    sh[threadIdx.x] = v;
    __syncthreads();
#pragma unroll
    for (int d = 1; d < 256; d <<= 1) {
        int t = (threadIdx.x >= d) ? sh[threadIdx.x - d] : 0;
        __syncthreads();
        sh[threadIdx.x] += t;
        __syncthreads();
    }
    int incl = sh[threadIdx.x];
    int total = sh[255];

    if (threadIdx.x == 0) {
        if (b == 0) {
            pref[0] = total;
            __threadfence();
            ((int*)stat)[0] = 2;
            s_prefix = 0;
        } else {
            aggr[b] = total;
            __threadfence();
            ((int*)stat)[b] = 1;
            int run = 0;
            int p = b - 1;
            while (true) {
                int st;
                do { st = stat[p]; } while (st == 0);
                __threadfence();
                if (st == 2) { run += pref[p]; break; }
                run += aggr[p];
                p--;
            }
            pref[b] = run + total;
            __threadfence();
            ((int*)stat)[b] = 2;
            s_prefix = run;
        }
    }
    __syncthreads();
    int prefix = s_prefix;
    if (i < n) {
        int o = prefix + incl - v;
        off[i] = o;
        cur[i] = o;
        dis[i] = rsqrtf((float)(v + 1));
    }
}

__global__ void k_place(const int* __restrict__ row, const int* __restrict__ col,
                        int* __restrict__ cur, int* __restrict__ srt, int E) {
    int e = blockIdx.x * blockDim.x + threadIdx.x;
    if (e >= E) return;
    int pos = atomicAdd(&cur[col[e]], 1);
    srt[pos] = row[e];
}

// ---------------- cvt: split x into bf16 hi/lo; transpose+split W1, W2 ---------
__global__ void k_cvt(const float* __restrict__ x, const float* __restrict__ W1,
                      const float* __restrict__ W2,
                      __nv_bfloat16* __restrict__ xhi, __nv_bfloat16* __restrict__ xlo,
                      __nv_bfloat16* __restrict__ b1hi, __nv_bfloat16* __restrict__ b1lo,
                      __nv_bfloat16* __restrict__ b2hi, __nv_bfloat16* __restrict__ b2lo,
                      int M)
{
    const int NX4 = M * 32;           // float4 count of x
    int gid = blockIdx.x * blockDim.x + threadIdx.x;
    if (gid < NX4) {
        float4 v = ((const float4*)x)[gid];
        __nv_bfloat16 h0 = __float2bfloat16(v.x), h1 = __float2bfloat16(v.y);
        __nv_bfloat16 h2 = __float2bfloat16(v.z), h3 = __float2bfloat16(v.w);
        __nv_bfloat16 l0 = __float2bfloat16(v.x - __bfloat162float(h0));
        __nv_bfloat16 l1 = __float2bfloat16(v.y - __bfloat162float(h1));
        __nv_bfloat16 l2 = __float2bfloat16(v.z - __bfloat162float(h2));
        __nv_bfloat16 l3 = __float2bfloat16(v.w - __bfloat162float(h3));
        __nv_bfloat162 a, b;
        a.x = h0; a.y = h1; b.x = h2; b.y = h3;
        *(__nv_bfloat162*)&xhi[(size_t)gid * 4]     = a;
        *(__nv_bfloat162*)&xhi[(size_t)gid * 4 + 2] = b;
        a.x = l0; a.y = l1; b.x = l2; b.y = l3;
        *(__nv_bfloat162*)&xlo[(size_t)gid * 4]     = a;
        *(__nv_bfloat162*)&xlo[(size_t)gid * 4 + 2] = b;
    } else if (gid < NX4 + 128 * 128) {
        int e = gid - NX4;
        int k = e >> 7, n = e & 127;
        float w = W1[e];
        __nv_bfloat16 h = __float2bfloat16(w);
        __nv_bfloat16 l = __float2bfloat16(w - __bfloat162float(h));
        b1hi[n * 128 + k] = h;
        b1lo[n * 128 + k] = l;
    } else if (gid < NX4 + 128 * 128 + 128 * 64) {
        int e = gid - NX4 - 128 * 128;
        int k = e >> 6, n = e & 63;
        float w = W2[e];
        __nv_bfloat16 h = __float2bfloat16(w);
        __nv_bfloat16 l = __float2bfloat16(w - __bfloat162float(h));
        b2hi[n * 128 + k] = h;
        b2lo[n * 128 + k] = l;
    }
}

// ---------------- mma.sync GEMM: out[M,N] = (Ahi+Alo)[M,128] @ B[N,128]^T ------
// Split precision: D = Ah*Bh + Ah*Bl + Al*Bh (fp32 accum).
// Block: 64 x N, 8 warps (4 m-tiles of 16 x 2 n-groups). K=128 smem-resident.
// Row pitch 136 bf16: fragment word addr = 68*gid+tig = 4*gid+tig (mod 32),
// all distinct -> conflict-free.
template<int N>
__global__ __launch_bounds__(256, 2) void k_mmagemm(
    const __nv_bfloat16* __restrict__ Ahi, const __nv_bfloat16* __restrict__ Alo,
    const __nv_bfloat16* __restrict__ Bhi, const __nv_bfloat16* __restrict__ Blo,
    float* __restrict__ out, int M)
{
    constexpr int NT = N / 16;            // n8-tiles per warp (8 or 4)
    extern __shared__ __nv_bfloat16 smb[];
    __nv_bfloat16* Ah_s = smb;                      // [64][136]
    __nv_bfloat16* Al_s = smb + 64 * 136;
    __nv_bfloat16* Bh_s = smb + 2 * 64 * 136;       // [N][136]
    __nv_bfloat16* Bl_s = smb + 2 * 64 * 136 + N * 136;

    const int tid  = threadIdx.x;
    const int warp = tid >> 5;
    const int lane = tid & 31;
    const int gid  = lane >> 2;       // 0..7
    const int tig  = lane & 3;        // 0..3
    const int mbase = (warp >> 1) * 16;
    const int nbase = (warp & 1) * (N / 2);
    const int row0 = blockIdx.x * 64;

    // ---- load A tiles (zero-fill beyond M) ----
    for (int i = tid; i < 64 * 16; i += 256) {
        int r = i >> 4, c = i & 15;           // 16B chunks of 8 bf16
        int gr = row0 + r;
        uint4 vh = make_uint4(0,0,0,0), vl = make_uint4(0,0,0,0);
        if (gr < M) {
            vh = *(const uint4*)&Ahi[(size_t)gr * 128 + c * 8];
            vl = *(const uint4*)&Alo[(size_t)gr * 128 + c * 8];
        }
        *(uint4*)&Ah_s[r * 136 + c * 8] = vh;
        *(uint4*)&Al_s[r * 136 + c * 8] = vl;
    }
    // ---- load B tiles ----
    for (int i = tid; i < N * 16; i += 256) {
        int r = i >> 4, c = i & 15;
        *(uint4*)&Bh_s[r * 136 + c * 8] = *(const uint4*)&Bhi[(size_t)r * 128 + c * 8];
        *(uint4*)&Bl_s[r * 136 + c * 8] = *(const uint4*)&Blo[(size_t)r * 128 + c * 8];
    }
    __syncthreads();

    float acc[NT][4];
#pragma unroll
    for (int nj = 0; nj < NT; nj++)
#pragma unroll
        for (int q = 0; q < 4; q++) acc[nj][q] = 0.f;

#pragma unroll
    for (int pass = 0; pass < 3; pass++) {
        const __nv_bfloat16* As = (pass == 2) ? Al_s : Ah_s;
        const __nv_bfloat16* Bs = (pass == 1) ? Bl_s : Bh_s;
#pragma unroll
        for (int ks = 0; ks < 8; ks++) {
            const int k0 = ks * 16;
            unsigned a[4];
            {
                int r = mbase + gid;
                a[0] = *(const unsigned*)&As[r * 136 + k0 + tig * 2];
                a[1] = *(const unsigned*)&As[(r + 8) * 136 + k0 + tig * 2];
                a[2] = *(const unsigned*)&As[r * 136 + k0 + 8 + tig * 2];
                a[3] = *(const unsigned*)&As[(r + 8) * 136 + k0 + 8 + tig * 2];
            }
#pragma unroll
            for (int nj = 0; nj < NT; nj++) {
                int n = nbase + nj * 8 + gid;
                unsigned b0 = *(const unsigned*)&Bs[n * 136 + k0 + tig * 2];
                unsigned b1 = *(const unsigned*)&Bs[n * 136 + k0 + 8 + tig * 2];
                mma_bf16(acc[nj], a, b0, b1);
            }
        }
    }

    // ---- epilogue: c0,c1 = row gid cols tig*2..+1; c2,c3 = row gid+8 ----
#pragma unroll
    for (int nj = 0; nj < NT; nj++) {
        int r = row0 + mbase + gid;
        int c = nbase + nj * 8 + tig * 2;
        if (r < M)
            *(float2*)&out[(size_t)r * N + c] = make_float2(acc[nj][0], acc[nj][1]);
        if (r + 8 < M)
            *(float2*)&out[(size_t)(r + 8) * N + c] = make_float2(acc[nj][2], acc[nj][3]);
    }
}

// ---------------- fused decoder (f32x2, unchanged) -----------------------------
#define DEC_SMEM_FLOATS 49920
__global__ __launch_bounds__(256) void k_decoder(
    const float* __restrict__ Z2, const float* __restrict__ W1,
    const float* __restrict__ b1, const float* __restrict__ W2,
    const float* __restrict__ b2, float* __restrict__ out, int M)
{
    extern __shared__ float smf[];
    float* As1 = smf;
    float* Ws1 = smf + 8448;
    float* Ws2 = smf + 16640;
    float* Tt  = smf + 33024;

    const int tid = threadIdx.x;
    const int tx = tid % 16;
    const int ty = tid / 16;
    const int row0 = blockIdx.x * 128;

#pragma unroll
    for (int l = 0; l < 8; l++) {
        int idx = tid + l * 256;
        int r   = idx >> 4;
        int kg  = idx & 15;
        int gr  = row0 + r;
        float4 v = make_float4(0.f,0.f,0.f,0.f);
        if (gr < M) v = *(const float4*)&Z2[(size_t)gr * 64 + kg * 4];
        As1[(kg*4+0)*132 + r] = v.x;
        As1[(kg*4+1)*132 + r] = v.y;
        As1[(kg*4+2)*132 + r] = v.z;
        As1[(kg*4+3)*132 + r] = v.w;
    }
#pragma unroll
    for (int l = 0; l < 8; l++) {
        int idx = tid + l * 256;
        int r   = idx >> 5;
        int cg  = idx & 31;
        *(float4*)&Ws1[r*128 + cg*4] = *(const float4*)&W1[(size_t)r*128 + cg*4];
    }
#pragma unroll
    for (int l = 0; l < 16; l++) {
        int idx = tid + l * 256;
        int r   = idx >> 5;
        int cg  = idx & 31;
        *(float4*)&Ws2[r*128 + cg*4] = *(const float4*)&W2[(size_t)r*128 + cg*4];
    }
    __syncthreads();

    {
        unsigned long long acc2[4][8];
#pragma unroll
        for (int i = 0; i < 4; i++)
#pragma unroll
            for (int j = 0; j < 8; j++) acc2[i][j] = 0ull;

#pragma unroll
        for (int k = 0; k < 64; k++) {
            unsigned long long ap[4];
#pragma unroll
            for (int i = 0; i < 2; i++) {
                ulonglong2 t = *(const ulonglong2*)&As1[k*132 + ty*8 + i*4];
                ap[i*2]   = t.x;
                ap[i*2+1] = t.y;
            }
            float4 w0 = *(const float4*)&Ws1[k*128 + tx*8];
            float4 w1 = *(const float4*)&Ws1[k*128 + tx*8 + 4];
            unsigned long long wd[8];
            wd[0] = dup2(w0.x); wd[1] = dup2(w0.y);
            wd[2] = dup2(w0.z); wd[3] = dup2(w0.w);
            wd[4] = dup2(w1.x); wd[5] = dup2(w1.y);
            wd[6] = dup2(w1.z); wd[7] = dup2(w1.w);
#pragma unroll
            for (int i = 0; i < 4; i++)
#pragma unroll
                for (int j = 0; j < 8; j++)
                    fma2(acc2[i][j], ap[i], wd[j]);
        }
#pragma unroll
        for (int i = 0; i < 4; i++) {
            int r0 = ty * 8 + 2 * i;
#pragma unroll
            for (int j = 0; j < 8; j++) {
                float2 f = unpk2(acc2[i][j]);
                float b = b1[tx*8 + j];
                Tt[(tx*8+j)*132 + r0]     = fmaxf(f.x + b, 0.f);
                Tt[(tx*8+j)*132 + r0 + 1] = fmaxf(f.y + b, 0.f);
            }
        }
    }
    __syncthreads();

    {
        unsigned long long acc2[4][8];
#pragma unroll
        for (int i = 0; i < 4; i++)
#pragma unroll
            for (int j = 0; j < 8; j++) acc2[i][j] = 0ull;

#pragma unroll
        for (int k = 0; k < 128; k++) {
            unsigned long long ap[4];
#pragma unroll
            for (int i = 0; i < 2; i++) {
                ulonglong2 t = *(const ulonglong2*)&Tt[k*132 + ty*8 + i*4];
                ap[i*2]   = t.x;
                ap[i*2+1] = t.y;
            }
            float4 w0 = *(const float4*)&Ws2[k*128 + tx*8];
            float4 w1 = *(const float4*)&Ws2[k*128 + tx*8 + 4];
            unsigned long long wd[8];
            wd[0] = dup2(w0.x); wd[1] = dup2(w0.y);
            wd[2] = dup2(w0.z); wd[3] = dup2(w0.w);
            wd[4] = dup2(w1.x); wd[5] = dup2(w1.y);
            wd[6] = dup2(w1.z); wd[7] = dup2(w1.w);
#pragma unroll
            for (int i = 0; i < 4; i++)
#pragma unroll
                for (int j = 0; j < 8; j++)
                    fma2(acc2[i][j], ap[i], wd[j]);
        }

        float bb[8];
#pragma unroll
        for (int j = 0; j < 8; j++) bb[j] = b2[tx*8 + j];
#pragma unroll
        for (int i = 0; i < 4; i++) {
            int r0 = row0 + ty * 8 + 2 * i;
#pragma unroll
            for (int h = 0; h < 2; h++) {
                int r = r0 + h;
                if (r >= M) continue;
                float o[8];
#pragma unroll
                for (int j = 0; j < 8; j++) {
                    float2 f = unpk2(acc2[i][j]);
                    o[j] = (h ? f.y : f.x) + bb[j];
                }
                size_t ob = (size_t)r * 128 + tx * 8;
                *(float4*)&out[ob]     = make_float4(o[0], o[1], o[2], o[3]);
                *(float4*)&out[ob + 4] = make_float4(o[4], o[5], o[6], o[7]);
            }
        }
    }
}

// ---------------- CSR gather F=128 -> bf16 hi/lo output ------------------------
__global__ __launch_bounds__(256) void k_gather128(
    const int* __restrict__ off, const int* __restrict__ cnt,
    const int* __restrict__ srt, const float* __restrict__ xs,
    const float* __restrict__ dis, const float* __restrict__ bias,
    __nv_bfloat16* __restrict__ zhi, __nv_bfloat16* __restrict__ zlo, int n)
{
    int w    = (blockIdx.x * blockDim.x + threadIdx.x) >> 5;
    int lane = threadIdx.x & 31;
    if (w >= n) return;
    int s = off[w];
    int e = s + cnt[w];
    float d = dis[w];

    float4 sv = *(const float4*)&xs[(size_t)w * 128 + lane * 4];
    float4 sum = make_float4(d * sv.x, d * sv.y, d * sv.z, d * sv.w);
    int t = s;
    for (; t + 4 <= e; t += 4) {
        int i0 = __ldg(&srt[t]);
        int i1 = __ldg(&srt[t + 1]);
        int i2 = __ldg(&srt[t + 2]);
        int i3 = __ldg(&srt[t + 3]);
        float d0 = __ldg(&dis[i0]);
        float d1 = __ldg(&dis[i1]);
        float d2 = __ldg(&dis[i2]);
        float d3 = __ldg(&dis[i3]);
        float4 v0 = *(const float4*)&xs[(size_t)i0 * 128 + lane * 4];
        float4 v1 = *(const float4*)&xs[(size_t)i1 * 128 + lane * 4];
        float4 v2 = *(const float4*)&xs[(size_t)i2 * 128 + lane * 4];
        float4 v3 = *(const float4*)&xs[(size_t)i3 * 128 + lane * 4];
        sum.x = fmaf(d3, v3.x, fmaf(d2, v2.x, fmaf(d1, v1.x, fmaf(d0, v0.x, sum.x))));
        sum.y = fmaf(d3, v3.y, fmaf(d2, v2.y, fmaf(d1, v1.y, fmaf(d0, v0.y, sum.y))));
        sum.z = fmaf(d3, v3.z, fmaf(d2, v2.z, fmaf(d1, v1.z, fmaf(d0, v0.z, sum.z))));
        sum.w = fmaf(d3, v3.w, fmaf(d2, v2.w, fmaf(d1, v1.w, fmaf(d0, v0.w, sum.w))));
    }
    for (; t < e; t++) {
        int i0 = __ldg(&srt[t]);
        float d0 = __ldg(&dis[i0]);
        float4 v0 = *(const float4*)&xs[(size_t)i0 * 128 + lane * 4];
        sum.x = fmaf(d0, v0.x, sum.x); sum.y = fmaf(d0, v0.y, sum.y);
        sum.z = fmaf(d0, v0.z, sum.z); sum.w = fmaf(d0, v0.w, sum.w);
    }
    const float4 b = *(const float4*)&bias[lane * 4];
    float o0 = fmaxf(fmaf(d, sum.x, b.x), 0.f);
    float o1 = fmaxf(fmaf(d, sum.y, b.y), 0.f);
    float o2 = fmaxf(fmaf(d, sum.z, b.z), 0.f);
    float o3 = fmaxf(fmaf(d, sum.w, b.w), 0.f);

    __nv_bfloat16 h0 = __float2bfloat16(o0), h1 = __float2bfloat16(o1);
    __nv_bfloat16 h2 = __float2bfloat16(o2), h3 = __float2bfloat16(o3);
    __nv_bfloat16 l0 = __float2bfloat16(o0 - __bfloat162float(h0));
    __nv_bfloat16 l1 = __float2bfloat16(o1 - __bfloat162float(h1));
    __nv_bfloat16 l2 = __float2bfloat16(o2 - __bfloat162float(h2));
    __nv_bfloat16 l3 = __float2bfloat16(o3 - __bfloat162float(h3));
    __nv_bfloat162 p;
    size_t ob = (size_t)w * 128 + lane * 4;
    p.x = h0; p.y = h1; *(__nv_bfloat162*)&zhi[ob]     = p;
    p.x = h2; p.y = h3; *(__nv_bfloat162*)&zhi[ob + 2] = p;
    p.x = l0; p.y = l1; *(__nv_bfloat162*)&zlo[ob]     = p;
    p.x = l2; p.y = l3; *(__nv_bfloat162*)&zlo[ob + 2] = p;
}

// ---------------- CSR gather F=64 (half-warp, fp32 out) ------------------------
__global__ __launch_bounds__(256) void k_gather64(
    const int* __restrict__ off, const int* __restrict__ cnt,
    const int* __restrict__ srt, const float* __restrict__ xs,
    const float* __restrict__ dis, const float* __restrict__ bias,
    float* __restrict__ out, int n)
{
    int hw   = (blockIdx.x * blockDim.x + threadIdx.x) >> 4;
    int lane = threadIdx.x & 15;
    if (hw >= n) return;
    int s = off[hw];
    int e = s + cnt[hw];
    float d = dis[hw];

    float4 sv = *(const float4*)&xs[(size_t)hw * 64 + lane * 4];
    float4 sum = make_float4(d * sv.x, d * sv.y, d * sv.z, d * sv.w);
    int t = s;
    for (; t + 4 <= e; t += 4) {
        int i0 = __ldg(&srt[t]);
        int i1 = __ldg(&srt[t + 1]);
        int i2 = __ldg(&srt[t + 2]);
        int i3 = __ldg(&srt[t + 3]);
        float d0 = __ldg(&dis[i0]);
        float d1 = __ldg(&dis[i1]);
        float d2 = __ldg(&dis[i2]);
        float d3 = __ldg(&dis[i3]);
        float4 v0 = *(const float4*)&xs[(size_t)i0 * 64 + lane * 4];
        float4 v1 = *(const float4*)&xs[(size_t)i1 * 64 + lane * 4];
        float4 v2 = *(const float4*)&xs[(size_t)i2 * 64 + lane * 4];
        float4 v3 = *(const float4*)&xs[(size_t)i3 * 64 + lane * 4];
        sum.x = fmaf(d3, v3.x, fmaf(d2, v2.x, fmaf(d1, v1.x, fmaf(d0, v0.x, sum.x))));
        sum.y = fmaf(d3, v3.y, fmaf(d2, v2.y, fmaf(d1, v1.y, fmaf(d0, v0.y, sum.y))));
        sum.z = fmaf(d3, v3.z, fmaf(d2, v2.z, fmaf(d1, v1.z, fmaf(d0, v0.z, sum.z))));
        sum.w = fmaf(d3, v3.w, fmaf(d2, v2.w, fmaf(d1, v1.w, fmaf(d0, v0.w, sum.w))));
    }
    for (; t < e; t++) {
        int i0 = __ldg(&srt[t]);
        float d0 = __ldg(&dis[i0]);
        float4 v0 = *(const float4*)&xs[(size_t)i0 * 64 + lane * 4];
        sum.x = fmaf(d0, v0.x, sum.x); sum.y = fmaf(d0, v0.y, sum.y);
        sum.z = fmaf(d0, v0.z, sum.z); sum.w = fmaf(d0, v0.w, sum.w);
    }
    const float4 b = *(const float4*)&bias[lane * 4];
    float4 o;
    o.x = fmaxf(fmaf(d, sum.x, b.x), 0.f);
    o.y = fmaxf(fmaf(d, sum.y, b.y), 0.f);
    o.z = fmaxf(fmaf(d, sum.z, b.z), 0.f);
    o.w = fmaxf(fmaf(d, sum.w, b.w), 0.f);
    *(float4*)&out[(size_t)hw * 64 + lane * 4] = o;
}

// ---------------- launch ----------------
extern "C" void kernel_launch(void* const* d_in, const int* in_sizes, int n_in,
                              void* d_out, int out_size)
{
    const float* x      = (const float*)d_in[0];
    const void*  ei     = d_in[1];
    const float* W_enc1 = (const float*)d_in[2];
    const float* b_enc1 = (const float*)d_in[3];
    const float* W_enc2 = (const float*)d_in[4];
    const float* b_enc2 = (const float*)d_in[5];
    const float* W_dec1 = (const float*)d_in[6];
    const float* b_dec1 = (const float*)d_in[7];
    const float* W_dec2 = (const float*)d_in[8];
    const float* b_dec2 = (const float*)d_in[9];
    float*       out    = (float*)d_out;

    const int M = in_sizes[0] / 128;   // 50000
    int E = in_sizes[1] / 2;           // 600000
    if (E > MAX_EDGES) E = MAX_EDGES;

    int *bad, *row, *col, *srt, *cnt, *off, *cur, *stat, *aggr, *pref;
    float *dis, *xs1, *xs2, *z2;
    __nv_bfloat16 *xhi, *xlo, *z1hi, *z1lo, *b1hi, *b1lo, *b2hi, *b2lo;
    cudaGetSymbolAddress((void**)&bad,  g_bad);
    cudaGetSymbolAddress((void**)&row,  g_row);
    cudaGetSymbolAddress((void**)&col,  g_col);
    cudaGetSymbolAddress((void**)&srt,  g_srt);
    cudaGetSymbolAddress((void**)&cnt,  g_cnt);
    cudaGetSymbolAddress((void**)&off,  g_off);
    cudaGetSymbolAddress((void**)&cur,  g_cur);
    cudaGetSymbolAddress((void**)&stat, g_stat);
    cudaGetSymbolAddress((void**)&aggr, g_aggr);
    cudaGetSymbolAddress((void**)&pref, g_pref);
    cudaGetSymbolAddress((void**)&dis,  g_dis);
    cudaGetSymbolAddress((void**)&xs1,  g_xs1);
    cudaGetSymbolAddress((void**)&xs2,  g_xs2);
    cudaGetSymbolAddress((void**)&z2,   g_z2);
    cudaGetSymbolAddress((void**)&xhi,  g_xhi);
    cudaGetSymbolAddress((void**)&xlo,  g_xlo);
    cudaGetSymbolAddress((void**)&z1hi, g_z1hi);
    cudaGetSymbolAddress((void**)&z1lo, g_z1lo);
    cudaGetSymbolAddress((void**)&b1hi, g_b1hi);
    cudaGetSymbolAddress((void**)&b1lo, g_b1lo);
    cudaGetSymbolAddress((void**)&b2hi, g_b2hi);
    cudaGetSymbolAddress((void**)&b2lo, g_b2lo);

    const int TG1 = (2 * 64 * 136 + 2 * 128 * 136) * 2;   // 104448 B
    const int TG2 = (2 * 64 * 136 + 2 * 64 * 136) * 2;    //  69632 B
    static bool attr_set = false;
    if (!attr_set) {
        cudaFuncSetAttribute(k_decoder, cudaFuncAttributeMaxDynamicSharedMemorySize,
                             DEC_SMEM_FLOATS * 4);
        cudaFuncSetAttribute(k_mmagemm<128>, cudaFuncAttributeMaxDynamicSharedMemorySize, TG1);
        cudaFuncSetAttribute(k_mmagemm<64>,  cudaFuncAttributeMaxDynamicSharedMemorySize, TG2);
        attr_set = true;
    }

    const int TB = 256;
    const int EB = (E + TB - 1) / TB;
    const int NB = (M + 255) / 256;
    const int GB64 = (M + 63) / 64;        // mma gemm blocks (BM=64)
    const int GB   = (M + 127) / 128;      // decoder blocks
    const int AGB1 = (M * 32 + TB - 1) / TB;
    const int AGB2 = (M * 16 + TB - 1) / TB;
    const int CVB  = (M * 32 + 128 * 128 + 128 * 64 + TB - 1) / TB;

    // 1: split x / transpose+split W1,W2
    k_cvt    <<<CVB, TB>>>(x, W_enc1, W_enc2, xhi, xlo, b1hi, b1lo, b2hi, b2lo, M);
    // 2: zero cnt/status + dtype sniff
    k_prep   <<<EB, TB>>>((const long long*)ei, E, M, cnt, stat, bad);
    // 3: convert + degree count
    k_convert<<<EB, TB>>>(ei, E, M, bad, row, col, cnt);
    // 4 (PROFILED SLOT): tensor gemm1 -> xs1 (unscaled xw, fp32)
    k_mmagemm<128><<<GB64, 256, TG1>>>(xhi, xlo, b1hi, b1lo, xs1, M);
    // 5: single-pass scan -> off/cur/dis
    k_scan   <<<NB, 256>>>(cnt, M, off, cur, dis, stat, aggr, pref);
    // 6: CSR placement
    k_place  <<<EB, TB>>>(row, col, cur, srt, E);
    // 7: GCN layer 1 aggregation -> z1 hi/lo bf16
    k_gather128<<<AGB1, TB>>>(off, cnt, srt, xs1, dis, b_enc1, z1hi, z1lo, M);
    // 8: tensor gemm2 -> xs2 fp32
    k_mmagemm<64><<<GB64, 256, TG2>>>(z1hi, z1lo, b2hi, b2lo, xs2, M);
    // 9: GCN layer 2 aggregation -> z2 fp32
    k_gather64<<<AGB2, TB>>>(off, cnt, srt, xs2, dis, b_enc2, z2, M);
    // 10: fused decoder
    k_decoder<<<GB, 256, DEC_SMEM_FLOATS * 4>>>(z2, W_dec1, b_dec1, W_dec2, b_dec2, out, M);
}

// round 14
// speedup vs baseline: 1.2622x; 1.1791x over previous
#include <cuda_runtime.h>
#include <cuda_bf16.h>

// Problem constants (reference: N_NODES=50000, F=128, HIDDEN=128, OUT=64, E=600000)
#define MAX_NODES 50000
#define MAX_EDGES 600000
#define SCAN_NB ((MAX_NODES + 255) / 256)   // 196

// ---------------- scratch (device globals; no allocations allowed) -------------
__device__ int   g_bad = 0;
__device__ int   g_row [MAX_EDGES];
__device__ int   g_col [MAX_EDGES];
__device__ int   g_srt [MAX_EDGES];
__device__ int   g_cnt [MAX_NODES];
__device__ int   g_off [MAX_NODES];
__device__ int   g_cur [MAX_NODES];
__device__ int   g_stat[SCAN_NB];
__device__ int   g_aggr[SCAN_NB];
__device__ int   g_pref[SCAN_NB];
__device__ float g_dis [MAX_NODES];
__device__ float g_xs1 [MAX_NODES * 128];
__device__ float g_xs2 [MAX_NODES * 64];
// bf16 split-precision operands / intermediates
__device__ __nv_bfloat16 g_xhi [MAX_NODES * 128];
__device__ __nv_bfloat16 g_xlo [MAX_NODES * 128];
__device__ __nv_bfloat16 g_z1hi[MAX_NODES * 128];
__device__ __nv_bfloat16 g_z1lo[MAX_NODES * 128];
__device__ __nv_bfloat16 g_z2hi[MAX_NODES * 64];
__device__ __nv_bfloat16 g_z2lo[MAX_NODES * 64];
__device__ __nv_bfloat16 g_thi [MAX_NODES * 128];
__device__ __nv_bfloat16 g_tlo [MAX_NODES * 128];
__device__ __nv_bfloat16 g_b1hi[128 * 128];   // W_enc1^T  [n][k=128]
__device__ __nv_bfloat16 g_b1lo[128 * 128];
__device__ __nv_bfloat16 g_b2hi[64 * 128];    // W_enc2^T  [n][k=128]
__device__ __nv_bfloat16 g_b2lo[64 * 128];
__device__ __nv_bfloat16 g_d1hi[128 * 64];    // W_dec1^T  [n=128][k=64]
__device__ __nv_bfloat16 g_d1lo[128 * 64];
__device__ __nv_bfloat16 g_d2hi[128 * 128];   // W_dec2^T  [n=128][k=128]
__device__ __nv_bfloat16 g_d2lo[128 * 128];

// ---------------- helpers ------------------------------------------------------
__device__ __forceinline__ unsigned int smem_u32(const void* p) {
    unsigned int a;
    asm("{ .reg .u64 t; cvta.to.shared.u64 t, %1; cvt.u32.u64 %0, t; }"
        : "=r"(a) : "l"(p));
    return a;
}
__device__ __forceinline__ void mma_bf16(float* c, const unsigned* a,
                                         unsigned b0, unsigned b1) {
    asm volatile(
        "mma.sync.aligned.m16n8k16.row.col.f32.bf16.bf16.f32 "
        "{%0,%1,%2,%3}, {%4,%5,%6,%7}, {%8,%9}, {%0,%1,%2,%3};"
        : "+f"(c[0]), "+f"(c[1]), "+f"(c[2]), "+f"(c[3])
        : "r"(a[0]), "r"(a[1]), "r"(a[2]), "r"(a[3]), "r"(b0), "r"(b1));
}
__device__ __forceinline__ void ldsm4(unsigned* r, unsigned addr) {
    asm volatile("ldmatrix.sync.aligned.m8n8.x4.shared.b16 {%0,%1,%2,%3}, [%4];"
        : "=r"(r[0]), "=r"(r[1]), "=r"(r[2]), "=r"(r[3]) : "r"(addr));
}
__device__ __forceinline__ void split_bf16(float v, __nv_bfloat16& h, __nv_bfloat16& l) {
    h = __float2bfloat16(v);
    l = __float2bfloat16(v - __bfloat162float(h));
}

// ---------------- prep / convert / scan / place --------------------------------
__global__ void k_prep(const long long* __restrict__ ei, int E, int n,
                       int* __restrict__ cnt, int* __restrict__ stat,
                       int* __restrict__ bad) {
    int i = blockIdx.x * blockDim.x + threadIdx.x;
    if (i < n) cnt[i] = 0;
    if (i < SCAN_NB) stat[i] = 0;
    bool oob = false;
    if (i < E) {
        long long v = ei[i];
        oob = (v < 0 || v >= (long long)n);
    }
    unsigned m = __ballot_sync(0xFFFFFFFFu, oob);
    if (oob && (threadIdx.x & 31) == (__ffs(m) - 1)) {
        if (*bad == 0) atomicOr(bad, 1);
    }
}

__global__ void k_convert(const void* __restrict__ ei, int E, int n,
                          const int* __restrict__ bad,
                          int* __restrict__ row, int* __restrict__ col,
                          int* __restrict__ cnt) {
    int i = blockIdx.x * blockDim.x + threadIdx.x;
    if (i >= E) return;
    int r, c;
    if (*bad == 0) {
        r = (int)((const long long*)ei)[i];
        c = (int)((const long long*)ei)[(size_t)E + i];
    } else {
        r = ((const int*)ei)[i];
        c = ((const int*)ei)[(size_t)E + i];
    }
    if ((unsigned)r >= (unsigned)n) r = 0;
    if ((unsigned)c >= (unsigned)n) c = 0;
    row[i] = r;
    col[i] = c;
    atomicAdd(&cnt[c], 1);
}

__global__ __launch_bounds__(256) void k_scan(
    const int* __restrict__ cnt, int n,
    int* __restrict__ off, int* __restrict__ cur, float* __restrict__ dis,
    volatile int* stat, volatile int* aggr, volatile int* pref)
{
    __shared__ int sh[256];
    __shared__ int s_prefix;
    const int b = blockIdx.x;
    const int i = b * 256 + threadIdx.x;
    int v = (i < n) ? cnt[i] : 0;
    sh[threadIdx.x] = v;
    __syncthreads();
#pragma unroll
    for (int d = 1; d < 256; d <<= 1) {
        int t = (threadIdx.x >= d) ? sh[threadIdx.x - d] : 0;
        __syncthreads();
        sh[threadIdx.x] += t;
        __syncthreads();
    }
    int incl = sh[threadIdx.x];
    int total = sh[255];

    if (threadIdx.x == 0) {
        if (b == 0) {
            pref[0] = total;
            __threadfence();
            ((int*)stat)[0] = 2;
            s_prefix = 0;
        } else {
            aggr[b] = total;
            __threadfence();
            ((int*)stat)[b] = 1;
            int run = 0;
            int p = b - 1;
            while (true) {
                int st;
                do { st = stat[p]; } while (st == 0);
                __threadfence();
                if (st == 2) { run += pref[p]; break; }
                run += aggr[p];
                p--;
            }
            pref[b] = run + total;
            __threadfence();
            ((int*)stat)[b] = 2;
            s_prefix = run;
        }
    }
    __syncthreads();
    int prefix = s_prefix;
    if (i < n) {
        int o = prefix + incl - v;
        off[i] = o;
        cur[i] = o;
        dis[i] = rsqrtf((float)(v + 1));
    }
}

__global__ void k_place(const int* __restrict__ row, const int* __restrict__ col,
                        int* __restrict__ cur, int* __restrict__ srt, int E) {
    int e = blockIdx.x * blockDim.x + threadIdx.x;
    if (e >= E) return;
    int pos = atomicAdd(&cur[col[e]], 1);
    srt[pos] = row[e];
}

// ---------------- cvt: split x; transpose+split all 4 weight matrices ----------
__global__ void k_cvt(const float* __restrict__ x,
                      const float* __restrict__ W1, const float* __restrict__ W2,
                      const float* __restrict__ Wd1, const float* __restrict__ Wd2,
                      __nv_bfloat16* __restrict__ xhi, __nv_bfloat16* __restrict__ xlo,
                      __nv_bfloat16* __restrict__ b1hi, __nv_bfloat16* __restrict__ b1lo,
                      __nv_bfloat16* __restrict__ b2hi, __nv_bfloat16* __restrict__ b2lo,
                      __nv_bfloat16* __restrict__ d1hi, __nv_bfloat16* __restrict__ d1lo,
                      __nv_bfloat16* __restrict__ d2hi, __nv_bfloat16* __restrict__ d2lo,
                      int M)
{
    const int NX4 = M * 32;           // float4 count of x
    int gid = blockIdx.x * blockDim.x + threadIdx.x;
    if (gid < NX4) {
        float4 v = ((const float4*)x)[gid];
        __nv_bfloat16 h0, h1, h2, h3, l0, l1, l2, l3;
        split_bf16(v.x, h0, l0); split_bf16(v.y, h1, l1);
        split_bf16(v.z, h2, l2); split_bf16(v.w, h3, l3);
        __nv_bfloat162 a, b;
        a.x = h0; a.y = h1; b.x = h2; b.y = h3;
        *(__nv_bfloat162*)&xhi[(size_t)gid * 4]     = a;
        *(__nv_bfloat162*)&xhi[(size_t)gid * 4 + 2] = b;
        a.x = l0; a.y = l1; b.x = l2; b.y = l3;
        *(__nv_bfloat162*)&xlo[(size_t)gid * 4]     = a;
        *(__nv_bfloat162*)&xlo[(size_t)gid * 4 + 2] = b;
        return;
    }
    int e = gid - NX4;
    if (e < 128 * 128) {                      // W_enc1 [k=128][n=128]
        int k = e >> 7, n = e & 127;
        __nv_bfloat16 h, l; split_bf16(W1[e], h, l);
        b1hi[n * 128 + k] = h; b1lo[n * 128 + k] = l;
        return;
    }
    e -= 128 * 128;
    if (e < 128 * 64) {                       // W_enc2 [k=128][n=64]
        int k = e >> 6, n = e & 63;
        __nv_bfloat16 h, l; split_bf16(W2[e], h, l);
        b2hi[n * 128 + k] = h; b2lo[n * 128 + k] = l;
        return;
    }
    e -= 128 * 64;
    if (e < 64 * 128) {                       // W_dec1 [k=64][n=128]
        int k = e >> 7, n = e & 127;
        __nv_bfloat16 h, l; split_bf16(Wd1[e], h, l);
        d1hi[n * 64 + k] = h; d1lo[n * 64 + k] = l;
        return;
    }
    e -= 64 * 128;
    if (e < 128 * 128) {                      // W_dec2 [k=128][n=128]
        int k = e >> 7, n = e & 127;
        __nv_bfloat16 h, l; split_bf16(Wd2[e], h, l);
        d2hi[n * 128 + k] = h; d2lo[n * 128 + k] = l;
    }
}

// ---------------- unified split-bf16 mma GEMM ----------------------------------
// out[M,N] = (Ahi+Alo)[M,K] @ (Bhi+Blo)[N,K]^T  (3 passes: AhBh + AhBl + AlBh)
// Block: 64 x N, 8 warps (4 m-tiles of 16 x 2 n-halves). ldmatrix fragment loads.
// MODE 0: raw fp32 -> outf.  MODE 1: +bias, relu -> bf16 hi/lo (ohi/olo).
// MODE 2: +bias -> fp32 outf.
template<int K, int N, int MODE>
__global__ __launch_bounds__(256, 2) void k_mmagemm(
    const __nv_bfloat16* __restrict__ Ahi, const __nv_bfloat16* __restrict__ Alo,
    const __nv_bfloat16* __restrict__ Bhi, const __nv_bfloat16* __restrict__ Blo,
    const float* __restrict__ bias, float* __restrict__ outf,
    __nv_bfloat16* __restrict__ ohi, __nv_bfloat16* __restrict__ olo, int M)
{
    constexpr int P   = K + 8;          // smem row pitch (bf16)
    constexpr int NT  = N / 16;         // n8-tile pairs handled per warp = NT (tiles), pairs = NT/2
    constexpr int KS  = K / 16;         // k-steps
    constexpr int CPR = K / 8;          // 16B chunks per row
    extern __shared__ __nv_bfloat16 smb[];
    __nv_bfloat16* Ah_s = smb;                     // [64][P]
    __nv_bfloat16* Al_s = smb + 64 * P;
    __nv_bfloat16* Bh_s = smb + 2 * 64 * P;        // [N][P]
    __nv_bfloat16* Bl_s = smb + 2 * 64 * P + N * P;

    const int tid  = threadIdx.x;
    const int warp = tid >> 5;
    const int lane = tid & 31;
    const int gid  = lane >> 2;       // 0..7
    const int tig  = lane & 3;        // 0..3
    const int mbase = (warp >> 1) * 16;
    const int nbase = (warp & 1) * (N / 2);
    const int row0 = blockIdx.x * 64;

    // ---- load A tiles (zero-fill beyond M) ----
    for (int i = tid; i < 64 * CPR; i += 256) {
        int r = i / CPR, c = i % CPR;
        int gr = row0 + r;
        uint4 vh = make_uint4(0,0,0,0), vl = make_uint4(0,0,0,0);
        if (gr < M) {
            vh = *(const uint4*)&Ahi[(size_t)gr * K + c * 8];
            vl = *(const uint4*)&Alo[(size_t)gr * K + c * 8];
        }
        *(uint4*)&Ah_s[r * P + c * 8] = vh;
        *(uint4*)&Al_s[r * P + c * 8] = vl;
    }
    // ---- load B tiles ----
    for (int i = tid; i < N * CPR; i += 256) {
        int r = i / CPR, c = i % CPR;
        *(uint4*)&Bh_s[r * P + c * 8] = *(const uint4*)&Bhi[(size_t)r * K + c * 8];
        *(uint4*)&Bl_s[r * P + c * 8] = *(const uint4*)&Blo[(size_t)r * K + c * 8];
    }
    __syncthreads();

    // ---- lane-dependent ldmatrix byte offsets ----
    const unsigned sbase = smem_u32(smb);
    // A: lanes 0-15 -> rows mbase+(lane&15), k+0 ; lanes 16-31 -> same rows, k+8
    const unsigned offA = ((mbase + (lane & 15)) * P + ((lane & 16) ? 8 : 0)) * 2;
    // B: per n-tile pair p: lanes {0-7:(n+l,k0)}, {8-15:(n+l,k8)}, {16-23:(n+8+l,k0)}, {24-31:(n+8+l,k8)}
    unsigned offB[NT / 2];
#pragma unroll
    for (int p = 0; p < NT / 2; p++)
        offB[p] = ((nbase + p * 16 + ((lane & 16) ? 8 : 0) + (lane & 7)) * P
                   + ((lane & 8) ? 8 : 0)) * 2;

    const unsigned aHi = sbase;
    const unsigned aLo = sbase + 64 * P * 2;
    const unsigned bHi = sbase + 4 * 64 * P;       // = 2*64*P*2 bytes
    const unsigned bLo = bHi + N * P * 2;

    float acc[NT][4];
#pragma unroll
    for (int nj = 0; nj < NT; nj++)
#pragma unroll
        for (int q = 0; q < 4; q++) acc[nj][q] = 0.f;

#pragma unroll
    for (int pass = 0; pass < 3; pass++) {
        const unsigned aB = ((pass == 2) ? aLo : aHi) + offA;
        const unsigned bB = (pass == 1) ? bLo : bHi;
#pragma unroll
        for (int ks = 0; ks < KS; ks++) {
            unsigned a[4];
            ldsm4(a, aB + ks * 32);
#pragma unroll
            for (int p = 0; p < NT / 2; p++) {
                unsigned b[4];
                ldsm4(b, bB + offB[p] + ks * 32);
                mma_bf16(acc[2 * p],     a, b[0], b[1]);
                mma_bf16(acc[2 * p + 1], a, b[2], b[3]);
            }
        }
    }

    // ---- epilogue: acc[nj] = {r,c0},{r,c1},{r+8,c0},{r+8,c1} ----
    const int r = row0 + mbase + gid;
#pragma unroll
    for (int nj = 0; nj < NT; nj++) {
        const int c = nbase + nj * 8 + tig * 2;
        if (MODE == 0) {
            if (r < M)
                *(float2*)&outf[(size_t)r * N + c] = make_float2(acc[nj][0], acc[nj][1]);
            if (r + 8 < M)
                *(float2*)&outf[(size_t)(r + 8) * N + c] = make_float2(acc[nj][2], acc[nj][3]);
        } else {
            const float b0 = bias[c], b1 = bias[c + 1];
            if (MODE == 1) {
#pragma unroll
                for (int h = 0; h < 2; h++) {
                    int rr = r + h * 8;
                    if (rr >= M) continue;
                    float o0 = fmaxf(acc[nj][2 * h]     + b0, 0.f);
                    float o1 = fmaxf(acc[nj][2 * h + 1] + b1, 0.f);
                    __nv_bfloat16 h0, h1, l0, l1;
                    split_bf16(o0, h0, l0);
                    split_bf16(o1, h1, l1);
                    __nv_bfloat162 ph; ph.x = h0; ph.y = h1;
                    __nv_bfloat162 pl; pl.x = l0; pl.y = l1;
                    *(__nv_bfloat162*)&ohi[(size_t)rr * N + c] = ph;
                    *(__nv_bfloat162*)&olo[(size_t)rr * N + c] = pl;
                }
            } else {  // MODE 2
                if (r < M)
                    *(float2*)&outf[(size_t)r * N + c] =
                        make_float2(acc[nj][0] + b0, acc[nj][1] + b1);
                if (r + 8 < M)
                    *(float2*)&outf[(size_t)(r + 8) * N + c] =
                        make_float2(acc[nj][2] + b0, acc[nj][3] + b1);
            }
        }
    }
}

// ---------------- CSR gather F=128 -> bf16 hi/lo output ------------------------
__global__ __launch_bounds__(256) void k_gather128(
    const int* __restrict__ off, const int* __restrict__ cnt,
    const int* __restrict__ srt, const float* __restrict__ xs,
    const float* __restrict__ dis, const float* __restrict__ bias,
    __nv_bfloat16* __restrict__ zhi, __nv_bfloat16* __restrict__ zlo, int n)
{
    int w    = (blockIdx.x * blockDim.x + threadIdx.x) >> 5;
    int lane = threadIdx.x & 31;
    if (w >= n) return;
    int s = off[w];
    int e = s + cnt[w];
    float d = dis[w];

    float4 sv = *(const float4*)&xs[(size_t)w * 128 + lane * 4];
    float4 sum = make_float4(d * sv.x, d * sv.y, d * sv.z, d * sv.w);
    int t = s;
    for (; t + 4 <= e; t += 4) {
        int i0 = __ldg(&srt[t]);
        int i1 = __ldg(&srt[t + 1]);
        int i2 = __ldg(&srt[t + 2]);
        int i3 = __ldg(&srt[t + 3]);
        float d0 = __ldg(&dis[i0]);
        float d1 = __ldg(&dis[i1]);
        float d2 = __ldg(&dis[i2]);
        float d3 = __ldg(&dis[i3]);
        float4 v0 = *(const float4*)&xs[(size_t)i0 * 128 + lane * 4];
        float4 v1 = *(const float4*)&xs[(size_t)i1 * 128 + lane * 4];
        float4 v2 = *(const float4*)&xs[(size_t)i2 * 128 + lane * 4];
        float4 v3 = *(const float4*)&xs[(size_t)i3 * 128 + lane * 4];
        sum.x = fmaf(d3, v3.x, fmaf(d2, v2.x, fmaf(d1, v1.x, fmaf(d0, v0.x, sum.x))));
        sum.y = fmaf(d3, v3.y, fmaf(d2, v2.y, fmaf(d1, v1.y, fmaf(d0, v0.y, sum.y))));
        sum.z = fmaf(d3, v3.z, fmaf(d2, v2.z, fmaf(d1, v1.z, fmaf(d0, v0.z, sum.z))));
        sum.w = fmaf(d3, v3.w, fmaf(d2, v2.w, fmaf(d1, v1.w, fmaf(d0, v0.w, sum.w))));
    }
    for (; t < e; t++) {
        int i0 = __ldg(&srt[t]);
        float d0 = __ldg(&dis[i0]);
        float4 v0 = *(const float4*)&xs[(size_t)i0 * 128 + lane * 4];
        sum.x = fmaf(d0, v0.x, sum.x); sum.y = fmaf(d0, v0.y, sum.y);
        sum.z = fmaf(d0, v0.z, sum.z); sum.w = fmaf(d0, v0.w, sum.w);
    }
    const float4 b = *(const float4*)&bias[lane * 4];
    float o0 = fmaxf(fmaf(d, sum.x, b.x), 0.f);
    float o1 = fmaxf(fmaf(d, sum.y, b.y), 0.f);
    float o2 = fmaxf(fmaf(d, sum.z, b.z), 0.f);
    float o3 = fmaxf(fmaf(d, sum.w, b.w), 0.f);

    __nv_bfloat16 h0, h1, h2, h3, l0, l1, l2, l3;
    split_bf16(o0, h0, l0); split_bf16(o1, h1, l1);
    split_bf16(o2, h2, l2); split_bf16(o3, h3, l3);
    __nv_bfloat162 p;
    size_t ob = (size_t)w * 128 + lane * 4;
    p.x = h0; p.y = h1; *(__nv_bfloat162*)&zhi[ob]     = p;
    p.x = h2; p.y = h3; *(__nv_bfloat162*)&zhi[ob + 2] = p;
    p.x = l0; p.y = l1; *(__nv_bfloat162*)&zlo[ob]     = p;
    p.x = l2; p.y = l3; *(__nv_bfloat162*)&zlo[ob + 2] = p;
}

// ---------------- CSR gather F=64 (half-warp) -> bf16 hi/lo --------------------
__global__ __launch_bounds__(256) void k_gather64(
    const int* __restrict__ off, const int* __restrict__ cnt,
    const int* __restrict__ srt, const float* __restrict__ xs,
    const float* __restrict__ dis, const float* __restrict__ bias,
    __nv_bfloat16* __restrict__ zhi, __nv_bfloat16* __restrict__ zlo, int n)
{
    int hw   = (blockIdx.x * blockDim.x + threadIdx.x) >> 4;
    int lane = threadIdx.x & 15;
    if (hw >= n) return;
    int s = off[hw];
    int e = s + cnt[hw];
    float d = dis[hw];

    float4 sv = *(const float4*)&xs[(size_t)hw * 64 + lane * 4];
    float4 sum = make_float4(d * sv.x, d * sv.y, d * sv.z, d * sv.w);
    int t = s;
    for (; t + 4 <= e; t += 4) {
        int i0 = __ldg(&srt[t]);
        int i1 = __ldg(&srt[t + 1]);
        int i2 = __ldg(&srt[t + 2]);
        int i3 = __ldg(&srt[t + 3]);
        float d0 = __ldg(&dis[i0]);
        float d1 = __ldg(&dis[i1]);
        float d2 = __ldg(&dis[i2]);
        float d3 = __ldg(&dis[i3]);
        float4 v0 = *(const float4*)&xs[(size_t)i0 * 64 + lane * 4];
        float4 v1 = *(const float4*)&xs[(size_t)i1 * 64 + lane * 4];
        float4 v2 = *(const float4*)&xs[(size_t)i2 * 64 + lane * 4];
        float4 v3 = *(const float4*)&xs[(size_t)i3 * 64 + lane * 4];
        sum.x = fmaf(d3, v3.x, fmaf(d2, v2.x, fmaf(d1, v1.x, fmaf(d0, v0.x, sum.x))));
        sum.y = fmaf(d3, v3.y, fmaf(d2, v2.y, fmaf(d1, v1.y, fmaf(d0, v0.y, sum.y))));
        sum.z = fmaf(d3, v3.z, fmaf(d2, v2.z, fmaf(d1, v1.z, fmaf(d0, v0.z, sum.z))));
        sum.w = fmaf(d3, v3.w, fmaf(d2, v2.w, fmaf(d1, v1.w, fmaf(d0, v0.w, sum.w))));
    }
    for (; t < e; t++) {
        int i0 = __ldg(&srt[t]);
        float d0 = __ldg(&dis[i0]);
        float4 v0 = *(const float4*)&xs[(size_t)i0 * 64 + lane * 4];
        sum.x = fmaf(d0, v0.x, sum.x); sum.y = fmaf(d0, v0.y, sum.y);
        sum.z = fmaf(d0, v0.z, sum.z); sum.w = fmaf(d0, v0.w, sum.w);
    }
    const float4 b = *(const float4*)&bias[lane * 4];
    float o0 = fmaxf(fmaf(d, sum.x, b.x), 0.f);
    float o1 = fmaxf(fmaf(d, sum.y, b.y), 0.f);
    float o2 = fmaxf(fmaf(d, sum.z, b.z), 0.f);
    float o3 = fmaxf(fmaf(d, sum.w, b.w), 0.f);

    __nv_bfloat16 h0, h1, h2, h3, l0, l1, l2, l3;
    split_bf16(o0, h0, l0); split_bf16(o1, h1, l1);
    split_bf16(o2, h2, l2); split_bf16(o3, h3, l3);
    __nv_bfloat162 p;
    size_t ob = (size_t)hw * 64 + lane * 4;
    p.x = h0; p.y = h1; *(__nv_bfloat162*)&zhi[ob]     = p;
    p.x = h2; p.y = h3; *(__nv_bfloat162*)&zhi[ob + 2] = p;
    p.x = l0; p.y = l1; *(__nv_bfloat162*)&zlo[ob]     = p;
    p.x = l2; p.y = l3; *(__nv_bfloat162*)&zlo[ob + 2] = p;
}

// ---------------- launch ----------------
extern "C" void kernel_launch(void* const* d_in, const int* in_sizes, int n_in,
                              void* d_out, int out_size)
{
    const float* x      = (const float*)d_in[0];
    const void*  ei     = d_in[1];
    const float* W_enc1 = (const float*)d_in[2];
    const float* b_enc1 = (const float*)d_in[3];
    const float* W_enc2 = (const float*)d_in[4];
    const float* b_enc2 = (const float*)d_in[5];
    const float* W_dec1 = (const float*)d_in[6];
    const float* b_dec1 = (const float*)d_in[7];
    const float* W_dec2 = (const float*)d_in[8];
    const float* b_dec2 = (const float*)d_in[9];
    float*       out    = (float*)d_out;

    const int M = in_sizes[0] / 128;   // 50000
    int E = in_sizes[1] / 2;           // 600000
    if (E > MAX_EDGES) E = MAX_EDGES;

    int *bad, *row, *col, *srt, *cnt, *off, *cur, *stat, *aggr, *pref;
    float *dis, *xs1, *xs2;
    __nv_bfloat16 *xhi, *xlo, *z1hi, *z1lo, *z2hi, *z2lo, *thi, *tlo;
    __nv_bfloat16 *b1hi, *b1lo, *b2hi, *b2lo, *d1hi, *d1lo, *d2hi, *d2lo;
    cudaGetSymbolAddress((void**)&bad,  g_bad);
    cudaGetSymbolAddress((void**)&row,  g_row);
    cudaGetSymbolAddress((void**)&col,  g_col);
    cudaGetSymbolAddress((void**)&srt,  g_srt);
    cudaGetSymbolAddress((void**)&cnt,  g_cnt);
    cudaGetSymbolAddress((void**)&off,  g_off);
    cudaGetSymbolAddress((void**)&cur,  g_cur);
    cudaGetSymbolAddress((void**)&stat, g_stat);
    cudaGetSymbolAddress((void**)&aggr, g_aggr);
    cudaGetSymbolAddress((void**)&pref, g_pref);
    cudaGetSymbolAddress((void**)&dis,  g_dis);
    cudaGetSymbolAddress((void**)&xs1,  g_xs1);
    cudaGetSymbolAddress((void**)&xs2,  g_xs2);
    cudaGetSymbolAddress((void**)&xhi,  g_xhi);
    cudaGetSymbolAddress((void**)&xlo,  g_xlo);
    cudaGetSymbolAddress((void**)&z1hi, g_z1hi);
    cudaGetSymbolAddress((void**)&z1lo, g_z1lo);
    cudaGetSymbolAddress((void**)&z2hi, g_z2hi);
    cudaGetSymbolAddress((void**)&z2lo, g_z2lo);
    cudaGetSymbolAddress((void**)&thi,  g_thi);
    cudaGetSymbolAddress((void**)&tlo,  g_tlo);
    cudaGetSymbolAddress((void**)&b1hi, g_b1hi);
    cudaGetSymbolAddress((void**)&b1lo, g_b1lo);
    cudaGetSymbolAddress((void**)&b2hi, g_b2hi);
    cudaGetSymbolAddress((void**)&b2lo, g_b2lo);
    cudaGetSymbolAddress((void**)&d1hi, g_d1hi);
    cudaGetSymbolAddress((void**)&d1lo, g_d1lo);
    cudaGetSymbolAddress((void**)&d2hi, g_d2hi);
    cudaGetSymbolAddress((void**)&d2lo, g_d2lo);

    // smem sizes (bytes): 2*(64 + N) * (K+8) * 2
    const int SM_128_128 = 2 * (64 + 128) * 136 * 2;  // 104448
    const int SM_128_64  = 2 * (64 + 64)  * 136 * 2;  //  69632
    const int SM_64_128  = 2 * (64 + 128) * 72  * 2;  //  55296
    static bool attr_set = false;
    if (!attr_set) {
        cudaFuncSetAttribute(k_mmagemm<128,128,0>, cudaFuncAttributeMaxDynamicSharedMemorySize, SM_128_128);
        cudaFuncSetAttribute(k_mmagemm<128,64,0>,  cudaFuncAttributeMaxDynamicSharedMemorySize, SM_128_64);
        cudaFuncSetAttribute(k_mmagemm<64,128,1>,  cudaFuncAttributeMaxDynamicSharedMemorySize, SM_64_128);
        cudaFuncSetAttribute(k_mmagemm<128,128,2>, cudaFuncAttributeMaxDynamicSharedMemorySize, SM_128_128);
        attr_set = true;
    }

    const int TB = 256;
    const int EB = (E + TB - 1) / TB;
    const int NB = (M + 255) / 256;
    const int GB64 = (M + 63) / 64;
    const int AGB1 = (M * 32 + TB - 1) / TB;
    const int AGB2 = (M * 16 + TB - 1) / TB;
    const int CVT_ELEMS = 128 * 128 + 128 * 64 + 64 * 128 + 128 * 128;
    const int CVB  = (M * 32 + CVT_ELEMS + TB - 1) / TB;

    // 1: split x / transpose+split all weights
    k_cvt    <<<CVB, TB>>>(x, W_enc1, W_enc2, W_dec1, W_dec2,
                           xhi, xlo, b1hi, b1lo, b2hi, b2lo,
                           d1hi, d1lo, d2hi, d2lo, M);
    // 2: zero cnt/status + dtype sniff
    k_prep   <<<EB, TB>>>((const long long*)ei, E, M, cnt, stat, bad);
    // 3: convert + degree count
    k_convert<<<EB, TB>>>(ei, E, M, bad, row, col, cnt);
    // 4 (PROFILED SLOT): gemm1 -> xs1 fp32 (unscaled xw)
    k_mmagemm<128,128,0><<<GB64, 256, SM_128_128>>>(xhi, xlo, b1hi, b1lo,
                                                    nullptr, xs1, nullptr, nullptr, M);
    // 5: single-pass scan -> off/cur/dis
    k_scan   <<<NB, 256>>>(cnt, M, off, cur, dis, stat, aggr, pref);
    // 6: CSR placement
    k_place  <<<EB, TB>>>(row, col, cur, srt, E);
    // 7: layer-1 aggregation -> z1 hi/lo
    k_gather128<<<AGB1, TB>>>(off, cnt, srt, xs1, dis, b_enc1, z1hi, z1lo, M);
    // 8: gemm2 -> xs2 fp32
    k_mmagemm<128,64,0><<<GB64, 256, SM_128_64>>>(z1hi, z1lo, b2hi, b2lo,
                                                  nullptr, xs2, nullptr, nullptr, M);
    // 9: layer-2 aggregation -> z2 hi/lo
    k_gather64<<<AGB2, TB>>>(off, cnt, srt, xs2, dis, b_enc2, z2hi, z2lo, M);
    // 10: decoder stage 1: T = relu(z2 @ Wd1 + b1) -> bf16 hi/lo
    k_mmagemm<64,128,1><<<GB64, 256, SM_64_128>>>(z2hi, z2lo, d1hi, d1lo,
                                                  b_dec1, nullptr, thi, tlo, M);
    // 11: decoder stage 2: out = T @ Wd2 + b2 -> fp32
    k_mmagemm<128,128,2><<<GB64, 256, SM_128_128>>>(thi, tlo, d2hi, d2lo,
                                                    b_dec2, out, nullptr, nullptr, M);
}

// round 15
// speedup vs baseline: 1.3288x; 1.0527x over previous
#include <cuda_runtime.h>
#include <cuda_bf16.h>

// Problem constants (reference: N_NODES=50000, F=128, HIDDEN=128, OUT=64, E=600000)
#define MAX_NODES 50000
#define MAX_EDGES 600000
#define SCAN_NB ((MAX_NODES + 255) / 256)   // 196

// ---------------- scratch (device globals; no allocations allowed) -------------
__device__ int   g_bad = 0;
__device__ int   g_row [MAX_EDGES];
__device__ int   g_col [MAX_EDGES];
__device__ int   g_srt [MAX_EDGES];
__device__ int   g_cnt [MAX_NODES];
__device__ int   g_off [MAX_NODES];
__device__ int   g_cur [MAX_NODES];
__device__ int   g_stat[SCAN_NB];
__device__ int   g_aggr[SCAN_NB];
__device__ int   g_pref[SCAN_NB];
__device__ float g_dis [MAX_NODES];
__device__ float g_xs1 [MAX_NODES * 128];
__device__ float g_xs2 [MAX_NODES * 64];
// bf16 split-precision operands / intermediates
__device__ __nv_bfloat16 g_xhi [MAX_NODES * 128];
__device__ __nv_bfloat16 g_xlo [MAX_NODES * 128];
__device__ __nv_bfloat16 g_z1hi[MAX_NODES * 128];
__device__ __nv_bfloat16 g_z1lo[MAX_NODES * 128];
__device__ __nv_bfloat16 g_z2hi[MAX_NODES * 64];
__device__ __nv_bfloat16 g_z2lo[MAX_NODES * 64];
__device__ __nv_bfloat16 g_b1hi[128 * 128];   // W_enc1^T  [n][k=128]
__device__ __nv_bfloat16 g_b1lo[128 * 128];
__device__ __nv_bfloat16 g_b2hi[64 * 128];    // W_enc2^T  [n][k=128]
__device__ __nv_bfloat16 g_b2lo[64 * 128];
__device__ __nv_bfloat16 g_d1hi[128 * 64];    // W_dec1^T  [n=128][k=64]
__device__ __nv_bfloat16 g_d1lo[128 * 64];
__device__ __nv_bfloat16 g_d2hi[128 * 128];   // W_dec2^T  [n=128][k=128]
__device__ __nv_bfloat16 g_d2lo[128 * 128];

// ---------------- helpers ------------------------------------------------------
__device__ __forceinline__ unsigned int smem_u32(const void* p) {
    unsigned int a;
    asm("{ .reg .u64 t; cvta.to.shared.u64 t, %1; cvt.u32.u64 %0, t; }"
        : "=r"(a) : "l"(p));
    return a;
}
__device__ __forceinline__ void mma_bf16(float* c, const unsigned* a,
                                         unsigned b0, unsigned b1) {
    asm volatile(
        "mma.sync.aligned.m16n8k16.row.col.f32.bf16.bf16.f32 "
        "{%0,%1,%2,%3}, {%4,%5,%6,%7}, {%8,%9}, {%0,%1,%2,%3};"
        : "+f"(c[0]), "+f"(c[1]), "+f"(c[2]), "+f"(c[3])
        : "r"(a[0]), "r"(a[1]), "r"(a[2]), "r"(a[3]), "r"(b0), "r"(b1));
}
__device__ __forceinline__ void ldsm4(unsigned* r, unsigned addr) {
    asm volatile("ldmatrix.sync.aligned.m8n8.x4.shared.b16 {%0,%1,%2,%3}, [%4];"
        : "=r"(r[0]), "=r"(r[1]), "=r"(r[2]), "=r"(r[3]) : "r"(addr));
}
__device__ __forceinline__ void split_bf16(float v, __nv_bfloat16& h, __nv_bfloat16& l) {
    h = __float2bfloat16(v);
    l = __float2bfloat16(v - __bfloat162float(h));
}

// ---------------- prep / convert / scan / place --------------------------------
__global__ void k_prep(const long long* __restrict__ ei, int E, int n,
                       int* __restrict__ cnt, int* __restrict__ stat,
                       int* __restrict__ bad) {
    int i = blockIdx.x * blockDim.x + threadIdx.x;
    if (i < n) cnt[i] = 0;
    if (i < SCAN_NB) stat[i] = 0;
    bool oob = false;
    if (i < E) {
        long long v = ei[i];
        oob = (v < 0 || v >= (long long)n);
    }
    unsigned m = __ballot_sync(0xFFFFFFFFu, oob);
    if (oob && (threadIdx.x & 31) == (__ffs(m) - 1)) {
        if (*bad == 0) atomicOr(bad, 1);
    }
}

__global__ void k_convert(const void* __restrict__ ei, int E, int n,
                          const int* __restrict__ bad,
                          int* __restrict__ row, int* __restrict__ col,
                          int* __restrict__ cnt) {
    int i = blockIdx.x * blockDim.x + threadIdx.x;
    if (i >= E) return;
    int r, c;
    if (*bad == 0) {
        r = (int)((const long long*)ei)[i];
        c = (int)((const long long*)ei)[(size_t)E + i];
    } else {
        r = ((const int*)ei)[i];
        c = ((const int*)ei)[(size_t)E + i];
    }
    if ((unsigned)r >= (unsigned)n) r = 0;
    if ((unsigned)c >= (unsigned)n) c = 0;
    row[i] = r;
    col[i] = c;
    atomicAdd(&cnt[c], 1);
}

__global__ __launch_bounds__(256) void k_scan(
    const int* __restrict__ cnt, int n,
    int* __restrict__ off, int* __restrict__ cur, float* __restrict__ dis,
    volatile int* stat, volatile int* aggr, volatile int* pref)
{
    __shared__ int sh[256];
    __shared__ int s_prefix;
    const int b = blockIdx.x;
    const int i = b * 256 + threadIdx.x;
    int v = (i < n) ? cnt[i] : 0;
    sh[threadIdx.x] = v;
    __syncthreads();
#pragma unroll
    for (int d = 1; d < 256; d <<= 1) {
        int t = (threadIdx.x >= d) ? sh[threadIdx.x - d] : 0;
        __syncthreads();
        sh[threadIdx.x] += t;
        __syncthreads();
    }
    int incl = sh[threadIdx.x];
    int total = sh[255];

    if (threadIdx.x == 0) {
        if (b == 0) {
            pref[0] = total;
            __threadfence();
            ((int*)stat)[0] = 2;
            s_prefix = 0;
        } else {
            aggr[b] = total;
            __threadfence();
            ((int*)stat)[b] = 1;
            int run = 0;
            int p = b - 1;
            while (true) {
                int st;
                do { st = stat[p]; } while (st == 0);
                __threadfence();
                if (st == 2) { run += pref[p]; break; }
                run += aggr[p];
                p--;
            }
            pref[b] = run + total;
            __threadfence();
            ((int*)stat)[b] = 2;
            s_prefix = run;
        }
    }
    __syncthreads();
    int prefix = s_prefix;
    if (i < n) {
        int o = prefix + incl - v;
        off[i] = o;
        cur[i] = o;
        dis[i] = rsqrtf((float)(v + 1));
    }
}

__global__ void k_place(const int* __restrict__ row, const int* __restrict__ col,
                        int* __restrict__ cur, int* __restrict__ srt, int E) {
    int e = blockIdx.x * blockDim.x + threadIdx.x;
    if (e >= E) return;
    int pos = atomicAdd(&cur[col[e]], 1);
    srt[pos] = row[e];
}

// ---------------- cvt: split x; transpose+split all 4 weight matrices ----------
__global__ void k_cvt(const float* __restrict__ x,
                      const float* __restrict__ W1, const float* __restrict__ W2,
                      const float* __restrict__ Wd1, const float* __restrict__ Wd2,
                      __nv_bfloat16* __restrict__ xhi, __nv_bfloat16* __restrict__ xlo,
                      __nv_bfloat16* __restrict__ b1hi, __nv_bfloat16* __restrict__ b1lo,
                      __nv_bfloat16* __restrict__ b2hi, __nv_bfloat16* __restrict__ b2lo,
                      __nv_bfloat16* __restrict__ d1hi, __nv_bfloat16* __restrict__ d1lo,
                      __nv_bfloat16* __restrict__ d2hi, __nv_bfloat16* __restrict__ d2lo,
                      int M)
{
    const int NX4 = M * 32;           // float4 count of x
    int gid = blockIdx.x * blockDim.x + threadIdx.x;
    if (gid < NX4) {
        float4 v = ((const float4*)x)[gid];
        __nv_bfloat16 h0, h1, h2, h3, l0, l1, l2, l3;
        split_bf16(v.x, h0, l0); split_bf16(v.y, h1, l1);
        split_bf16(v.z, h2, l2); split_bf16(v.w, h3, l3);
        __nv_bfloat162 a, b;
        a.x = h0; a.y = h1; b.x = h2; b.y = h3;
        *(__nv_bfloat162*)&xhi[(size_t)gid * 4]     = a;
        *(__nv_bfloat162*)&xhi[(size_t)gid * 4 + 2] = b;
        a.x = l0; a.y = l1; b.x = l2; b.y = l3;
        *(__nv_bfloat162*)&xlo[(size_t)gid * 4]     = a;
        *(__nv_bfloat162*)&xlo[(size_t)gid * 4 + 2] = b;
        return;
    }
    int e = gid - NX4;
    if (e < 128 * 128) {                      // W_enc1 [k=128][n=128]
        int k = e >> 7, n = e & 127;
        __nv_bfloat16 h, l; split_bf16(W1[e], h, l);
        b1hi[n * 128 + k] = h; b1lo[n * 128 + k] = l;
        return;
    }
    e -= 128 * 128;
    if (e < 128 * 64) {                       // W_enc2 [k=128][n=64]
        int k = e >> 6, n = e & 63;
        __nv_bfloat16 h, l; split_bf16(W2[e], h, l);
        b2hi[n * 128 + k] = h; b2lo[n * 128 + k] = l;
        return;
    }
    e -= 128 * 64;
    if (e < 64 * 128) {                       // W_dec1 [k=64][n=128]
        int k = e >> 7, n = e & 127;
        __nv_bfloat16 h, l; split_bf16(Wd1[e], h, l);
        d1hi[n * 64 + k] = h; d1lo[n * 64 + k] = l;
        return;
    }
    e -= 64 * 128;
    if (e < 128 * 128) {                      // W_dec2 [k=128][n=128]
        int k = e >> 7, n = e & 127;
        __nv_bfloat16 h, l; split_bf16(Wd2[e], h, l);
        d2hi[n * 128 + k] = h; d2lo[n * 128 + k] = l;
    }
}

// ---------------- unified split-bf16 mma GEMM ----------------------------------
// out[M,N] = (Ahi+Alo)[M,K] @ (Bhi+Blo)[N,K]^T  (3 passes: AhBh + AhBl + AlBh)
// NW warps: NW/2 m-tiles of 16 rows (BM = NW*8) x 2 n-halves. ldmatrix loads.
// MODE 0: raw fp32 -> outf.
template<int K, int N, int MODE, int NW>
__global__ __launch_bounds__(NW * 32, (NW == 8) ? 2 : 1) void k_mmagemm(
    const __nv_bfloat16* __restrict__ Ahi, const __nv_bfloat16* __restrict__ Alo,
    const __nv_bfloat16* __restrict__ Bhi, const __nv_bfloat16* __restrict__ Blo,
    float* __restrict__ outf, int M)
{
    constexpr int BM  = NW * 8;         // 64 (NW=8) or 128 (NW=16)
    constexpr int TH  = NW * 32;
    constexpr int P   = K + 8;
    constexpr int NT  = N / 16;
    constexpr int KS  = K / 16;
    constexpr int CPR = K / 8;
    extern __shared__ __nv_bfloat16 smb[];
    __nv_bfloat16* Ah_s = smb;                     // [BM][P]
    __nv_bfloat16* Al_s = smb + BM * P;
    __nv_bfloat16* Bh_s = smb + 2 * BM * P;        // [N][P]
    __nv_bfloat16* Bl_s = smb + 2 * BM * P + N * P;

    const int tid  = threadIdx.x;
    const int warp = tid >> 5;
    const int lane = tid & 31;
    const int gid  = lane >> 2;
    const int tig  = lane & 3;
    const int mbase = (warp >> 1) * 16;
    const int nbase = (warp & 1) * (N / 2);
    const int row0 = blockIdx.x * BM;

    for (int i = tid; i < BM * CPR; i += TH) {
        int r = i / CPR, c = i % CPR;
        int gr = row0 + r;
        uint4 vh = make_uint4(0,0,0,0), vl = make_uint4(0,0,0,0);
        if (gr < M) {
            vh = *(const uint4*)&Ahi[(size_t)gr * K + c * 8];
            vl = *(const uint4*)&Alo[(size_t)gr * K + c * 8];
        }
        *(uint4*)&Ah_s[r * P + c * 8] = vh;
        *(uint4*)&Al_s[r * P + c * 8] = vl;
    }
    for (int i = tid; i < N * CPR; i += TH) {
        int r = i / CPR, c = i % CPR;
        *(uint4*)&Bh_s[r * P + c * 8] = *(const uint4*)&Bhi[(size_t)r * K + c * 8];
        *(uint4*)&Bl_s[r * P + c * 8] = *(const uint4*)&Blo[(size_t)r * K + c * 8];
    }
    __syncthreads();

    const unsigned sbase = smem_u32(smb);
    const unsigned offA = ((mbase + (lane & 15)) * P + ((lane & 16) ? 8 : 0)) * 2;
    unsigned offB[NT / 2];
#pragma unroll
    for (int p = 0; p < NT / 2; p++)
        offB[p] = ((nbase + p * 16 + ((lane & 16) ? 8 : 0) + (lane & 7)) * P
                   + ((lane & 8) ? 8 : 0)) * 2;

    const unsigned aHi = sbase;
    const unsigned aLo = sbase + BM * P * 2;
    const unsigned bHi = sbase + 4 * BM * P;
    const unsigned bLo = bHi + N * P * 2;

    float acc[NT][4];
#pragma unroll
    for (int nj = 0; nj < NT; nj++)
#pragma unroll
        for (int q = 0; q < 4; q++) acc[nj][q] = 0.f;

#pragma unroll
    for (int pass = 0; pass < 3; pass++) {
        const unsigned aB = ((pass == 2) ? aLo : aHi) + offA;
        const unsigned bB = (pass == 1) ? bLo : bHi;
#pragma unroll
        for (int ks = 0; ks < KS; ks++) {
            unsigned a[4];
            ldsm4(a, aB + ks * 32);
#pragma unroll
            for (int p = 0; p < NT / 2; p++) {
                unsigned b[4];
                ldsm4(b, bB + offB[p] + ks * 32);
                mma_bf16(acc[2 * p],     a, b[0], b[1]);
                mma_bf16(acc[2 * p + 1], a, b[2], b[3]);
            }
        }
    }

    const int r = row0 + mbase + gid;
#pragma unroll
    for (int nj = 0; nj < NT; nj++) {
        const int c = nbase + nj * 8 + tig * 2;
        if (r < M)
            *(float2*)&outf[(size_t)r * N + c] = make_float2(acc[nj][0], acc[nj][1]);
        if (r + 8 < M)
            *(float2*)&outf[(size_t)(r + 8) * N + c] = make_float2(acc[nj][2], acc[nj][3]);
    }
}

// ---------------- fused decoder: out = relu(z2@Wd1 + b1) @ Wd2 + b2 ------------
// 512 threads, BM=128. Stage-1 intermediate T kept in smem as bf16 hi/lo.
// smem (bf16 elems): Zh/Zl [128][72], W1h/W1l [128][72],
//                    Th/Tl [128][136], W2h/W2l [128][136]  -> 212992 bytes.
#define DEC_SMEM_BYTES 212992
__global__ __launch_bounds__(512, 1) void k_dec(
    const __nv_bfloat16* __restrict__ Zhi, const __nv_bfloat16* __restrict__ Zlo,
    const __nv_bfloat16* __restrict__ W1h, const __nv_bfloat16* __restrict__ W1l,
    const float* __restrict__ b1,
    const __nv_bfloat16* __restrict__ W2h, const __nv_bfloat16* __restrict__ W2l,
    const float* __restrict__ b2, float* __restrict__ out, int M)
{
    constexpr int P1 = 72, P2 = 136;
    extern __shared__ __nv_bfloat16 smb[];
    __nv_bfloat16* Zh_s  = smb;                    // [128][72]
    __nv_bfloat16* Zl_s  = smb + 128 * P1;
    __nv_bfloat16* W1h_s = smb + 2 * 128 * P1;     // [128][72]
    __nv_bfloat16* W1l_s = smb + 3 * 128 * P1;
    __nv_bfloat16* Th_s  = smb + 4 * 128 * P1;     // [128][136]
    __nv_bfloat16* Tl_s  = smb + 4 * 128 * P1 + 128 * P2;
    __nv_bfloat16* W2h_s = smb + 4 * 128 * P1 + 2 * 128 * P2;
    __nv_bfloat16* W2l_s = smb + 4 * 128 * P1 + 3 * 128 * P2;

    const int tid  = threadIdx.x;
    const int warp = tid >> 5;
    const int lane = tid & 31;
    const int gid  = lane >> 2;
    const int tig  = lane & 3;
    const int mbase = (warp >> 1) * 16;    // 8 m-tiles of 16 rows
    const int nbase = (warp & 1) * 64;     // 2 n-halves of N=128
    const int row0 = blockIdx.x * 128;

    // ---- loads: Z (K=64, 8 chunks/row), W1 (8 chunks), W2 (16 chunks) ----
    for (int i = tid; i < 128 * 8; i += 512) {
        int r = i >> 3, c = i & 7;
        int gr = row0 + r;
        uint4 vh = make_uint4(0,0,0,0), vl = make_uint4(0,0,0,0);
        if (gr < M) {
            vh = *(const uint4*)&Zhi[(size_t)gr * 64 + c * 8];
            vl = *(const uint4*)&Zlo[(size_t)gr * 64 + c * 8];
        }
        *(uint4*)&Zh_s[r * P1 + c * 8] = vh;
        *(uint4*)&Zl_s[r * P1 + c * 8] = vl;
    }
    for (int i = tid; i < 128 * 8; i += 512) {
        int r = i >> 3, c = i & 7;
        *(uint4*)&W1h_s[r * P1 + c * 8] = *(const uint4*)&W1h[(size_t)r * 64 + c * 8];
        *(uint4*)&W1l_s[r * P1 + c * 8] = *(const uint4*)&W1l[(size_t)r * 64 + c * 8];
    }
    for (int i = tid; i < 128 * 16; i += 512) {
        int r = i >> 4, c = i & 15;
        *(uint4*)&W2h_s[r * P2 + c * 8] = *(const uint4*)&W2h[(size_t)r * 128 + c * 8];
        *(uint4*)&W2l_s[r * P2 + c * 8] = *(const uint4*)&W2l[(size_t)r * 128 + c * 8];
    }
    __syncthreads();

    const unsigned sbase = smem_u32(smb);
    const unsigned zHi  = sbase;
    const unsigned zLo  = sbase + 128 * P1 * 2;
    const unsigned w1Hi = sbase + 2 * 128 * P1 * 2;
    const unsigned w1Lo = sbase + 3 * 128 * P1 * 2;
    const unsigned tHi  = sbase + 4 * 128 * P1 * 2;
    const unsigned tLo  = tHi + 128 * P2 * 2;
    const unsigned w2Hi = tHi + 2 * 128 * P2 * 2;
    const unsigned w2Lo = tHi + 3 * 128 * P2 * 2;

    // ---- stage 1: T = relu(z2 @ Wd1 + b1), K=64 ----
    {
        const unsigned offA = ((mbase + (lane & 15)) * P1 + ((lane & 16) ? 8 : 0)) * 2;
        unsigned offB[4];
#pragma unroll
        for (int p = 0; p < 4; p++)
            offB[p] = ((nbase + p * 16 + ((lane & 16) ? 8 : 0) + (lane & 7)) * P1
                       + ((lane & 8) ? 8 : 0)) * 2;

        float acc[8][4];
#pragma unroll
        for (int nj = 0; nj < 8; nj++)
#pragma unroll
            for (int q = 0; q < 4; q++) acc[nj][q] = 0.f;

#pragma unroll
        for (int pass = 0; pass < 3; pass++) {
            const unsigned aB = ((pass == 2) ? zLo : zHi) + offA;
            const unsigned bB = (pass == 1) ? w1Lo : w1Hi;
#pragma unroll
            for (int ks = 0; ks < 4; ks++) {
                unsigned a[4];
                ldsm4(a, aB + ks * 32);
#pragma unroll
                for (int p = 0; p < 4; p++) {
                    unsigned b[4];
                    ldsm4(b, bB + offB[p] + ks * 32);
                    mma_bf16(acc[2 * p],     a, b[0], b[1]);
                    mma_bf16(acc[2 * p + 1], a, b[2], b[3]);
                }
            }
        }

        // epilogue 1: bias + relu -> split -> Th/Tl (smem)
        const int rl = mbase + gid;
#pragma unroll
        for (int nj = 0; nj < 8; nj++) {
            const int c = nbase + nj * 8 + tig * 2;
            const float bb0 = b1[c], bb1 = b1[c + 1];
#pragma unroll
            for (int h = 0; h < 2; h++) {
                int rr = rl + h * 8;
                float o0 = fmaxf(acc[nj][2 * h]     + bb0, 0.f);
                float o1 = fmaxf(acc[nj][2 * h + 1] + bb1, 0.f);
                __nv_bfloat16 h0, h1, l0, l1;
                split_bf16(o0, h0, l0);
                split_bf16(o1, h1, l1);
                __nv_bfloat162 ph; ph.x = h0; ph.y = h1;
                __nv_bfloat162 pl; pl.x = l0; pl.y = l1;
                *(__nv_bfloat162*)&Th_s[rr * P2 + c] = ph;
                *(__nv_bfloat162*)&Tl_s[rr * P2 + c] = pl;
            }
        }
    }
    __syncthreads();

    // ---- stage 2: out = T @ Wd2 + b2, K=128 ----
    {
        const unsigned offA = ((mbase + (lane & 15)) * P2 + ((lane & 16) ? 8 : 0)) * 2;
        unsigned offB[4];
#pragma unroll
        for (int p = 0; p < 4; p++)
            offB[p] = ((nbase + p * 16 + ((lane & 16) ? 8 : 0) + (lane & 7)) * P2
                       + ((lane & 8) ? 8 : 0)) * 2;

        float acc[8][4];
#pragma unroll
        for (int nj = 0; nj < 8; nj++)
#pragma unroll
            for (int q = 0; q < 4; q++) acc[nj][q] = 0.f;

#pragma unroll
        for (int pass = 0; pass < 3; pass++) {
            const unsigned aB = ((pass == 2) ? tLo : tHi) + offA;
            const unsigned bB = (pass == 1) ? w2Lo : w2Hi;
#pragma unroll
            for (int ks = 0; ks < 8; ks++) {
                unsigned a[4];
                ldsm4(a, aB + ks * 32);
#pragma unroll
                for (int p = 0; p < 4; p++) {
                    unsigned b[4];
                    ldsm4(b, bB + offB[p] + ks * 32);
                    mma_bf16(acc[2 * p],     a, b[0], b[1]);
                    mma_bf16(acc[2 * p + 1], a, b[2], b[3]);
                }
            }
        }

        const int r = row0 + mbase + gid;
#pragma unroll
        for (int nj = 0; nj < 8; nj++) {
            const int c = nbase + nj * 8 + tig * 2;
            const float bb0 = b2[c], bb1 = b2[c + 1];
            if (r < M)
                *(float2*)&out[(size_t)r * 128 + c] =
                    make_float2(acc[nj][0] + bb0, acc[nj][1] + bb1);
            if (r + 8 < M)
                *(float2*)&out[(size_t)(r + 8) * 128 + c] =
                    make_float2(acc[nj][2] + bb0, acc[nj][3] + bb1);
        }
    }
}

// ---------------- CSR gather F=128 -> bf16 hi/lo output ------------------------
__global__ __launch_bounds__(256) void k_gather128(
    const int* __restrict__ off, const int* __restrict__ cnt,
    const int* __restrict__ srt, const float* __restrict__ xs,
    const float* __restrict__ dis, const float* __restrict__ bias,
    __nv_bfloat16* __restrict__ zhi, __nv_bfloat16* __restrict__ zlo, int n)
{
    int w    = (blockIdx.x * blockDim.x + threadIdx.x) >> 5;
    int lane = threadIdx.x & 31;
    if (w >= n) return;
    int s = off[w];
    int e = s + cnt[w];
    float d = dis[w];

    float4 sv = *(const float4*)&xs[(size_t)w * 128 + lane * 4];
    float4 sum = make_float4(d * sv.x, d * sv.y, d * sv.z, d * sv.w);
    int t = s;
    for (; t + 4 <= e; t += 4) {
        int i0 = __ldg(&srt[t]);
        int i1 = __ldg(&srt[t + 1]);
        int i2 = __ldg(&srt[t + 2]);
        int i3 = __ldg(&srt[t + 3]);
        float d0 = __ldg(&dis[i0]);
        float d1 = __ldg(&dis[i1]);
        float d2 = __ldg(&dis[i2]);
        float d3 = __ldg(&dis[i3]);
        float4 v0 = *(const float4*)&xs[(size_t)i0 * 128 + lane * 4];
        float4 v1 = *(const float4*)&xs[(size_t)i1 * 128 + lane * 4];
        float4 v2 = *(const float4*)&xs[(size_t)i2 * 128 + lane * 4];
        float4 v3 = *(const float4*)&xs[(size_t)i3 * 128 + lane * 4];
        sum.x = fmaf(d3, v3.x, fmaf(d2, v2.x, fmaf(d1, v1.x, fmaf(d0, v0.x, sum.x))));
        sum.y = fmaf(d3, v3.y, fmaf(d2, v2.y, fmaf(d1, v1.y, fmaf(d0, v0.y, sum.y))));
        sum.z = fmaf(d3, v3.z, fmaf(d2, v2.z, fmaf(d1, v1.z, fmaf(d0, v0.z, sum.z))));
        sum.w = fmaf(d3, v3.w, fmaf(d2, v2.w, fmaf(d1, v1.w, fmaf(d0, v0.w, sum.w))));
    }
    for (; t < e; t++) {
        int i0 = __ldg(&srt[t]);
        float d0 = __ldg(&dis[i0]);
        float4 v0 = *(const float4*)&xs[(size_t)i0 * 128 + lane * 4];
        sum.x = fmaf(d0, v0.x, sum.x); sum.y = fmaf(d0, v0.y, sum.y);
        sum.z = fmaf(d0, v0.z, sum.z); sum.w = fmaf(d0, v0.w, sum.w);
    }
    const float4 b = *(const float4*)&bias[lane * 4];
    float o0 = fmaxf(fmaf(d, sum.x, b.x), 0.f);
    float o1 = fmaxf(fmaf(d, sum.y, b.y), 0.f);
    float o2 = fmaxf(fmaf(d, sum.z, b.z), 0.f);
    float o3 = fmaxf(fmaf(d, sum.w, b.w), 0.f);

    __nv_bfloat16 h0, h1, h2, h3, l0, l1, l2, l3;
    split_bf16(o0, h0, l0); split_bf16(o1, h1, l1);
    split_bf16(o2, h2, l2); split_bf16(o3, h3, l3);
    __nv_bfloat162 p;
    size_t ob = (size_t)w * 128 + lane * 4;
    p.x = h0; p.y = h1; *(__nv_bfloat162*)&zhi[ob]     = p;
    p.x = h2; p.y = h3; *(__nv_bfloat162*)&zhi[ob + 2] = p;
    p.x = l0; p.y = l1; *(__nv_bfloat162*)&zlo[ob]     = p;
    p.x = l2; p.y = l3; *(__nv_bfloat162*)&zlo[ob + 2] = p;
}

// ---------------- CSR gather F=64 (half-warp) -> bf16 hi/lo --------------------
__global__ __launch_bounds__(256) void k_gather64(
    const int* __restrict__ off, const int* __restrict__ cnt,
    const int* __restrict__ srt, const float* __restrict__ xs,
    const float* __restrict__ dis, const float* __restrict__ bias,
    __nv_bfloat16* __restrict__ zhi, __nv_bfloat16* __restrict__ zlo, int n)
{
    int hw   = (blockIdx.x * blockDim.x + threadIdx.x) >> 4;
    int lane = threadIdx.x & 15;
    if (hw >= n) return;
    int s = off[hw];
    int e = s + cnt[hw];
    float d = dis[hw];

    float4 sv = *(const float4*)&xs[(size_t)hw * 64 + lane * 4];
    float4 sum = make_float4(d * sv.x, d * sv.y, d * sv.z, d * sv.w);
    int t = s;
    for (; t + 4 <= e; t += 4) {
        int i0 = __ldg(&srt[t]);
        int i1 = __ldg(&srt[t + 1]);
        int i2 = __ldg(&srt[t + 2]);
        int i3 = __ldg(&srt[t + 3]);
        float d0 = __ldg(&dis[i0]);
        float d1 = __ldg(&dis[i1]);
        float d2 = __ldg(&dis[i2]);
        float d3 = __ldg(&dis[i3]);
        float4 v0 = *(const float4*)&xs[(size_t)i0 * 64 + lane * 4];
        float4 v1 = *(const float4*)&xs[(size_t)i1 * 64 + lane * 4];
        float4 v2 = *(const float4*)&xs[(size_t)i2 * 64 + lane * 4];
        float4 v3 = *(const float4*)&xs[(size_t)i3 * 64 + lane * 4];
        sum.x = fmaf(d3, v3.x, fmaf(d2, v2.x, fmaf(d1, v1.x, fmaf(d0, v0.x, sum.x))));
        sum.y = fmaf(d3, v3.y, fmaf(d2, v2.y, fmaf(d1, v1.y, fmaf(d0, v0.y, sum.y))));
        sum.z = fmaf(d3, v3.z, fmaf(d2, v2.z, fmaf(d1, v1.z, fmaf(d0, v0.z, sum.z))));
        sum.w = fmaf(d3, v3.w, fmaf(d2, v2.w, fmaf(d1, v1.w, fmaf(d0, v0.w, sum.w))));
    }
    for (; t < e; t++) {
        int i0 = __ldg(&srt[t]);
        float d0 = __ldg(&dis[i0]);
        float4 v0 = *(const float4*)&xs[(size_t)i0 * 64 + lane * 4];
        sum.x = fmaf(d0, v0.x, sum.x); sum.y = fmaf(d0, v0.y, sum.y);
        sum.z = fmaf(d0, v0.z, sum.z); sum.w = fmaf(d0, v0.w, sum.w);
    }
    const float4 b = *(const float4*)&bias[lane * 4];
    float o0 = fmaxf(fmaf(d, sum.x, b.x), 0.f);
    float o1 = fmaxf(fmaf(d, sum.y, b.y), 0.f);
    float o2 = fmaxf(fmaf(d, sum.z, b.z), 0.f);
    float o3 = fmaxf(fmaf(d, sum.w, b.w), 0.f);

    __nv_bfloat16 h0, h1, h2, h3, l0, l1, l2, l3;
    split_bf16(o0, h0, l0); split_bf16(o1, h1, l1);
    split_bf16(o2, h2, l2); split_bf16(o3, h3, l3);
    __nv_bfloat162 p;
    size_t ob = (size_t)hw * 64 + lane * 4;
    p.x = h0; p.y = h1; *(__nv_bfloat162*)&zhi[ob]     = p;
    p.x = h2; p.y = h3; *(__nv_bfloat162*)&zhi[ob + 2] = p;
    p.x = l0; p.y = l1; *(__nv_bfloat162*)&zlo[ob]     = p;
    p.x = l2; p.y = l3; *(__nv_bfloat162*)&zlo[ob + 2] = p;
}

// ---------------- launch ----------------
extern "C" void kernel_launch(void* const* d_in, const int* in_sizes, int n_in,
                              void* d_out, int out_size)
{
    const float* x      = (const float*)d_in[0];
    const void*  ei     = d_in[1];
    const float* W_enc1 = (const float*)d_in[2];
    const float* b_enc1 = (const float*)d_in[3];
    const float* W_enc2 = (const float*)d_in[4];
    const float* b_enc2 = (const float*)d_in[5];
    const float* W_dec1 = (const float*)d_in[6];
    const float* b_dec1 = (const float*)d_in[7];
    const float* W_dec2 = (const float*)d_in[8];
    const float* b_dec2 = (const float*)d_in[9];
    float*       out    = (float*)d_out;

    const int M = in_sizes[0] / 128;   // 50000
    int E = in_sizes[1] / 2;           // 600000
    if (E > MAX_EDGES) E = MAX_EDGES;

    int *bad, *row, *col, *srt, *cnt, *off, *cur, *stat, *aggr, *pref;
    float *dis, *xs1, *xs2;
    __nv_bfloat16 *xhi, *xlo, *z1hi, *z1lo, *z2hi, *z2lo;
    __nv_bfloat16 *b1hi, *b1lo, *b2hi, *b2lo, *d1hi, *d1lo, *d2hi, *d2lo;
    cudaGetSymbolAddress((void**)&bad,  g_bad);
    cudaGetSymbolAddress((void**)&row,  g_row);
    cudaGetSymbolAddress((void**)&col,  g_col);
    cudaGetSymbolAddress((void**)&srt,  g_srt);
    cudaGetSymbolAddress((void**)&cnt,  g_cnt);
    cudaGetSymbolAddress((void**)&off,  g_off);
    cudaGetSymbolAddress((void**)&cur,  g_cur);
    cudaGetSymbolAddress((void**)&stat, g_stat);
    cudaGetSymbolAddress((void**)&aggr, g_aggr);
    cudaGetSymbolAddress((void**)&pref, g_pref);
    cudaGetSymbolAddress((void**)&dis,  g_dis);
    cudaGetSymbolAddress((void**)&xs1,  g_xs1);
    cudaGetSymbolAddress((void**)&xs2,  g_xs2);
    cudaGetSymbolAddress((void**)&xhi,  g_xhi);
    cudaGetSymbolAddress((void**)&xlo,  g_xlo);
    cudaGetSymbolAddress((void**)&z1hi, g_z1hi);
    cudaGetSymbolAddress((void**)&z1lo, g_z1lo);
    cudaGetSymbolAddress((void**)&z2hi, g_z2hi);
    cudaGetSymbolAddress((void**)&z2lo, g_z2lo);
    cudaGetSymbolAddress((void**)&b1hi, g_b1hi);
    cudaGetSymbolAddress((void**)&b1lo, g_b1lo);
    cudaGetSymbolAddress((void**)&b2hi, g_b2hi);
    cudaGetSymbolAddress((void**)&b2lo, g_b2lo);
    cudaGetSymbolAddress((void**)&d1hi, g_d1hi);
    cudaGetSymbolAddress((void**)&d1lo, g_d1lo);
    cudaGetSymbolAddress((void**)&d2hi, g_d2hi);
    cudaGetSymbolAddress((void**)&d2lo, g_d2lo);

    // smem sizes (bytes)
    const int SM_G1 = 2 * (128 + 128) * 136 * 2;  // 139264 (K=128,N=128,NW=16)
    const int SM_G2 = 2 * (64 + 64)   * 136 * 2;  //  69632 (K=128,N=64, NW=8)
    static bool attr_set = false;
    if (!attr_set) {
        cudaFuncSetAttribute(k_mmagemm<128,128,0,16>, cudaFuncAttributeMaxDynamicSharedMemorySize, SM_G1);
        cudaFuncSetAttribute(k_mmagemm<128,64,0,8>,   cudaFuncAttributeMaxDynamicSharedMemorySize, SM_G2);
        cudaFuncSetAttribute(k_dec, cudaFuncAttributeMaxDynamicSharedMemorySize, DEC_SMEM_BYTES);
        attr_set = true;
    }

    const int TB = 256;
    const int EB = (E + TB - 1) / TB;
    const int NB = (M + 255) / 256;
    const int GB128 = (M + 127) / 128;
    const int GB64  = (M + 63) / 64;
    const int AGB1 = (M * 32 + TB - 1) / TB;
    const int AGB2 = (M * 16 + TB - 1) / TB;
    const int CVT_ELEMS = 128 * 128 + 128 * 64 + 64 * 128 + 128 * 128;
    const int CVB  = (M * 32 + CVT_ELEMS + TB - 1) / TB;

    // 1: split x / transpose+split all weights
    k_cvt    <<<CVB, TB>>>(x, W_enc1, W_enc2, W_dec1, W_dec2,
                           xhi, xlo, b1hi, b1lo, b2hi, b2lo,
                           d1hi, d1lo, d2hi, d2lo, M);
    // 2: zero cnt/status + dtype sniff
    k_prep   <<<EB, TB>>>((const long long*)ei, E, M, cnt, stat, bad);
    // 3: convert + degree count
    k_convert<<<EB, TB>>>(ei, E, M, bad, row, col, cnt);
    // 4 (PROFILED SLOT): gemm1 -> xs1 fp32 (unscaled xw), BM=128
    k_mmagemm<128,128,0,16><<<GB128, 512, SM_G1>>>(xhi, xlo, b1hi, b1lo, xs1, M);
    // 5: single-pass scan -> off/cur/dis
    k_scan   <<<NB, 256>>>(cnt, M, off, cur, dis, stat, aggr, pref);
    // 6: CSR placement
    k_place  <<<EB, TB>>>(row, col, cur, srt, E);
    // 7: layer-1 aggregation -> z1 hi/lo
    k_gather128<<<AGB1, TB>>>(off, cnt, srt, xs1, dis, b_enc1, z1hi, z1lo, M);
    // 8: gemm2 -> xs2 fp32
    k_mmagemm<128,64,0,8><<<GB64, 256, SM_G2>>>(z1hi, z1lo, b2hi, b2lo, xs2, M);
    // 9: layer-2 aggregation -> z2 hi/lo
    k_gather64<<<AGB2, TB>>>(off, cnt, srt, xs2, dis, b_enc2, z2hi, z2lo, M);
    // 10: fused decoder
    k_dec<<<GB128, 512, DEC_SMEM_BYTES>>>(z2hi, z2lo, d1hi, d1lo, b_dec1,
                                          d2hi, d2lo, b_dec2, out, M);
}

// round 16
// speedup vs baseline: 1.5113x; 1.1373x over previous
#include <cuda_runtime.h>
#include <cuda_bf16.h>

// Problem constants (reference: N_NODES=50000, F=128, HIDDEN=128, OUT=64, E=600000)
#define MAX_NODES 50000
#define MAX_EDGES 600000
#define SCAN_NB ((MAX_NODES + 255) / 256)   // 196

// ---------------- scratch (device globals; no allocations allowed) -------------
__device__ int   g_bad = 0;
__device__ int   g_row [MAX_EDGES];
__device__ int   g_col [MAX_EDGES];
__device__ int   g_srt [MAX_EDGES];
__device__ int   g_cnt [MAX_NODES];
__device__ int   g_off [MAX_NODES];
__device__ int   g_cur [MAX_NODES];
__device__ int   g_stat[SCAN_NB];
__device__ int   g_aggr[SCAN_NB];
__device__ int   g_pref[SCAN_NB];
__device__ float g_dis [MAX_NODES];
__device__ float g_xs1 [MAX_NODES * 128];
__device__ float g_xs2 [MAX_NODES * 64];
// bf16 split-precision operands / intermediates
__device__ __nv_bfloat16 g_xhi [MAX_NODES * 128];
__device__ __nv_bfloat16 g_xlo [MAX_NODES * 128];
__device__ __nv_bfloat16 g_z1hi[MAX_NODES * 128];
__device__ __nv_bfloat16 g_z1lo[MAX_NODES * 128];
__device__ __nv_bfloat16 g_z2hi[MAX_NODES * 64];
__device__ __nv_bfloat16 g_z2lo[MAX_NODES * 64];
__device__ __nv_bfloat16 g_b1hi[128 * 128];   // W_enc1^T  [n][k=128]
__device__ __nv_bfloat16 g_b1lo[128 * 128];
__device__ __nv_bfloat16 g_b2hi[64 * 128];    // W_enc2^T  [n][k=128]
__device__ __nv_bfloat16 g_b2lo[64 * 128];
__device__ __nv_bfloat16 g_d1hi[128 * 64];    // W_dec1^T  [n=128][k=64]
__device__ __nv_bfloat16 g_d1lo[128 * 64];
__device__ __nv_bfloat16 g_d2hi[128 * 128];   // W_dec2^T  [n=128][k=128]
__device__ __nv_bfloat16 g_d2lo[128 * 128];

// ---------------- helpers ------------------------------------------------------
__device__ __forceinline__ unsigned int smem_u32(const void* p) {
    unsigned int a;
    asm("{ .reg .u64 t; cvta.to.shared.u64 t, %1; cvt.u32.u64 %0, t; }"
        : "=r"(a) : "l"(p));
    return a;
}
__device__ __forceinline__ void mma_bf16(float* c, const unsigned* a,
                                         unsigned b0, unsigned b1) {
    asm volatile(
        "mma.sync.aligned.m16n8k16.row.col.f32.bf16.bf16.f32 "
        "{%0,%1,%2,%3}, {%4,%5,%6,%7}, {%8,%9}, {%0,%1,%2,%3};"
        : "+f"(c[0]), "+f"(c[1]), "+f"(c[2]), "+f"(c[3])
        : "r"(a[0]), "r"(a[1]), "r"(a[2]), "r"(a[3]), "r"(b0), "r"(b1));
}
__device__ __forceinline__ void ldsm4(unsigned* r, unsigned addr) {
    asm volatile("ldmatrix.sync.aligned.m8n8.x4.shared.b16 {%0,%1,%2,%3}, [%4];"
        : "=r"(r[0]), "=r"(r[1]), "=r"(r[2]), "=r"(r[3]) : "r"(addr));
}
__device__ __forceinline__ void split_bf16(float v, __nv_bfloat16& h, __nv_bfloat16& l) {
    h = __float2bfloat16(v);
    l = __float2bfloat16(v - __bfloat162float(h));
}

// ---------------- cvt + prep (merged): split operands, zero counters, sniff ----
__global__ void k_cvtprep(const float* __restrict__ x,
                      const float* __restrict__ W1, const float* __restrict__ W2,
                      const float* __restrict__ Wd1, const float* __restrict__ Wd2,
                      const long long* __restrict__ ei, int E,
                      __nv_bfloat16* __restrict__ xhi, __nv_bfloat16* __restrict__ xlo,
                      __nv_bfloat16* __restrict__ b1hi, __nv_bfloat16* __restrict__ b1lo,
                      __nv_bfloat16* __restrict__ b2hi, __nv_bfloat16* __restrict__ b2lo,
                      __nv_bfloat16* __restrict__ d1hi, __nv_bfloat16* __restrict__ d1lo,
                      __nv_bfloat16* __restrict__ d2hi, __nv_bfloat16* __restrict__ d2lo,
                      int* __restrict__ cnt, int* __restrict__ stat,
                      int* __restrict__ bad, int M)
{
    const int NX4 = M * 32;           // float4 count of x
    int gid = blockIdx.x * blockDim.x + threadIdx.x;
    if (gid < NX4) {
        float4 v = ((const float4*)x)[gid];
        __nv_bfloat16 h0, h1, h2, h3, l0, l1, l2, l3;
        split_bf16(v.x, h0, l0); split_bf16(v.y, h1, l1);
        split_bf16(v.z, h2, l2); split_bf16(v.w, h3, l3);
        __nv_bfloat162 a, b;
        a.x = h0; a.y = h1; b.x = h2; b.y = h3;
        *(__nv_bfloat162*)&xhi[(size_t)gid * 4]     = a;
        *(__nv_bfloat162*)&xhi[(size_t)gid * 4 + 2] = b;
        a.x = l0; a.y = l1; b.x = l2; b.y = l3;
        *(__nv_bfloat162*)&xlo[(size_t)gid * 4]     = a;
        *(__nv_bfloat162*)&xlo[(size_t)gid * 4 + 2] = b;
        return;
    }
    int e = gid - NX4;
    if (e < 128 * 128) {                      // W_enc1 [k=128][n=128]
        int k = e >> 7, n = e & 127;
        __nv_bfloat16 h, l; split_bf16(W1[e], h, l);
        b1hi[n * 128 + k] = h; b1lo[n * 128 + k] = l;
        return;
    }
    e -= 128 * 128;
    if (e < 128 * 64) {                       // W_enc2 [k=128][n=64]
        int k = e >> 6, n = e & 63;
        __nv_bfloat16 h, l; split_bf16(W2[e], h, l);
        b2hi[n * 128 + k] = h; b2lo[n * 128 + k] = l;
        return;
    }
    e -= 128 * 64;
    if (e < 64 * 128) {                       // W_dec1 [k=64][n=128]
        int k = e >> 7, n = e & 127;
        __nv_bfloat16 h, l; split_bf16(Wd1[e], h, l);
        d1hi[n * 64 + k] = h; d1lo[n * 64 + k] = l;
        return;
    }
    e -= 64 * 128;
    if (e < 128 * 128) {                      // W_dec2 [k=128][n=128]
        int k = e >> 7, n = e & 127;
        __nv_bfloat16 h, l; split_bf16(Wd2[e], h, l);
        d2hi[n * 128 + k] = h; d2lo[n * 128 + k] = l;
        return;
    }
    e -= 128 * 128;
    if (e < E) {                              // dtype sniff (int64 view in-bounds
        long long v = ei[e];                  //  under either layout)
        if ((v < 0 || v >= (long long)M) && *bad == 0) atomicOr(bad, 1);
        return;
    }
    e -= E;
    if (e < M) { cnt[e] = 0; return; }        // zero degree counters
    e -= M;
    if (e < SCAN_NB) stat[e] = 0;             // zero scan statuses
}

// ---------------- convert to int32 row/col + in-degree count -------------------
__global__ void k_convert(const void* __restrict__ ei, int E, int n,
                          const int* __restrict__ bad,
                          int* __restrict__ row, int* __restrict__ col,
                          int* __restrict__ cnt) {
    int i = blockIdx.x * blockDim.x + threadIdx.x;
    if (i >= E) return;
    int r, c;
    if (*bad == 0) {
        r = (int)((const long long*)ei)[i];
        c = (int)((const long long*)ei)[(size_t)E + i];
    } else {
        r = ((const int*)ei)[i];
        c = ((const int*)ei)[(size_t)E + i];
    }
    if ((unsigned)r >= (unsigned)n) r = 0;
    if ((unsigned)c >= (unsigned)n) c = 0;
    row[i] = r;
    col[i] = c;
    atomicAdd(&cnt[c], 1);
}

__global__ __launch_bounds__(256) void k_scan(
    const int* __restrict__ cnt, int n,
    int* __restrict__ off, int* __restrict__ cur, float* __restrict__ dis,
    volatile int* stat, volatile int* aggr, volatile int* pref)
{
    __shared__ int sh[256];
    __shared__ int s_prefix;
    const int b = blockIdx.x;
    const int i = b * 256 + threadIdx.x;
    int v = (i < n) ? cnt[i] : 0;
    sh[threadIdx.x] = v;
    __syncthreads();
#pragma unroll
    for (int d = 1; d < 256; d <<= 1) {
        int t = (threadIdx.x >= d) ? sh[threadIdx.x - d] : 0;
        __syncthreads();
        sh[threadIdx.x] += t;
        __syncthreads();
    }
    int incl = sh[threadIdx.x];
    int total = sh[255];

    if (threadIdx.x == 0) {
        if (b == 0) {
            pref[0] = total;
            __threadfence();
            ((int*)stat)[0] = 2;
            s_prefix = 0;
        } else {
            aggr[b] = total;
            __threadfence();
            ((int*)stat)[b] = 1;
            int run = 0;
            int p = b - 1;
            while (true) {
                int st;
                do { st = stat[p]; } while (st == 0);
                __threadfence();
                if (st == 2) { run += pref[p]; break; }
                run += aggr[p];
                p--;
            }
            pref[b] = run + total;
            __threadfence();
            ((int*)stat)[b] = 2;
            s_prefix = run;
        }
    }
    __syncthreads();
    int prefix = s_prefix;
    if (i < n) {
        int o = prefix + incl - v;
        off[i] = o;
        cur[i] = o;
        dis[i] = rsqrtf((float)(v + 1));
    }
}

__global__ void k_place(const int* __restrict__ row, const int* __restrict__ col,
                        int* __restrict__ cur, int* __restrict__ srt, int E) {
    int e = blockIdx.x * blockDim.x + threadIdx.x;
    if (e >= E) return;
    int pos = atomicAdd(&cur[col[e]], 1);
    srt[pos] = row[e];
}

// ---------------- unified split-bf16 mma GEMM (fused 3-product k-loop) ---------
// out[M,N] = (Ahi+Alo)[M,K] @ (Bhi+Blo)[N,K]^T   (AhBh + AhBl + AlBh per k-step)
template<int K, int N, int NW>
__global__ __launch_bounds__(NW * 32, (NW == 8) ? 2 : 1) void k_mmagemm(
    const __nv_bfloat16* __restrict__ Ahi, const __nv_bfloat16* __restrict__ Alo,
    const __nv_bfloat16* __restrict__ Bhi, const __nv_bfloat16* __restrict__ Blo,
    float* __restrict__ outf, int M)
{
    constexpr int BM  = NW * 8;
    constexpr int TH  = NW * 32;
    constexpr int P   = K + 8;
    constexpr int NT  = N / 16;
    constexpr int KS  = K / 16;
    constexpr int CPR = K / 8;
    extern __shared__ __nv_bfloat16 smb[];
    __nv_bfloat16* Ah_s = smb;
    __nv_bfloat16* Al_s = smb + BM * P;
    __nv_bfloat16* Bh_s = smb + 2 * BM * P;
    __nv_bfloat16* Bl_s = smb + 2 * BM * P + N * P;

    const int tid  = threadIdx.x;
    const int warp = tid >> 5;
    const int lane = tid & 31;
    const int gid  = lane >> 2;
    const int tig  = lane & 3;
    const int mbase = (warp >> 1) * 16;
    const int nbase = (warp & 1) * (N / 2);
    const int row0 = blockIdx.x * BM;

    for (int i = tid; i < BM * CPR; i += TH) {
        int r = i / CPR, c = i % CPR;
        int gr = row0 + r;
        uint4 vh = make_uint4(0,0,0,0), vl = make_uint4(0,0,0,0);
        if (gr < M) {
            vh = *(const uint4*)&Ahi[(size_t)gr * K + c * 8];
            vl = *(const uint4*)&Alo[(size_t)gr * K + c * 8];
        }
        *(uint4*)&Ah_s[r * P + c * 8] = vh;
        *(uint4*)&Al_s[r * P + c * 8] = vl;
    }
    for (int i = tid; i < N * CPR; i += TH) {
        int r = i / CPR, c = i % CPR;
        *(uint4*)&Bh_s[r * P + c * 8] = *(const uint4*)&Bhi[(size_t)r * K + c * 8];
        *(uint4*)&Bl_s[r * P + c * 8] = *(const uint4*)&Blo[(size_t)r * K + c * 8];
    }
    __syncthreads();

    const unsigned sbase = smem_u32(smb);
    const unsigned offA = ((mbase + (lane & 15)) * P + ((lane & 16) ? 8 : 0)) * 2;
    unsigned offB[NT / 2];
#pragma unroll
    for (int p = 0; p < NT / 2; p++)
        offB[p] = ((nbase + p * 16 + ((lane & 16) ? 8 : 0) + (lane & 7)) * P
                   + ((lane & 8) ? 8 : 0)) * 2;

    const unsigned aHi = sbase + offA;
    const unsigned aLo = aHi + BM * P * 2;
    const unsigned bHi = sbase + 4 * BM * P;
    const unsigned bLo = bHi + N * P * 2;

    float acc[NT][4];
#pragma unroll
    for (int nj = 0; nj < NT; nj++)
#pragma unroll
        for (int q = 0; q < 4; q++) acc[nj][q] = 0.f;

#pragma unroll
    for (int ks = 0; ks < KS; ks++) {
        unsigned ah[4], al[4];
        ldsm4(ah, aHi + ks * 32);
        ldsm4(al, aLo + ks * 32);
#pragma unroll
        for (int p = 0; p < NT / 2; p++) {
            unsigned bh[4], bl[4];
            ldsm4(bh, bHi + offB[p] + ks * 32);
            ldsm4(bl, bLo + offB[p] + ks * 32);
            mma_bf16(acc[2 * p],     ah, bh[0], bh[1]);
            mma_bf16(acc[2 * p + 1], ah, bh[2], bh[3]);
            mma_bf16(acc[2 * p],     ah, bl[0], bl[1]);
            mma_bf16(acc[2 * p + 1], ah, bl[2], bl[3]);
            mma_bf16(acc[2 * p],     al, bh[0], bh[1]);
            mma_bf16(acc[2 * p + 1], al, bh[2], bh[3]);
        }
    }

    const int r = row0 + mbase + gid;
#pragma unroll
    for (int nj = 0; nj < NT; nj++) {
        const int c = nbase + nj * 8 + tig * 2;
        if (r < M)
            *(float2*)&outf[(size_t)r * N + c] = make_float2(acc[nj][0], acc[nj][1]);
        if (r + 8 < M)
            *(float2*)&outf[(size_t)(r + 8) * N + c] = make_float2(acc[nj][2], acc[nj][3]);
    }
}

// ---------------- fused decoder: out = relu(z2@Wd1 + b1) @ Wd2 + b2 ------------
#define DEC_SMEM_BYTES 212992
__global__ __launch_bounds__(512, 1) void k_dec(
    const __nv_bfloat16* __restrict__ Zhi, const __nv_bfloat16* __restrict__ Zlo,
    const __nv_bfloat16* __restrict__ W1h, const __nv_bfloat16* __restrict__ W1l,
    const float* __restrict__ b1,
    const __nv_bfloat16* __restrict__ W2h, const __nv_bfloat16* __restrict__ W2l,
    const float* __restrict__ b2, float* __restrict__ out, int M)
{
    constexpr int P1 = 72, P2 = 136;
    extern __shared__ __nv_bfloat16 smb[];
    __nv_bfloat16* Zh_s  = smb;
    __nv_bfloat16* Zl_s  = smb + 128 * P1;
    __nv_bfloat16* W1h_s = smb + 2 * 128 * P1;
    __nv_bfloat16* W1l_s = smb + 3 * 128 * P1;
    __nv_bfloat16* Th_s  = smb + 4 * 128 * P1;
    __nv_bfloat16* Tl_s  = smb + 4 * 128 * P1 + 128 * P2;
    __nv_bfloat16* W2h_s = smb + 4 * 128 * P1 + 2 * 128 * P2;
    __nv_bfloat16* W2l_s = smb + 4 * 128 * P1 + 3 * 128 * P2;

    const int tid  = threadIdx.x;
    const int warp = tid >> 5;
    const int lane = tid & 31;
    const int gid  = lane >> 2;
    const int tig  = lane & 3;
    const int mbase = (warp >> 1) * 16;
    const int nbase = (warp & 1) * 64;
    const int row0 = blockIdx.x * 128;

    for (int i = tid; i < 128 * 8; i += 512) {
        int r = i >> 3, c = i & 7;
        int gr = row0 + r;
        uint4 vh = make_uint4(0,0,0,0), vl = make_uint4(0,0,0,0);
        if (gr < M) {
            vh = *(const uint4*)&Zhi[(size_t)gr * 64 + c * 8];
            vl = *(const uint4*)&Zlo[(size_t)gr * 64 + c * 8];
        }
        *(uint4*)&Zh_s[r * P1 + c * 8] = vh;
        *(uint4*)&Zl_s[r * P1 + c * 8] = vl;
    }
    for (int i = tid; i < 128 * 8; i += 512) {
        int r = i >> 3, c = i & 7;
        *(uint4*)&W1h_s[r * P1 + c * 8] = *(const uint4*)&W1h[(size_t)r * 64 + c * 8];
        *(uint4*)&W1l_s[r * P1 + c * 8] = *(const uint4*)&W1l[(size_t)r * 64 + c * 8];
    }
    for (int i = tid; i < 128 * 16; i += 512) {
        int r = i >> 4, c = i & 15;
        *(uint4*)&W2h_s[r * P2 + c * 8] = *(const uint4*)&W2h[(size_t)r * 128 + c * 8];
        *(uint4*)&W2l_s[r * P2 + c * 8] = *(const uint4*)&W2l[(size_t)r * 128 + c * 8];
    }
    __syncthreads();

    const unsigned sbase = smem_u32(smb);
    const unsigned zHi  = sbase;
    const unsigned zLo  = sbase + 128 * P1 * 2;
    const unsigned w1Hi = sbase + 2 * 128 * P1 * 2;
    const unsigned w1Lo = sbase + 3 * 128 * P1 * 2;
    const unsigned tHi  = sbase + 4 * 128 * P1 * 2;
    const unsigned tLo  = tHi + 128 * P2 * 2;
    const unsigned w2Hi = tHi + 2 * 128 * P2 * 2;
    const unsigned w2Lo = tHi + 3 * 128 * P2 * 2;

    // ---- stage 1: T = relu(z2 @ Wd1 + b1), K=64 ----
    {
        const unsigned offA = ((mbase + (lane & 15)) * P1 + ((lane & 16) ? 8 : 0)) * 2;
        unsigned offB[4];
#pragma unroll
        for (int p = 0; p < 4; p++)
            offB[p] = ((nbase + p * 16 + ((lane & 16) ? 8 : 0) + (lane & 7)) * P1
                       + ((lane & 8) ? 8 : 0)) * 2;

        float acc[8][4];
#pragma unroll
        for (int nj = 0; nj < 8; nj++)
#pragma unroll
            for (int q = 0; q < 4; q++) acc[nj][q] = 0.f;

#pragma unroll
        for (int ks = 0; ks < 4; ks++) {
            unsigned ah[4], al[4];
            ldsm4(ah, zHi + offA + ks * 32);
            ldsm4(al, zLo + offA + ks * 32);
#pragma unroll
            for (int p = 0; p < 4; p++) {
                unsigned bh[4], bl[4];
                ldsm4(bh, w1Hi + offB[p] + ks * 32);
                ldsm4(bl, w1Lo + offB[p] + ks * 32);
                mma_bf16(acc[2 * p],     ah, bh[0], bh[1]);
                mma_bf16(acc[2 * p + 1], ah, bh[2], bh[3]);
                mma_bf16(acc[2 * p],     ah, bl[0], bl[1]);
                mma_bf16(acc[2 * p + 1], ah, bl[2], bl[3]);
                mma_bf16(acc[2 * p],     al, bh[0], bh[1]);
                mma_bf16(acc[2 * p + 1], al, bh[2], bh[3]);
            }
        }

        const int rl = mbase + gid;
#pragma unroll
        for (int nj = 0; nj < 8; nj++) {
            const int c = nbase + nj * 8 + tig * 2;
            const float bb0 = b1[c], bb1 = b1[c + 1];
#pragma unroll
            for (int h = 0; h < 2; h++) {
                int rr = rl + h * 8;
                float o0 = fmaxf(acc[nj][2 * h]     + bb0, 0.f);
                float o1 = fmaxf(acc[nj][2 * h + 1] + bb1, 0.f);
                __nv_bfloat16 h0, h1, l0, l1;
                split_bf16(o0, h0, l0);
                split_bf16(o1, h1, l1);
                __nv_bfloat162 ph; ph.x = h0; ph.y = h1;
                __nv_bfloat162 pl; pl.x = l0; pl.y = l1;
                *(__nv_bfloat162*)&Th_s[rr * P2 + c] = ph;
                *(__nv_bfloat162*)&Tl_s[rr * P2 + c] = pl;
            }
        }
    }
    __syncthreads();

    // ---- stage 2: out = T @ Wd2 + b2, K=128 ----
    {
        const unsigned offA = ((mbase + (lane & 15)) * P2 + ((lane & 16) ? 8 : 0)) * 2;
        unsigned offB[4];
#pragma unroll
        for (int p = 0; p < 4; p++)
            offB[p] = ((nbase + p * 16 + ((lane & 16) ? 8 : 0) + (lane & 7)) * P2
                       + ((lane & 8) ? 8 : 0)) * 2;

        float acc[8][4];
#pragma unroll
        for (int nj = 0; nj < 8; nj++)
#pragma unroll
            for (int q = 0; q < 4; q++) acc[nj][q] = 0.f;

#pragma unroll
        for (int ks = 0; ks < 8; ks++) {
            unsigned ah[4], al[4];
            ldsm4(ah, tHi + offA + ks * 32);
            ldsm4(al, tLo + offA + ks * 32);
#pragma unroll
            for (int p = 0; p < 4; p++) {
                unsigned bh[4], bl[4];
                ldsm4(bh, w2Hi + offB[p] + ks * 32);
                ldsm4(bl, w2Lo + offB[p] + ks * 32);
                mma_bf16(acc[2 * p],     ah, bh[0], bh[1]);
                mma_bf16(acc[2 * p + 1], ah, bh[2], bh[3]);
                mma_bf16(acc[2 * p],     ah, bl[0], bl[1]);
                mma_bf16(acc[2 * p + 1], ah, bl[2], bl[3]);
                mma_bf16(acc[2 * p],     al, bh[0], bh[1]);
                mma_bf16(acc[2 * p + 1], al, bh[2], bh[3]);
            }
        }

        const int r = row0 + mbase + gid;
#pragma unroll
        for (int nj = 0; nj < 8; nj++) {
            const int c = nbase + nj * 8 + tig * 2;
            const float bb0 = b2[c], bb1 = b2[c + 1];
            if (r < M)
                *(float2*)&out[(size_t)r * 128 + c] =
                    make_float2(acc[nj][0] + bb0, acc[nj][1] + bb1);
            if (r + 8 < M)
                *(float2*)&out[(size_t)(r + 8) * 128 + c] =
                    make_float2(acc[nj][2] + bb0, acc[nj][3] + bb1);
        }
    }
}

// ---------------- CSR gather F=128 -> bf16 hi/lo output ------------------------
__global__ __launch_bounds__(256) void k_gather128(
    const int* __restrict__ off, const int* __restrict__ cnt,
    const int* __restrict__ srt, const float* __restrict__ xs,
    const float* __restrict__ dis, const float* __restrict__ bias,
    __nv_bfloat16* __restrict__ zhi, __nv_bfloat16* __restrict__ zlo, int n)
{
    int w    = (blockIdx.x * blockDim.x + threadIdx.x) >> 5;
    int lane = threadIdx.x & 31;
    if (w >= n) return;
    int s = off[w];
    int e = s + cnt[w];
    float d = dis[w];

    float4 sv = *(const float4*)&xs[(size_t)w * 128 + lane * 4];
    float4 sum = make_float4(d * sv.x, d * sv.y, d * sv.z, d * sv.w);
    int t = s;
    for (; t + 4 <= e; t += 4) {
        int i0 = __ldg(&srt[t]);
        int i1 = __ldg(&srt[t + 1]);
        int i2 = __ldg(&srt[t + 2]);
        int i3 = __ldg(&srt[t + 3]);
        float d0 = __ldg(&dis[i0]);
        float d1 = __ldg(&dis[i1]);
        float d2 = __ldg(&dis[i2]);
        float d3 = __ldg(&dis[i3]);
        float4 v0 = *(const float4*)&xs[(size_t)i0 * 128 + lane * 4];
        float4 v1 = *(const float4*)&xs[(size_t)i1 * 128 + lane * 4];
        float4 v2 = *(const float4*)&xs[(size_t)i2 * 128 + lane * 4];
        float4 v3 = *(const float4*)&xs[(size_t)i3 * 128 + lane * 4];
        sum.x = fmaf(d3, v3.x, fmaf(d2, v2.x, fmaf(d1, v1.x, fmaf(d0, v0.x, sum.x))));
        sum.y = fmaf(d3, v3.y, fmaf(d2, v2.y, fmaf(d1, v1.y, fmaf(d0, v0.y, sum.y))));
        sum.z = fmaf(d3, v3.z, fmaf(d2, v2.z, fmaf(d1, v1.z, fmaf(d0, v0.z, sum.z))));
        sum.w = fmaf(d3, v3.w, fmaf(d2, v2.w, fmaf(d1, v1.w, fmaf(d0, v0.w, sum.w))));
    }
    for (; t < e; t++) {
        int i0 = __ldg(&srt[t]);
        float d0 = __ldg(&dis[i0]);
        float4 v0 = *(const float4*)&xs[(size_t)i0 * 128 + lane * 4];
        sum.x = fmaf(d0, v0.x, sum.x); sum.y = fmaf(d0, v0.y, sum.y);
        sum.z = fmaf(d0, v0.z, sum.z); sum.w = fmaf(d0, v0.w, sum.w);
    }
    const float4 b = *(const float4*)&bias[lane * 4];
    float o0 = fmaxf(fmaf(d, sum.x, b.x), 0.f);
    float o1 = fmaxf(fmaf(d, sum.y, b.y), 0.f);
    float o2 = fmaxf(fmaf(d, sum.z, b.z), 0.f);
    float o3 = fmaxf(fmaf(d, sum.w, b.w), 0.f);

    __nv_bfloat16 h0, h1, h2, h3, l0, l1, l2, l3;
    split_bf16(o0, h0, l0); split_bf16(o1, h1, l1);
    split_bf16(o2, h2, l2); split_bf16(o3, h3, l3);
    __nv_bfloat162 p;
    size_t ob = (size_t)w * 128 + lane * 4;
    p.x = h0; p.y = h1; *(__nv_bfloat162*)&zhi[ob]     = p;
    p.x = h2; p.y = h3; *(__nv_bfloat162*)&zhi[ob + 2] = p;
    p.x = l0; p.y = l1; *(__nv_bfloat162*)&zlo[ob]     = p;
    p.x = l2; p.y = l3; *(__nv_bfloat162*)&zlo[ob + 2] = p;
}

// ---------------- CSR gather F=64 (half-warp) -> bf16 hi/lo --------------------
__global__ __launch_bounds__(256) void k_gather64(
    const int* __restrict__ off, const int* __restrict__ cnt,
    const int* __restrict__ srt, const float* __restrict__ xs,
    const float* __restrict__ dis, const float* __restrict__ bias,
    __nv_bfloat16* __restrict__ zhi, __nv_bfloat16* __restrict__ zlo, int n)
{
    int hw   = (blockIdx.x * blockDim.x + threadIdx.x) >> 4;
    int lane = threadIdx.x & 15;
    if (hw >= n) return;
    int s = off[hw];
    int e = s + cnt[hw];
    float d = dis[hw];

    float4 sv = *(const float4*)&xs[(size_t)hw * 64 + lane * 4];
    float4 sum = make_float4(d * sv.x, d * sv.y, d * sv.z, d * sv.w);
    int t = s;
    for (; t + 4 <= e; t += 4) {
        int i0 = __ldg(&srt[t]);
        int i1 = __ldg(&srt[t + 1]);
        int i2 = __ldg(&srt[t + 2]);
        int i3 = __ldg(&srt[t + 3]);
        float d0 = __ldg(&dis[i0]);
        float d1 = __ldg(&dis[i1]);
        float d2 = __ldg(&dis[i2]);
        float d3 = __ldg(&dis[i3]);
        float4 v0 = *(const float4*)&xs[(size_t)i0 * 64 + lane * 4];
        float4 v1 = *(const float4*)&xs[(size_t)i1 * 64 + lane * 4];
        float4 v2 = *(const float4*)&xs[(size_t)i2 * 64 + lane * 4];
        float4 v3 = *(const float4*)&xs[(size_t)i3 * 64 + lane * 4];
        sum.x = fmaf(d3, v3.x, fmaf(d2, v2.x, fmaf(d1, v1.x, fmaf(d0, v0.x, sum.x))));
        sum.y = fmaf(d3, v3.y, fmaf(d2, v2.y, fmaf(d1, v1.y, fmaf(d0, v0.y, sum.y))));
        sum.z = fmaf(d3, v3.z, fmaf(d2, v2.z, fmaf(d1, v1.z, fmaf(d0, v0.z, sum.z))));
        sum.w = fmaf(d3, v3.w, fmaf(d2, v2.w, fmaf(d1, v1.w, fmaf(d0, v0.w, sum.w))));
    }
    for (; t < e; t++) {
        int i0 = __ldg(&srt[t]);
        float d0 = __ldg(&dis[i0]);
        float4 v0 = *(const float4*)&xs[(size_t)i0 * 64 + lane * 4];
        sum.x = fmaf(d0, v0.x, sum.x); sum.y = fmaf(d0, v0.y, sum.y);
        sum.z = fmaf(d0, v0.z, sum.z); sum.w = fmaf(d0, v0.w, sum.w);
    }
    const float4 b = *(const float4*)&bias[lane * 4];
    float o0 = fmaxf(fmaf(d, sum.x, b.x), 0.f);
    float o1 = fmaxf(fmaf(d, sum.y, b.y), 0.f);
    float o2 = fmaxf(fmaf(d, sum.z, b.z), 0.f);
    float o3 = fmaxf(fmaf(d, sum.w, b.w), 0.f);

    __nv_bfloat16 h0, h1, h2, h3, l0, l1, l2, l3;
    split_bf16(o0, h0, l0); split_bf16(o1, h1, l1);
    split_bf16(o2, h2, l2); split_bf16(o3, h3, l3);
    __nv_bfloat162 p;
    size_t ob = (size_t)hw * 64 + lane * 4;
    p.x = h0; p.y = h1; *(__nv_bfloat162*)&zhi[ob]     = p;
    p.x = h2; p.y = h3; *(__nv_bfloat162*)&zhi[ob + 2] = p;
    p.x = l0; p.y = l1; *(__nv_bfloat162*)&zlo[ob]     = p;
    p.x = l2; p.y = l3; *(__nv_bfloat162*)&zlo[ob + 2] = p;
}

// ---------------- launch ----------------
extern "C" void kernel_launch(void* const* d_in, const int* in_sizes, int n_in,
                              void* d_out, int out_size)
{
    const float* x      = (const float*)d_in[0];
    const void*  ei     = d_in[1];
    const float* W_enc1 = (const float*)d_in[2];
    const float* b_enc1 = (const float*)d_in[3];
    const float* W_enc2 = (const float*)d_in[4];
    const float* b_enc2 = (const float*)d_in[5];
    const float* W_dec1 = (const float*)d_in[6];
    const float* b_dec1 = (const float*)d_in[7];
    const float* W_dec2 = (const float*)d_in[8];
    const float* b_dec2 = (const float*)d_in[9];
    float*       out    = (float*)d_out;

    const int M = in_sizes[0] / 128;   // 50000
    int E = in_sizes[1] / 2;           // 600000
    if (E > MAX_EDGES) E = MAX_EDGES;

    int *bad, *row, *col, *srt, *cnt, *off, *cur, *stat, *aggr, *pref;
    float *dis, *xs1, *xs2;
    __nv_bfloat16 *xhi, *xlo, *z1hi, *z1lo, *z2hi, *z2lo;
    __nv_bfloat16 *b1hi, *b1lo, *b2hi, *b2lo, *d1hi, *d1lo, *d2hi, *d2lo;
    cudaGetSymbolAddress((void**)&bad,  g_bad);
    cudaGetSymbolAddress((void**)&row,  g_row);
    cudaGetSymbolAddress((void**)&col,  g_col);
    cudaGetSymbolAddress((void**)&srt,  g_srt);
    cudaGetSymbolAddress((void**)&cnt,  g_cnt);
    cudaGetSymbolAddress((void**)&off,  g_off);
    cudaGetSymbolAddress((void**)&cur,  g_cur);
    cudaGetSymbolAddress((void**)&stat, g_stat);
    cudaGetSymbolAddress((void**)&aggr, g_aggr);
    cudaGetSymbolAddress((void**)&pref, g_pref);
    cudaGetSymbolAddress((void**)&dis,  g_dis);
    cudaGetSymbolAddress((void**)&xs1,  g_xs1);
    cudaGetSymbolAddress((void**)&xs2,  g_xs2);
    cudaGetSymbolAddress((void**)&xhi,  g_xhi);
    cudaGetSymbolAddress((void**)&xlo,  g_xlo);
    cudaGetSymbolAddress((void**)&z1hi, g_z1hi);
    cudaGetSymbolAddress((void**)&z1lo, g_z1lo);
    cudaGetSymbolAddress((void**)&z2hi, g_z2hi);
    cudaGetSymbolAddress((void**)&z2lo, g_z2lo);
    cudaGetSymbolAddress((void**)&b1hi, g_b1hi);
    cudaGetSymbolAddress((void**)&b1lo, g_b1lo);
    cudaGetSymbolAddress((void**)&b2hi, g_b2hi);
    cudaGetSymbolAddress((void**)&b2lo, g_b2lo);
    cudaGetSymbolAddress((void**)&d1hi, g_d1hi);
    cudaGetSymbolAddress((void**)&d1lo, g_d1lo);
    cudaGetSymbolAddress((void**)&d2hi, g_d2hi);
    cudaGetSymbolAddress((void**)&d2lo, g_d2lo);

    const int SM_G1 = 2 * (128 + 128) * 136 * 2;  // 139264 (K=128,N=128,NW=16)
    const int SM_G2 = 2 * (64 + 64)   * 136 * 2;  //  69632 (K=128,N=64, NW=8)
    static bool attr_set = false;
    if (!attr_set) {
        cudaFuncSetAttribute(k_mmagemm<128,128,16>, cudaFuncAttributeMaxDynamicSharedMemorySize, SM_G1);
        cudaFuncSetAttribute(k_mmagemm<128,64,8>,   cudaFuncAttributeMaxDynamicSharedMemorySize, SM_G2);
        cudaFuncSetAttribute(k_dec, cudaFuncAttributeMaxDynamicSharedMemorySize, DEC_SMEM_BYTES);
        attr_set = true;
    }

    const int TB = 256;
    const int EB = (E + TB - 1) / TB;
    const int NB = (M + 255) / 256;
    const int GB128 = (M + 127) / 128;
    const int GB64  = (M + 63) / 64;
    const int AGB1 = (M * 32 + TB - 1) / TB;
    const int AGB2 = (M * 16 + TB - 1) / TB;
    const int CVT_ELEMS = 128 * 128 + 128 * 64 + 64 * 128 + 128 * 128;
    const long long CPTOT = (long long)M * 32 + CVT_ELEMS + E + M + SCAN_NB;
    const int CVB  = (int)((CPTOT + TB - 1) / TB);

    // 1: split x / transpose+split weights / zero counters / dtype sniff
    k_cvtprep<<<CVB, TB>>>(x, W_enc1, W_enc2, W_dec1, W_dec2,
                           (const long long*)ei, E,
                           xhi, xlo, b1hi, b1lo, b2hi, b2lo,
                           d1hi, d1lo, d2hi, d2lo, cnt, stat, bad, M);
    // 2: convert + degree count
    k_convert<<<EB, TB>>>(ei, E, M, bad, row, col, cnt);
    // 3: single-pass scan -> off/cur/dis
    k_scan   <<<NB, 256>>>(cnt, M, off, cur, dis, stat, aggr, pref);
    // 4 (PROFILED SLOT): gemm1 -> xs1 fp32 (unscaled xw), BM=128
    k_mmagemm<128,128,16><<<GB128, 512, SM_G1>>>(xhi, xlo, b1hi, b1lo, xs1, M);
    // 5: CSR placement
    k_place  <<<EB, TB>>>(row, col, cur, srt, E);
    // 6: layer-1 aggregation -> z1 hi/lo
    k_gather128<<<AGB1, TB>>>(off, cnt, srt, xs1, dis, b_enc1, z1hi, z1lo, M);
    // 7: gemm2 -> xs2 fp32
    k_mmagemm<128,64,8><<<GB64, 256, SM_G2>>>(z1hi, z1lo, b2hi, b2lo, xs2, M);
    // 8: layer-2 aggregation -> z2 hi/lo
    k_gather64<<<AGB2, TB>>>(off, cnt, srt, xs2, dis, b_enc2, z2hi, z2lo, M);
    // 9: fused decoder
    k_dec<<<GB128, 512, DEC_SMEM_BYTES>>>(z2hi, z2lo, d1hi, d1lo, b_dec1,
                                          d2hi, d2lo, b_dec2, out, M);
}

// round 17
// speedup vs baseline: 1.5447x; 1.0221x over previous
#include <cuda_runtime.h>
#include <cuda_bf16.h>

// Problem constants (reference: N_NODES=50000, F=128, HIDDEN=128, OUT=64, E=600000)
#define MAX_NODES 50000
#define MAX_EDGES 600000
#define SCAN_NB ((MAX_NODES + 255) / 256)   // 196

// ---------------- scratch (device globals; no allocations allowed) -------------
__device__ int   g_bad = 0;
__device__ int   g_row [MAX_EDGES];
__device__ int   g_col [MAX_EDGES];
__device__ int   g_srt [MAX_EDGES];
__device__ int   g_cnt [MAX_NODES];
__device__ int   g_off [MAX_NODES];
__device__ int   g_cur [MAX_NODES];
__device__ int   g_stat[SCAN_NB];
__device__ int   g_aggr[SCAN_NB];
__device__ int   g_pref[SCAN_NB];
__device__ float g_dis [MAX_NODES];
__device__ float g_xs1 [MAX_NODES * 128];
__device__ float g_xs2 [MAX_NODES * 64];
// bf16 split-precision operands / intermediates
__device__ __nv_bfloat16 g_xhi [MAX_NODES * 128];
__device__ __nv_bfloat16 g_xlo [MAX_NODES * 128];
__device__ __nv_bfloat16 g_z1hi[MAX_NODES * 128];
__device__ __nv_bfloat16 g_z1lo[MAX_NODES * 128];
__device__ __nv_bfloat16 g_z2hi[MAX_NODES * 64];
__device__ __nv_bfloat16 g_z2lo[MAX_NODES * 64];
__device__ __nv_bfloat16 g_b1hi[128 * 128];   // W_enc1^T  [n][k=128]
__device__ __nv_bfloat16 g_b1lo[128 * 128];
__device__ __nv_bfloat16 g_b2hi[64 * 128];    // W_enc2^T  [n][k=128]
__device__ __nv_bfloat16 g_b2lo[64 * 128];
__device__ __nv_bfloat16 g_d1hi[128 * 64];    // W_dec1^T  [n=128][k=64]
__device__ __nv_bfloat16 g_d1lo[128 * 64];
__device__ __nv_bfloat16 g_d2hi[128 * 128];   // W_dec2^T  [n=128][k=128]
__device__ __nv_bfloat16 g_d2lo[128 * 128];

// ---------------- helpers ------------------------------------------------------
__device__ __forceinline__ unsigned int smem_u32(const void* p) {
    unsigned int a;
    asm("{ .reg .u64 t; cvta.to.shared.u64 t, %1; cvt.u32.u64 %0, t; }"
        : "=r"(a) : "l"(p));
    return a;
}
__device__ __forceinline__ void mma_bf16(float* c, const unsigned* a,
                                         unsigned b0, unsigned b1) {
    asm volatile(
        "mma.sync.aligned.m16n8k16.row.col.f32.bf16.bf16.f32 "
        "{%0,%1,%2,%3}, {%4,%5,%6,%7}, {%8,%9}, {%0,%1,%2,%3};"
        : "+f"(c[0]), "+f"(c[1]), "+f"(c[2]), "+f"(c[3])
        : "r"(a[0]), "r"(a[1]), "r"(a[2]), "r"(a[3]), "r"(b0), "r"(b1));
}
__device__ __forceinline__ void ldsm4(unsigned* r, unsigned addr) {
    asm volatile("ldmatrix.sync.aligned.m8n8.x4.shared.b16 {%0,%1,%2,%3}, [%4];"
        : "=r"(r[0]), "=r"(r[1]), "=r"(r[2]), "=r"(r[3]) : "r"(addr));
}
__device__ __forceinline__ void split_bf16(float v, __nv_bfloat16& h, __nv_bfloat16& l) {
    h = __float2bfloat16(v);
    l = __float2bfloat16(v - __bfloat162float(h));
}

// ---------------- cvtA: split x + transpose/split W_enc1 (gemm1 inputs) --------
__global__ void k_cvtA(const float* __restrict__ x, const float* __restrict__ W1,
                       __nv_bfloat16* __restrict__ xhi, __nv_bfloat16* __restrict__ xlo,
                       __nv_bfloat16* __restrict__ b1hi, __nv_bfloat16* __restrict__ b1lo,
                       int M)
{
    const int NX4 = M * 32;
    int gid = blockIdx.x * blockDim.x + threadIdx.x;
    if (gid < NX4) {
        float4 v = ((const float4*)x)[gid];
        __nv_bfloat16 h0, h1, h2, h3, l0, l1, l2, l3;
        split_bf16(v.x, h0, l0); split_bf16(v.y, h1, l1);
        split_bf16(v.z, h2, l2); split_bf16(v.w, h3, l3);
        __nv_bfloat162 a, b;
        a.x = h0; a.y = h1; b.x = h2; b.y = h3;
        *(__nv_bfloat162*)&xhi[(size_t)gid * 4]     = a;
        *(__nv_bfloat162*)&xhi[(size_t)gid * 4 + 2] = b;
        a.x = l0; a.y = l1; b.x = l2; b.y = l3;
        *(__nv_bfloat162*)&xlo[(size_t)gid * 4]     = a;
        *(__nv_bfloat162*)&xlo[(size_t)gid * 4 + 2] = b;
        return;
    }
    int e = gid - NX4;
    if (e < 128 * 128) {                      // W_enc1 [k=128][n=128]
        int k = e >> 7, n = e & 127;
        __nv_bfloat16 h, l; split_bf16(W1[e], h, l);
        b1hi[n * 128 + k] = h; b1lo[n * 128 + k] = l;
    }
}

// ---------------- cvtB: other weights + dtype sniff + counter zeroing ----------
__global__ void k_cvtB(const float* __restrict__ W2,
                       const float* __restrict__ Wd1, const float* __restrict__ Wd2,
                       const long long* __restrict__ ei, int E,
                       __nv_bfloat16* __restrict__ b2hi, __nv_bfloat16* __restrict__ b2lo,
                       __nv_bfloat16* __restrict__ d1hi, __nv_bfloat16* __restrict__ d1lo,
                       __nv_bfloat16* __restrict__ d2hi, __nv_bfloat16* __restrict__ d2lo,
                       int* __restrict__ cnt, int* __restrict__ stat,
                       int* __restrict__ bad, int M)
{
    int e = blockIdx.x * blockDim.x + threadIdx.x;
    if (e < 128 * 64) {                       // W_enc2 [k=128][n=64]
        int k = e >> 6, n = e & 63;
        __nv_bfloat16 h, l; split_bf16(W2[e], h, l);
        b2hi[n * 128 + k] = h; b2lo[n * 128 + k] = l;
        return;
    }
    e -= 128 * 64;
    if (e < 64 * 128) {                       // W_dec1 [k=64][n=128]
        int k = e >> 7, n = e & 127;
        __nv_bfloat16 h, l; split_bf16(Wd1[e], h, l);
        d1hi[n * 64 + k] = h; d1lo[n * 64 + k] = l;
        return;
    }
    e -= 64 * 128;
    if (e < 128 * 128) {                      // W_dec2 [k=128][n=128]
        int k = e >> 7, n = e & 127;
        __nv_bfloat16 h, l; split_bf16(Wd2[e], h, l);
        d2hi[n * 128 + k] = h; d2lo[n * 128 + k] = l;
        return;
    }
    e -= 128 * 128;
    if (e < E) {                              // dtype sniff (int64 view in-bounds
        long long v = ei[e];                  //  under either layout)
        if ((v < 0 || v >= (long long)M) && *bad == 0) atomicOr(bad, 1);
        return;
    }
    e -= E;
    if (e < M) { cnt[e] = 0; return; }        // zero degree counters
    e -= M;
    if (e < SCAN_NB) stat[e] = 0;             // zero scan statuses
}

// ---------------- convert to int32 row/col + in-degree count -------------------
__global__ void k_convert(const void* __restrict__ ei, int E, int n,
                          const int* __restrict__ bad,
                          int* __restrict__ row, int* __restrict__ col,
                          int* __restrict__ cnt) {
    int i = blockIdx.x * blockDim.x + threadIdx.x;
    if (i >= E) return;
    int r, c;
    if (*bad == 0) {
        r = (int)((const long long*)ei)[i];
        c = (int)((const long long*)ei)[(size_t)E + i];
    } else {
        r = ((const int*)ei)[i];
        c = ((const int*)ei)[(size_t)E + i];
    }
    if ((unsigned)r >= (unsigned)n) r = 0;
    if ((unsigned)c >= (unsigned)n) c = 0;
    row[i] = r;
    col[i] = c;
    atomicAdd(&cnt[c], 1);
}

__global__ __launch_bounds__(256) void k_scan(
    const int* __restrict__ cnt, int n,
    int* __restrict__ off, int* __restrict__ cur, float* __restrict__ dis,
    volatile int* stat, volatile int* aggr, volatile int* pref)
{
    __shared__ int sh[256];
    __shared__ int s_prefix;
    const int b = blockIdx.x;
    const int i = b * 256 + threadIdx.x;
    int v = (i < n) ? cnt[i] : 0;
    sh[threadIdx.x] = v;
    __syncthreads();
#pragma unroll
    for (int d = 1; d < 256; d <<= 1) {
        int t = (threadIdx.x >= d) ? sh[threadIdx.x - d] : 0;
        __syncthreads();
        sh[threadIdx.x] += t;
        __syncthreads();
    }
    int incl = sh[threadIdx.x];
    int total = sh[255];

    if (threadIdx.x == 0) {
        if (b == 0) {
            pref[0] = total;
            __threadfence();
            ((int*)stat)[0] = 2;
            s_prefix = 0;
        } else {
            aggr[b] = total;
            __threadfence();
            ((int*)stat)[b] = 1;
            int run = 0;
            int p = b - 1;
            while (true) {
                int st;
                do { st = stat[p]; } while (st == 0);
                __threadfence();
                if (st == 2) { run += pref[p]; break; }
                run += aggr[p];
                p--;
            }
            pref[b] = run + total;
            __threadfence();
            ((int*)stat)[b] = 2;
            s_prefix = run;
        }
    }
    __syncthreads();
    int prefix = s_prefix;
    if (i < n) {
        int o = prefix + incl - v;
        off[i] = o;
        cur[i] = o;
        dis[i] = rsqrtf((float)(v + 1));
    }
}

__global__ void k_place(const int* __restrict__ row, const int* __restrict__ col,
                        int* __restrict__ cur, int* __restrict__ srt, int E) {
    int e = blockIdx.x * blockDim.x + threadIdx.x;
    if (e >= E) return;
    int pos = atomicAdd(&cur[col[e]], 1);
    srt[pos] = row[e];
}

// ---------------- unified split-bf16 mma GEMM (fused 3-product k-loop) ---------
// out[M,N] = (Ahi+Alo)[M,K] @ (Bhi+Blo)[N,K]^T   (AhBh + AhBl + AlBh per k-step)
template<int K, int N, int NW>
__global__ __launch_bounds__(NW * 32, (NW == 8) ? 2 : 1) void k_mmagemm(
    const __nv_bfloat16* __restrict__ Ahi, const __nv_bfloat16* __restrict__ Alo,
    const __nv_bfloat16* __restrict__ Bhi, const __nv_bfloat16* __restrict__ Blo,
    float* __restrict__ outf, int M)
{
    constexpr int BM  = NW * 8;
    constexpr int TH  = NW * 32;
    constexpr int P   = K + 8;
    constexpr int NT  = N / 16;
    constexpr int KS  = K / 16;
    constexpr int CPR = K / 8;
    extern __shared__ __nv_bfloat16 smb[];
    __nv_bfloat16* Ah_s = smb;
    __nv_bfloat16* Al_s = smb + BM * P;
    __nv_bfloat16* Bh_s = smb + 2 * BM * P;
    __nv_bfloat16* Bl_s = smb + 2 * BM * P + N * P;

    const int tid  = threadIdx.x;
    const int warp = tid >> 5;
    const int lane = tid & 31;
    const int gid  = lane >> 2;
    const int tig  = lane & 3;
    const int mbase = (warp >> 1) * 16;
    const int nbase = (warp & 1) * (N / 2);
    const int row0 = blockIdx.x * BM;

    for (int i = tid; i < BM * CPR; i += TH) {
        int r = i / CPR, c = i % CPR;
        int gr = row0 + r;
        uint4 vh = make_uint4(0,0,0,0), vl = make_uint4(0,0,0,0);
        if (gr < M) {
            vh = *(const uint4*)&Ahi[(size_t)gr * K + c * 8];
            vl = *(const uint4*)&Alo[(size_t)gr * K + c * 8];
        }
        *(uint4*)&Ah_s[r * P + c * 8] = vh;
        *(uint4*)&Al_s[r * P + c * 8] = vl;
    }
    for (int i = tid; i < N * CPR; i += TH) {
        int r = i / CPR, c = i % CPR;
        *(uint4*)&Bh_s[r * P + c * 8] = *(const uint4*)&Bhi[(size_t)r * K + c * 8];
        *(uint4*)&Bl_s[r * P + c * 8] = *(const uint4*)&Blo[(size_t)r * K + c * 8];
    }
    __syncthreads();

    const unsigned sbase = smem_u32(smb);
    const unsigned offA = ((mbase + (lane & 15)) * P + ((lane & 16) ? 8 : 0)) * 2;
    unsigned offB[NT / 2];
#pragma unroll
    for (int p = 0; p < NT / 2; p++)
        offB[p] = ((nbase + p * 16 + ((lane & 16) ? 8 : 0) + (lane & 7)) * P
                   + ((lane & 8) ? 8 : 0)) * 2;

    const unsigned aHi = sbase + offA;
    const unsigned aLo = aHi + BM * P * 2;
    const unsigned bHi = sbase + 4 * BM * P;
    const unsigned bLo = bHi + N * P * 2;

    float acc[NT][4];
#pragma unroll
    for (int nj = 0; nj < NT; nj++)
#pragma unroll
        for (int q = 0; q < 4; q++) acc[nj][q] = 0.f;

#pragma unroll
    for (int ks = 0; ks < KS; ks++) {
        unsigned ah[4], al[4];
        ldsm4(ah, aHi + ks * 32);
        ldsm4(al, aLo + ks * 32);
#pragma unroll
        for (int p = 0; p < NT / 2; p++) {
            unsigned bh[4], bl[4];
            ldsm4(bh, bHi + offB[p] + ks * 32);
            ldsm4(bl, bLo + offB[p] + ks * 32);
            mma_bf16(acc[2 * p],     ah, bh[0], bh[1]);
            mma_bf16(acc[2 * p + 1], ah, bh[2], bh[3]);
            mma_bf16(acc[2 * p],     ah, bl[0], bl[1]);
            mma_bf16(acc[2 * p + 1], ah, bl[2], bl[3]);
            mma_bf16(acc[2 * p],     al, bh[0], bh[1]);
            mma_bf16(acc[2 * p + 1], al, bh[2], bh[3]);
        }
    }

    const int r = row0 + mbase + gid;
#pragma unroll
    for (int nj = 0; nj < NT; nj++) {
        const int c = nbase + nj * 8 + tig * 2;
        if (r < M)
            *(float2*)&outf[(size_t)r * N + c] = make_float2(acc[nj][0], acc[nj][1]);
        if (r + 8 < M)
            *(float2*)&outf[(size_t)(r + 8) * N + c] = make_float2(acc[nj][2], acc[nj][3]);
    }
}

// ---------------- fused decoder: out = relu(z2@Wd1 + b1) @ Wd2 + b2 ------------
#define DEC_SMEM_BYTES 212992
__global__ __launch_bounds__(512, 1) void k_dec(
    const __nv_bfloat16* __restrict__ Zhi, const __nv_bfloat16* __restrict__ Zlo,
    const __nv_bfloat16* __restrict__ W1h, const __nv_bfloat16* __restrict__ W1l,
    const float* __restrict__ b1,
    const __nv_bfloat16* __restrict__ W2h, const __nv_bfloat16* __restrict__ W2l,
    const float* __restrict__ b2, float* __restrict__ out, int M)
{
    constexpr int P1 = 72, P2 = 136;
    extern __shared__ __nv_bfloat16 smb[];
    __nv_bfloat16* Zh_s  = smb;
    __nv_bfloat16* Zl_s  = smb + 128 * P1;
    __nv_bfloat16* W1h_s = smb + 2 * 128 * P1;
    __nv_bfloat16* W1l_s = smb + 3 * 128 * P1;
    __nv_bfloat16* Th_s  = smb + 4 * 128 * P1;
    __nv_bfloat16* Tl_s  = smb + 4 * 128 * P1 + 128 * P2;
    __nv_bfloat16* W2h_s = smb + 4 * 128 * P1 + 2 * 128 * P2;
    __nv_bfloat16* W2l_s = smb + 4 * 128 * P1 + 3 * 128 * P2;

    const int tid  = threadIdx.x;
    const int warp = tid >> 5;
    const int lane = tid & 31;
    const int gid  = lane >> 2;
    const int tig  = lane & 3;
    const int mbase = (warp >> 1) * 16;
    const int nbase = (warp & 1) * 64;
    const int row0 = blockIdx.x * 128;

    for (int i = tid; i < 128 * 8; i += 512) {
        int r = i >> 3, c = i & 7;
        int gr = row0 + r;
        uint4 vh = make_uint4(0,0,0,0), vl = make_uint4(0,0,0,0);
        if (gr < M) {
            vh = *(const uint4*)&Zhi[(size_t)gr * 64 + c * 8];
            vl = *(const uint4*)&Zlo[(size_t)gr * 64 + c * 8];
        }
        *(uint4*)&Zh_s[r * P1 + c * 8] = vh;
        *(uint4*)&Zl_s[r * P1 + c * 8] = vl;
    }
    for (int i = tid; i < 128 * 8; i += 512) {
        int r = i >> 3, c = i & 7;
        *(uint4*)&W1h_s[r * P1 + c * 8] = *(const uint4*)&W1h[(size_t)r * 64 + c * 8];
        *(uint4*)&W1l_s[r * P1 + c * 8] = *(const uint4*)&W1l[(size_t)r * 64 + c * 8];
    }
    for (int i = tid; i < 128 * 16; i += 512) {
        int r = i >> 4, c = i & 15;
        *(uint4*)&W2h_s[r * P2 + c * 8] = *(const uint4*)&W2h[(size_t)r * 128 + c * 8];
        *(uint4*)&W2l_s[r * P2 + c * 8] = *(const uint4*)&W2l[(size_t)r * 128 + c * 8];
    }
    __syncthreads();

    const unsigned sbase = smem_u32(smb);
    const unsigned zHi  = sbase;
    const unsigned zLo  = sbase + 128 * P1 * 2;
    const unsigned w1Hi = sbase + 2 * 128 * P1 * 2;
    const unsigned w1Lo = sbase + 3 * 128 * P1 * 2;
    const unsigned tHi  = sbase + 4 * 128 * P1 * 2;
    const unsigned tLo  = tHi + 128 * P2 * 2;
    const unsigned w2Hi = tHi + 2 * 128 * P2 * 2;
    const unsigned w2Lo = tHi + 3 * 128 * P2 * 2;

    // ---- stage 1: T = relu(z2 @ Wd1 + b1), K=64 ----
    {
        const unsigned offA = ((mbase + (lane & 15)) * P1 + ((lane & 16) ? 8 : 0)) * 2;
        unsigned offB[4];
#pragma unroll
        for (int p = 0; p < 4; p++)
            offB[p] = ((nbase + p * 16 + ((lane & 16) ? 8 : 0) + (lane & 7)) * P1
                       + ((lane & 8) ? 8 : 0)) * 2;

        float acc[8][4];
#pragma unroll
        for (int nj = 0; nj < 8; nj++)
#pragma unroll
            for (int q = 0; q < 4; q++) acc[nj][q] = 0.f;

#pragma unroll
        for (int ks = 0; ks < 4; ks++) {
            unsigned ah[4], al[4];
            ldsm4(ah, zHi + offA + ks * 32);
            ldsm4(al, zLo + offA + ks * 32);
#pragma unroll
            for (int p = 0; p < 4; p++) {
                unsigned bh[4], bl[4];
                ldsm4(bh, w1Hi + offB[p] + ks * 32);
                ldsm4(bl, w1Lo + offB[p] + ks * 32);
                mma_bf16(acc[2 * p],     ah, bh[0], bh[1]);
                mma_bf16(acc[2 * p + 1], ah, bh[2], bh[3]);
                mma_bf16(acc[2 * p],     ah, bl[0], bl[1]);
                mma_bf16(acc[2 * p + 1], ah, bl[2], bl[3]);
                mma_bf16(acc[2 * p],     al, bh[0], bh[1]);
                mma_bf16(acc[2 * p + 1], al, bh[2], bh[3]);
            }
        }

        const int rl = mbase + gid;
#pragma unroll
        for (int nj = 0; nj < 8; nj++) {
            const int c = nbase + nj * 8 + tig * 2;
            const float bb0 = b1[c], bb1 = b1[c + 1];
#pragma unroll
            for (int h = 0; h < 2; h++) {
                int rr = rl + h * 8;
                float o0 = fmaxf(acc[nj][2 * h]     + bb0, 0.f);
                float o1 = fmaxf(acc[nj][2 * h + 1] + bb1, 0.f);
                __nv_bfloat16 h0, h1, l0, l1;
                split_bf16(o0, h0, l0);
                split_bf16(o1, h1, l1);
                __nv_bfloat162 ph; ph.x = h0; ph.y = h1;
                __nv_bfloat162 pl; pl.x = l0; pl.y = l1;
                *(__nv_bfloat162*)&Th_s[rr * P2 + c] = ph;
                *(__nv_bfloat162*)&Tl_s[rr * P2 + c] = pl;
            }
        }
    }
    __syncthreads();

    // ---- stage 2: out = T @ Wd2 + b2, K=128 ----
    {
        const unsigned offA = ((mbase + (lane & 15)) * P2 + ((lane & 16) ? 8 : 0)) * 2;
        unsigned offB[4];
#pragma unroll
        for (int p = 0; p < 4; p++)
            offB[p] = ((nbase + p * 16 + ((lane & 16) ? 8 : 0) + (lane & 7)) * P2
                       + ((lane & 8) ? 8 : 0)) * 2;

        float acc[8][4];
#pragma unroll
        for (int nj = 0; nj < 8; nj++)
#pragma unroll
            for (int q = 0; q < 4; q++) acc[nj][q] = 0.f;

#pragma unroll
        for (int ks = 0; ks < 8; ks++) {
            unsigned ah[4], al[4];
            ldsm4(ah, tHi + offA + ks * 32);
            ldsm4(al, tLo + offA + ks * 32);
#pragma unroll
            for (int p = 0; p < 4; p++) {
                unsigned bh[4], bl[4];
                ldsm4(bh, w2Hi + offB[p] + ks * 32);
                ldsm4(bl, w2Lo + offB[p] + ks * 32);
                mma_bf16(acc[2 * p],     ah, bh[0], bh[1]);
                mma_bf16(acc[2 * p + 1], ah, bh[2], bh[3]);
                mma_bf16(acc[2 * p],     ah, bl[0], bl[1]);
                mma_bf16(acc[2 * p + 1], ah, bl[2], bl[3]);
                mma_bf16(acc[2 * p],     al, bh[0], bh[1]);
                mma_bf16(acc[2 * p + 1], al, bh[2], bh[3]);
            }
        }

        const int r = row0 + mbase + gid;
#pragma unroll
        for (int nj = 0; nj < 8; nj++) {
            const int c = nbase + nj * 8 + tig * 2;
            const float bb0 = b2[c], bb1 = b2[c + 1];
            if (r < M)
                *(float2*)&out[(size_t)r * 128 + c] =
                    make_float2(acc[nj][0] + bb0, acc[nj][1] + bb1);
            if (r + 8 < M)
                *(float2*)&out[(size_t)(r + 8) * 128 + c] =
                    make_float2(acc[nj][2] + bb0, acc[nj][3] + bb1);
        }
    }
}

// ---------------- CSR gather F=128 -> bf16 hi/lo output ------------------------
__global__ __launch_bounds__(256) void k_gather128(
    const int* __restrict__ off, const int* __restrict__ cnt,
    const int* __restrict__ srt, const float* __restrict__ xs,
    const float* __restrict__ dis, const float* __restrict__ bias,
    __nv_bfloat16* __restrict__ zhi, __nv_bfloat16* __restrict__ zlo, int n)
{
    int w    = (blockIdx.x * blockDim.x + threadIdx.x) >> 5;
    int lane = threadIdx.x & 31;
    if (w >= n) return;
    int s = off[w];
    int e = s + cnt[w];
    float d = dis[w];

    float4 sv = *(const float4*)&xs[(size_t)w * 128 + lane * 4];
    float4 sum = make_float4(d * sv.x, d * sv.y, d * sv.z, d * sv.w);
    int t = s;
    for (; t + 4 <= e; t += 4) {
        int i0 = __ldg(&srt[t]);
        int i1 = __ldg(&srt[t + 1]);
        int i2 = __ldg(&srt[t + 2]);
        int i3 = __ldg(&srt[t + 3]);
        float d0 = __ldg(&dis[i0]);
        float d1 = __ldg(&dis[i1]);
        float d2 = __ldg(&dis[i2]);
        float d3 = __ldg(&dis[i3]);
        float4 v0 = *(const float4*)&xs[(size_t)i0 * 128 + lane * 4];
        float4 v1 = *(const float4*)&xs[(size_t)i1 * 128 + lane * 4];
        float4 v2 = *(const float4*)&xs[(size_t)i2 * 128 + lane * 4];
        float4 v3 = *(const float4*)&xs[(size_t)i3 * 128 + lane * 4];
        sum.x = fmaf(d3, v3.x, fmaf(d2, v2.x, fmaf(d1, v1.x, fmaf(d0, v0.x, sum.x))));
        sum.y = fmaf(d3, v3.y, fmaf(d2, v2.y, fmaf(d1, v1.y, fmaf(d0, v0.y, sum.y))));
        sum.z = fmaf(d3, v3.z, fmaf(d2, v2.z, fmaf(d1, v1.z, fmaf(d0, v0.z, sum.z))));
        sum.w = fmaf(d3, v3.w, fmaf(d2, v2.w, fmaf(d1, v1.w, fmaf(d0, v0.w, sum.w))));
    }
    for (; t < e; t++) {
        int i0 = __ldg(&srt[t]);
        float d0 = __ldg(&dis[i0]);
        float4 v0 = *(const float4*)&xs[(size_t)i0 * 128 + lane * 4];
        sum.x = fmaf(d0, v0.x, sum.x); sum.y = fmaf(d0, v0.y, sum.y);
        sum.z = fmaf(d0, v0.z, sum.z); sum.w = fmaf(d0, v0.w, sum.w);
    }
    const float4 b = *(const float4*)&bias[lane * 4];
    float o0 = fmaxf(fmaf(d, sum.x, b.x), 0.f);
    float o1 = fmaxf(fmaf(d, sum.y, b.y), 0.f);
    float o2 = fmaxf(fmaf(d, sum.z, b.z), 0.f);
    float o3 = fmaxf(fmaf(d, sum.w, b.w), 0.f);

    __nv_bfloat16 h0, h1, h2, h3, l0, l1, l2, l3;
    split_bf16(o0, h0, l0); split_bf16(o1, h1, l1);
    split_bf16(o2, h2, l2); split_bf16(o3, h3, l3);
    __nv_bfloat162 p;
    size_t ob = (size_t)w * 128 + lane * 4;
    p.x = h0; p.y = h1; *(__nv_bfloat162*)&zhi[ob]     = p;
    p.x = h2; p.y = h3; *(__nv_bfloat162*)&zhi[ob + 2] = p;
    p.x = l0; p.y = l1; *(__nv_bfloat162*)&zlo[ob]     = p;
    p.x = l2; p.y = l3; *(__nv_bfloat162*)&zlo[ob + 2] = p;
}

// ---------------- CSR gather F=64 (half-warp) -> bf16 hi/lo --------------------
__global__ __launch_bounds__(256) void k_gather64(
    const int* __restrict__ off, const int* __restrict__ cnt,
    const int* __restrict__ srt, const float* __restrict__ xs,
    const float* __restrict__ dis, const float* __restrict__ bias,
    __nv_bfloat16* __restrict__ zhi, __nv_bfloat16* __restrict__ zlo, int n)
{
    int hw   = (blockIdx.x * blockDim.x + threadIdx.x) >> 4;
    int lane = threadIdx.x & 15;
    if (hw >= n) return;
    int s = off[hw];
    int e = s + cnt[hw];
    float d = dis[hw];

    float4 sv = *(const float4*)&xs[(size_t)hw * 64 + lane * 4];
    float4 sum = make_float4(d * sv.x, d * sv.y, d * sv.z, d * sv.w);
    int t = s;
    for (; t + 4 <= e; t += 4) {
        int i0 = __ldg(&srt[t]);
        int i1 = __ldg(&srt[t + 1]);
        int i2 = __ldg(&srt[t + 2]);
        int i3 = __ldg(&srt[t + 3]);
        float d0 = __ldg(&dis[i0]);
        float d1 = __ldg(&dis[i1]);
        float d2 = __ldg(&dis[i2]);
        float d3 = __ldg(&dis[i3]);
        float4 v0 = *(const float4*)&xs[(size_t)i0 * 64 + lane * 4];
        float4 v1 = *(const float4*)&xs[(size_t)i1 * 64 + lane * 4];
        float4 v2 = *(const float4*)&xs[(size_t)i2 * 64 + lane * 4];
        float4 v3 = *(const float4*)&xs[(size_t)i3 * 64 + lane * 4];
        sum.x = fmaf(d3, v3.x, fmaf(d2, v2.x, fmaf(d1, v1.x, fmaf(d0, v0.x, sum.x))));
        sum.y = fmaf(d3, v3.y, fmaf(d2, v2.y, fmaf(d1, v1.y, fmaf(d0, v0.y, sum.y))));
        sum.z = fmaf(d3, v3.z, fmaf(d2, v2.z, fmaf(d1, v1.z, fmaf(d0, v0.z, sum.z))));
        sum.w = fmaf(d3, v3.w, fmaf(d2, v2.w, fmaf(d1, v1.w, fmaf(d0, v0.w, sum.w))));
    }
    for (; t < e; t++) {
        int i0 = __ldg(&srt[t]);
        float d0 = __ldg(&dis[i0]);
        float4 v0 = *(const float4*)&xs[(size_t)i0 * 64 + lane * 4];
        sum.x = fmaf(d0, v0.x, sum.x); sum.y = fmaf(d0, v0.y, sum.y);
        sum.z = fmaf(d0, v0.z, sum.z); sum.w = fmaf(d0, v0.w, sum.w);
    }
    const float4 b = *(const float4*)&bias[lane * 4];
    float o0 = fmaxf(fmaf(d, sum.x, b.x), 0.f);
    float o1 = fmaxf(fmaf(d, sum.y, b.y), 0.f);
    float o2 = fmaxf(fmaf(d, sum.z, b.z), 0.f);
    float o3 = fmaxf(fmaf(d, sum.w, b.w), 0.f);

    __nv_bfloat16 h0, h1, h2, h3, l0, l1, l2, l3;
    split_bf16(o0, h0, l0); split_bf16(o1, h1, l1);
    split_bf16(o2, h2, l2); split_bf16(o3, h3, l3);
    __nv_bfloat162 p;
    size_t ob = (size_t)hw * 64 + lane * 4;
    p.x = h0; p.y = h1; *(__nv_bfloat162*)&zhi[ob]     = p;
    p.x = h2; p.y = h3; *(__nv_bfloat162*)&zhi[ob + 2] = p;
    p.x = l0; p.y = l1; *(__nv_bfloat162*)&zlo[ob]     = p;
    p.x = l2; p.y = l3; *(__nv_bfloat162*)&zlo[ob + 2] = p;
}

// ---------------- launch ----------------
extern "C" void kernel_launch(void* const* d_in, const int* in_sizes, int n_in,
                              void* d_out, int out_size)
{
    const float* x      = (const float*)d_in[0];
    const void*  ei     = d_in[1];
    const float* W_enc1 = (const float*)d_in[2];
    const float* b_enc1 = (const float*)d_in[3];
    const float* W_enc2 = (const float*)d_in[4];
    const float* b_enc2 = (const float*)d_in[5];
    const float* W_dec1 = (const float*)d_in[6];
    const float* b_dec1 = (const float*)d_in[7];
    const float* W_dec2 = (const float*)d_in[8];
    const float* b_dec2 = (const float*)d_in[9];
    float*       out    = (float*)d_out;

    const int M = in_sizes[0] / 128;   // 50000
    int E = in_sizes[1] / 2;           // 600000
    if (E > MAX_EDGES) E = MAX_EDGES;

    int *bad, *row, *col, *srt, *cnt, *off, *cur, *stat, *aggr, *pref;
    float *dis, *xs1, *xs2;
    __nv_bfloat16 *xhi, *xlo, *z1hi, *z1lo, *z2hi, *z2lo;
    __nv_bfloat16 *b1hi, *b1lo, *b2hi, *b2lo, *d1hi, *d1lo, *d2hi, *d2lo;
    cudaGetSymbolAddress((void**)&bad,  g_bad);
    cudaGetSymbolAddress((void**)&row,  g_row);
    cudaGetSymbolAddress((void**)&col,  g_col);
    cudaGetSymbolAddress((void**)&srt,  g_srt);
    cudaGetSymbolAddress((void**)&cnt,  g_cnt);
    cudaGetSymbolAddress((void**)&off,  g_off);
    cudaGetSymbolAddress((void**)&cur,  g_cur);
    cudaGetSymbolAddress((void**)&stat, g_stat);
    cudaGetSymbolAddress((void**)&aggr, g_aggr);
    cudaGetSymbolAddress((void**)&pref, g_pref);
    cudaGetSymbolAddress((void**)&dis,  g_dis);
    cudaGetSymbolAddress((void**)&xs1,  g_xs1);
    cudaGetSymbolAddress((void**)&xs2,  g_xs2);
    cudaGetSymbolAddress((void**)&xhi,  g_xhi);
    cudaGetSymbolAddress((void**)&xlo,  g_xlo);
    cudaGetSymbolAddress((void**)&z1hi, g_z1hi);
    cudaGetSymbolAddress((void**)&z1lo, g_z1lo);
    cudaGetSymbolAddress((void**)&z2hi, g_z2hi);
    cudaGetSymbolAddress((void**)&z2lo, g_z2lo);
    cudaGetSymbolAddress((void**)&b1hi, g_b1hi);
    cudaGetSymbolAddress((void**)&b1lo, g_b1lo);
    cudaGetSymbolAddress((void**)&b2hi, g_b2hi);
    cudaGetSymbolAddress((void**)&b2lo, g_b2lo);
    cudaGetSymbolAddress((void**)&d1hi, g_d1hi);
    cudaGetSymbolAddress((void**)&d1lo, g_d1lo);
    cudaGetSymbolAddress((void**)&d2hi, g_d2hi);
    cudaGetSymbolAddress((void**)&d2lo, g_d2lo);

    const int SM_G1 = 2 * (128 + 128) * 136 * 2;  // 139264 (K=128,N=128,NW=16)
    const int SM_G2 = 2 * (64 + 64)   * 136 * 2;  //  69632 (K=128,N=64, NW=8)
    static cudaStream_t s1;
    static cudaEvent_t ev0, ev1;
    static bool init_done = false;
    if (!init_done) {
        cudaFuncSetAttribute(k_mmagemm<128,128,16>, cudaFuncAttributeMaxDynamicSharedMemorySize, SM_G1);
        cudaFuncSetAttribute(k_mmagemm<128,64,8>,   cudaFuncAttributeMaxDynamicSharedMemorySize, SM_G2);
        cudaFuncSetAttribute(k_dec, cudaFuncAttributeMaxDynamicSharedMemorySize, DEC_SMEM_BYTES);
        cudaStreamCreateWithFlags(&s1, cudaStreamNonBlocking);
        cudaEventCreateWithFlags(&ev0, cudaEventDisableTiming);
        cudaEventCreateWithFlags(&ev1, cudaEventDisableTiming);
        init_done = true;
    }

    const int TB = 256;
    const int EB = (E + TB - 1) / TB;
    const int NB = (M + 255) / 256;
    const int GB128 = (M + 127) / 128;
    const int GB64  = (M + 63) / 64;
    const int AGB1 = (M * 32 + TB - 1) / TB;
    const int AGB2 = (M * 16 + TB - 1) / TB;
    const long long ATOT = (long long)M * 32 + 128 * 128;                 // cvtA work
    const long long BTOT = 128 * 64 + 64 * 128 + 128 * 128 + E + M + SCAN_NB;  // cvtB work
    const int AVB = (int)((ATOT + TB - 1) / TB);
    const int BVB = (int)((BTOT + TB - 1) / TB);

    // ---- fork: s1 handles the edge pipeline + non-gemm1 weight splits ----
    cudaEventRecord(ev0, 0);
    cudaStreamWaitEvent(s1, ev0, 0);

    // s1 chain (independent of gemm1):
    k_cvtB   <<<BVB, TB, 0, s1>>>(W_enc2, W_dec1, W_dec2, (const long long*)ei, E,
                                  b2hi, b2lo, d1hi, d1lo, d2hi, d2lo,
                                  cnt, stat, bad, M);
    k_convert<<<EB, TB, 0, s1>>>(ei, E, M, bad, row, col, cnt);
    k_scan   <<<NB, 256, 0, s1>>>(cnt, M, off, cur, dis, stat, aggr, pref);
    k_place  <<<EB, TB, 0, s1>>>(row, col, cur, srt, E);
    cudaEventRecord(ev1, s1);

    // main stream: x/W1 split -> gemm1 (overlaps s1 chain)
    k_cvtA<<<AVB, TB>>>(x, W_enc1, xhi, xlo, b1hi, b1lo, M);
    k_mmagemm<128,128,16><<<GB128, 512, SM_G1>>>(xhi, xlo, b1hi, b1lo, xs1, M);

    // ---- join, then the dependent tail ----
    cudaStreamWaitEvent(0, ev1, 0);
    k_gather128<<<AGB1, TB>>>(off, cnt, srt, xs1, dis, b_enc1, z1hi, z1lo, M);
    k_mmagemm<128,64,8><<<GB64, 256, SM_G2>>>(z1hi, z1lo, b2hi, b2lo, xs2, M);
    k_gather64<<<AGB2, TB>>>(off, cnt, srt, xs2, dis, b_enc2, z2hi, z2lo, M);
    k_dec<<<GB128, 512, DEC_SMEM_BYTES>>>(z2hi, z2lo, d1hi, d1lo, b_dec1,
                                          d2hi, d2lo, b_dec2, out, M);
}